// round 1
// baseline (speedup 1.0000x reference)
#include <cuda_runtime.h>
#include <math.h>

#define NN 50000
#define NE 800000

// ---------------- scratch (static device globals; no allocation allowed) ----
__device__ __align__(16) float g_feat[NN * 256];   // GEMM output per layer
__device__ __align__(16) float g_h1[NN * 256];     // layer0 output
__device__ __align__(16) float g_h2[NN * 256];     // layer1 output
__device__ __align__(16) float g_feat2[NN * 16];   // layer2 feat
__device__ __align__(16) float g_res2[NN * 16];    // layer2 residual proj
__device__ float g_el[NN * 4];
__device__ float g_er[NN * 4];
__device__ int   g_deg[NN];
__device__ int   g_rowptr[NN + 1];
__device__ int   g_pos[NN];
__device__ int   g_csr_src[NE];

// ---------------- CSR build ------------------------------------------------
__global__ void k_zero_deg() {
    int i = blockIdx.x * blockDim.x + threadIdx.x;
    if (i < NN) g_deg[i] = 0;
}

__global__ void k_hist(const int* __restrict__ dst) {
    int e = blockIdx.x * blockDim.x + threadIdx.x;
    if (e < NE) atomicAdd(&g_deg[dst[e]], 1);
}

__global__ void k_scan() {
    __shared__ int sh[1024];
    __shared__ int carry;
    int t = threadIdx.x;
    if (t == 0) carry = 0;
    __syncthreads();
    for (int base = 0; base < NN; base += 1024) {
        int i = base + t;
        int v = (i < NN) ? g_deg[i] : 0;
        sh[t] = v;
        __syncthreads();
        for (int off = 1; off < 1024; off <<= 1) {
            int tmp = (t >= off) ? sh[t - off] : 0;
            __syncthreads();
            sh[t] += tmp;
            __syncthreads();
        }
        if (i < NN) {
            int ex = carry + sh[t] - v;   // exclusive prefix
            g_rowptr[i] = ex;
            g_pos[i] = ex;
        }
        __syncthreads();
        if (t == 0) carry += sh[1023];
        __syncthreads();
    }
    if (t == 0) g_rowptr[NN] = carry;
}

__global__ void k_scatter(const int* __restrict__ src, const int* __restrict__ dst) {
    int e = blockIdx.x * blockDim.x + threadIdx.x;
    if (e < NE) {
        int p = atomicAdd(&g_pos[dst[e]], 1);
        g_csr_src[p] = src[e];
    }
}

// ---------------- GEMM: C[N,F] = A[N,K] @ B[K,F], F multiple of 64, K of 16 -
__global__ void k_gemm(const float* __restrict__ A, const float* __restrict__ B,
                       float* __restrict__ C, int Nrows, int K, int F) {
    __shared__ __align__(16) float As[16][64];
    __shared__ __align__(16) float Bs[16][64];
    int tx = threadIdx.x & 15;
    int ty = threadIdx.x >> 4;
    int row0 = blockIdx.y * 64;
    int col0 = blockIdx.x * 64;
    float acc[4][4] = {};
    for (int k0 = 0; k0 < K; k0 += 16) {
#pragma unroll
        for (int t = 0; t < 4; t++) {
            int idx = threadIdx.x + t * 256;
            int r = idx >> 4, kk = idx & 15;
            int gr = row0 + r;
            As[kk][r] = (gr < Nrows) ? A[gr * K + k0 + kk] : 0.f;
            int kk2 = idx >> 6, c = idx & 63;
            Bs[kk2][c] = B[(k0 + kk2) * F + col0 + c];
        }
        __syncthreads();
#pragma unroll
        for (int k = 0; k < 16; k++) {
            float4 a4 = *(const float4*)&As[k][ty * 4];
            float4 b4 = *(const float4*)&Bs[k][tx * 4];
            float af[4] = {a4.x, a4.y, a4.z, a4.w};
            float bf[4] = {b4.x, b4.y, b4.z, b4.w};
#pragma unroll
            for (int i = 0; i < 4; i++)
#pragma unroll
                for (int j = 0; j < 4; j++)
                    acc[i][j] += af[i] * bf[j];
        }
        __syncthreads();
    }
#pragma unroll
    for (int i = 0; i < 4; i++) {
        int gr = row0 + ty * 4 + i;
        if (gr < Nrows) {
#pragma unroll
            for (int j = 0; j < 4; j++)
                C[gr * F + col0 + tx * 4 + j] = acc[i][j];
        }
    }
}

// ---------------- small GEMM: C[N,16] = A[N,256] @ B[256,16] ----------------
__global__ void k_gemm16(const float* __restrict__ A, const float* __restrict__ B,
                         float* __restrict__ C) {
    __shared__ float Bs[256 * 16];
    for (int i = threadIdx.x; i < 256 * 16; i += blockDim.x) Bs[i] = B[i];
    __syncthreads();
    int tid = blockIdx.x * blockDim.x + threadIdx.x;
    int f = tid & 15, node = tid >> 4;
    if (node >= NN) return;
    const float* a = A + node * 256;
    float acc = 0.f;
#pragma unroll 8
    for (int k = 0; k < 256; k++) acc += a[k] * Bs[k * 16 + f];
    C[node * 16 + f] = acc;
}

// ---------------- el/er per (node, head) ------------------------------------
__global__ void k_elr(const float* __restrict__ feat, const float* __restrict__ al,
                      const float* __restrict__ ar, int H, int D) {
    int i = blockIdx.x * blockDim.x + threadIdx.x;
    if (i >= NN * H) return;
    int n = i / H, h = i % H;
    const float* fp = feat + n * (H * D) + h * D;
    float sl = 0.f, sr = 0.f;
    for (int d = 0; d < D; d++) {
        float v = fp[d];
        sl += v * al[h * D + d];
        sr += v * ar[h * D + d];
    }
    g_el[i] = sl;
    g_er[i] = sr;
}

// ---------------- fused segment-softmax + aggregate + residual + bias (+mish)
__device__ __forceinline__ float mishf(float x) {
    float sp = fmaxf(x, 0.f) + log1pf(__expf(-fabsf(x)));
    return x * tanhf(sp);
}

template <int H, int D, bool ACT>
__global__ void k_agg(const float* __restrict__ feat, const float* __restrict__ res,
                      const float* __restrict__ bias, float* __restrict__ out) {
    int w = (blockIdx.x * blockDim.x + threadIdx.x) >> 5;
    int lane = threadIdx.x & 31;
    if (w >= NN * H) return;
    int node = w / H, head = w % H;
    int start = g_rowptr[node], end = g_rowptr[node + 1];
    float er_n = g_er[node * H + head];

    // pass 1: max over incoming-edge scores (lane-strided)
    float m = -1e30f;
    for (int i = start + lane; i < end; i += 32) {
        int s = g_csr_src[i];
        float e = g_el[s * H + head] + er_n;
        e = (e > 0.f) ? e : 0.2f * e;
        m = fmaxf(m, e);
    }
#pragma unroll
    for (int o = 16; o; o >>= 1) m = fmaxf(m, __shfl_xor_sync(0xffffffffu, m, o));

    // pass 2: fused exp-sum + weighted feature accumulation
    float acc0 = 0.f, acc1 = 0.f, ssum = 0.f;
    for (int i = start; i < end; i++) {
        int s = g_csr_src[i];                       // broadcast
        float e = g_el[s * H + head] + er_n;        // broadcast
        e = (e > 0.f) ? e : 0.2f * e;
        float wgt = __expf(e - m);
        ssum += wgt;
        const float* fp = feat + s * (H * D) + head * D;
        if (D == 64) {
            acc0 += wgt * fp[lane];
            acc1 += wgt * fp[lane + 32];
        } else {
            if (lane < D) acc0 += wgt * fp[lane];
        }
    }
    float inv = (end > start) ? 1.f / ssum : 0.f;

    int base = node * (H * D) + head * D;
    if (D == 64) {
        float r0 = acc0 * inv + res[base + lane] + bias[head * D + lane];
        float r1 = acc1 * inv + res[base + lane + 32] + bias[head * D + lane + 32];
        if (ACT) { r0 = mishf(r0); r1 = mishf(r1); }
        out[base + lane] = r0;
        out[base + lane + 32] = r1;
    } else {
        if (lane < D) {
            float r0 = acc0 * inv + res[base + lane] + bias[head * D + lane];
            if (ACT) r0 = mishf(r0);
            out[base + lane] = r0;
        }
    }
}

// ---------------- launch -----------------------------------------------------
extern "C" void kernel_launch(void* const* d_in, const int* in_sizes, int n_in,
                              void* d_out, int out_size) {
    const float* x    = (const float*)d_in[0];
    const int*   src  = (const int*)d_in[1];
    const int*   dst  = (const int*)d_in[2];
    const float* W0   = (const float*)d_in[3];
    const float* al0  = (const float*)d_in[4];
    const float* ar0  = (const float*)d_in[5];
    const float* b0   = (const float*)d_in[6];
    const float* W1   = (const float*)d_in[7];
    const float* al1  = (const float*)d_in[8];
    const float* ar1  = (const float*)d_in[9];
    const float* b1   = (const float*)d_in[10];
    const float* W2   = (const float*)d_in[11];
    const float* al2  = (const float*)d_in[12];
    const float* ar2  = (const float*)d_in[13];
    const float* b2   = (const float*)d_in[14];
    const float* rW2  = (const float*)d_in[15];
    float* out = (float*)d_out;

    float *feat, *h1, *h2, *feat2, *res2;
    cudaGetSymbolAddress((void**)&feat,  g_feat);
    cudaGetSymbolAddress((void**)&h1,    g_h1);
    cudaGetSymbolAddress((void**)&h2,    g_h2);
    cudaGetSymbolAddress((void**)&feat2, g_feat2);
    cudaGetSymbolAddress((void**)&res2,  g_res2);

    // ---- CSR by dst
    k_zero_deg<<<(NN + 255) / 256, 256>>>();
    k_hist<<<(NE + 255) / 256, 256>>>(dst);
    k_scan<<<1, 1024>>>();
    k_scatter<<<(NE + 255) / 256, 256>>>(src, dst);

    dim3 gblk(256);
    dim3 ggrid(4, (NN + 63) / 64);
    int aggBlocks01 = (NN * 4 * 32 + 255) / 256;
    int aggBlocks2  = (NN * 32 + 255) / 256;

    // ---- layer 0: 256 -> 4x64, identity residual, mish
    k_gemm<<<ggrid, gblk>>>(x, W0, feat, NN, 256, 256);
    k_elr<<<(NN * 4 + 255) / 256, 256>>>(feat, al0, ar0, 4, 64);
    k_agg<4, 64, true><<<aggBlocks01, 256>>>(feat, x, b0, h1);

    // ---- layer 1: 256 -> 4x64, identity residual, mish
    k_gemm<<<ggrid, gblk>>>(h1, W1, feat, NN, 256, 256);
    k_elr<<<(NN * 4 + 255) / 256, 256>>>(feat, al1, ar1, 4, 64);
    k_agg<4, 64, true><<<aggBlocks01, 256>>>(feat, h1, b1, h2);

    // ---- layer 2: 256 -> 1x16, projected residual, no act; mean over 1 head = id
    k_gemm16<<<(NN * 16 + 255) / 256, 256>>>(h2, W2, feat2);
    k_gemm16<<<(NN * 16 + 255) / 256, 256>>>(h2, rW2, res2);
    k_elr<<<(NN + 255) / 256, 256>>>(feat2, al2, ar2, 1, 16);
    k_agg<1, 16, false><<<aggBlocks2, 256>>>(feat2, res2, b2, out);
}

// round 2
// speedup vs baseline: 1.3476x; 1.3476x over previous
#include <cuda_runtime.h>
#include <math.h>
#include <stdint.h>

#define NN 50000
#define NE 800000

// ---------------- scratch (static device globals; no allocation allowed) ----
__device__ __align__(16) float g_feat[NN * 256];   // GEMM output per layer
__device__ __align__(16) float g_h1[NN * 256];     // layer0 output
__device__ __align__(16) float g_h2[NN * 256];     // layer1 output
__device__ __align__(16) float g_feat2[NN * 16];   // layer2 feat
__device__ __align__(16) float g_res2[NN * 16];    // layer2 residual proj
__device__ float g_el[NN * 4];
__device__ float g_er[NN * 4];
__device__ int   g_deg[NN];
__device__ int   g_rowptr[NN + 1];
__device__ int   g_pos[NN];
__device__ int   g_csr_src[NE];

// ---------------- CSR build ------------------------------------------------
__global__ void k_zero_deg() {
    int i = blockIdx.x * blockDim.x + threadIdx.x;
    if (i < NN) g_deg[i] = 0;
}

__global__ void k_hist(const int* __restrict__ dst) {
    int e = blockIdx.x * blockDim.x + threadIdx.x;
    if (e < NE) atomicAdd(&g_deg[dst[e]], 1);
}

__global__ void k_scan() {
    __shared__ int sh[1024];
    __shared__ int carry;
    int t = threadIdx.x;
    if (t == 0) carry = 0;
    __syncthreads();
    for (int base = 0; base < NN; base += 1024) {
        int i = base + t;
        int v = (i < NN) ? g_deg[i] : 0;
        sh[t] = v;
        __syncthreads();
        for (int off = 1; off < 1024; off <<= 1) {
            int tmp = (t >= off) ? sh[t - off] : 0;
            __syncthreads();
            sh[t] += tmp;
            __syncthreads();
        }
        if (i < NN) {
            int ex = carry + sh[t] - v;   // exclusive prefix
            g_rowptr[i] = ex;
            g_pos[i] = ex;
        }
        __syncthreads();
        if (t == 0) carry += sh[1023];
        __syncthreads();
    }
    if (t == 0) g_rowptr[NN] = carry;
}

__global__ void k_scatter(const int* __restrict__ src, const int* __restrict__ dst) {
    int e = blockIdx.x * blockDim.x + threadIdx.x;
    if (e < NE) {
        int p = atomicAdd(&g_pos[dst[e]], 1);
        g_csr_src[p] = src[e];
    }
}

// ---------------- tensor-core GEMM (3xTF32 split, fp32-accurate) ------------
// C[M,N] = A[M,K] @ B[K,N], fp32 in/out. BM=128 BN=64 BK=16, 8 warps.
__device__ __forceinline__ void tf32_split(float x, uint32_t& hi, uint32_t& lo) {
    uint32_t h = __float_as_uint(x) & 0xFFFFE000u;  // truncate to tf32
    hi = h;
    float r = x - __uint_as_float(h);
    uint32_t l;
    asm("cvt.rna.tf32.f32 %0, %1;" : "=r"(l) : "f"(r));
    lo = l;
}

__device__ __forceinline__ void mma8(float* d, const uint32_t* a, const uint32_t* b) {
    asm volatile(
        "mma.sync.aligned.m16n8k8.row.col.f32.tf32.tf32.f32 "
        "{%0,%1,%2,%3}, {%4,%5,%6,%7}, {%8,%9}, {%0,%1,%2,%3};\n"
        : "+f"(d[0]), "+f"(d[1]), "+f"(d[2]), "+f"(d[3])
        : "r"(a[0]), "r"(a[1]), "r"(a[2]), "r"(a[3]), "r"(b[0]), "r"(b[1]));
}

#define APAD 20
#define BPAD 72

__global__ __launch_bounds__(256, 2) void k_gemm_tc(
    const float* __restrict__ A, const float* __restrict__ B,
    float* __restrict__ C, int M, int K, int N) {
    __shared__ float As[2][128][APAD];
    __shared__ float Bs[2][16][BPAD];

    int tid = threadIdx.x;
    int lane = tid & 31;
    int wid = tid >> 5;
    int warp_m = wid >> 1;            // 0..3
    int warp_n = wid & 1;             // 0..1
    int m_base = warp_m * 32;
    int n_base = warp_n * 32;
    int row0 = blockIdx.y * 128;
    int col0 = blockIdx.x * 64;

    float acc[2][4][4];
#pragma unroll
    for (int mt = 0; mt < 2; mt++)
#pragma unroll
        for (int nt = 0; nt < 4; nt++)
#pragma unroll
            for (int i = 0; i < 4; i++) acc[mt][nt][i] = 0.f;

    // global load indices
    int ar = tid >> 2;                // 0..63
    int ac = (tid & 3) * 4;           // 0,4,8,12
    int br = tid >> 4;                // 0..15
    int bc = (tid & 15) * 4;          // 0..60
    int gr0 = row0 + ar;
    int gr1 = gr0 + 64;
    const float4 f4z = make_float4(0.f, 0.f, 0.f, 0.f);

    // prologue: stage 0
    {
        float4 va = (gr0 < M) ? *(const float4*)(A + (size_t)gr0 * K + ac) : f4z;
        float4 vb = (gr1 < M) ? *(const float4*)(A + (size_t)gr1 * K + ac) : f4z;
        float4 vc = *(const float4*)(B + (size_t)br * N + col0 + bc);
        *(float4*)&As[0][ar][ac] = va;
        *(float4*)&As[0][ar + 64][ac] = vb;
        *(float4*)&Bs[0][br][bc] = vc;
    }
    __syncthreads();

    int NS = K / 16;
    for (int s = 0; s < NS; s++) {
        int cur = s & 1;
        float4 va, vb, vc;
        bool more = (s + 1 < NS);
        if (more) {
            int k0 = (s + 1) * 16;
            va = (gr0 < M) ? *(const float4*)(A + (size_t)gr0 * K + k0 + ac) : f4z;
            vb = (gr1 < M) ? *(const float4*)(A + (size_t)gr1 * K + k0 + ac) : f4z;
            vc = *(const float4*)(B + (size_t)(k0 + br) * N + col0 + bc);
        }
#pragma unroll
        for (int kk = 0; kk < 2; kk++) {
            int k = kk * 8;
            uint32_t ah[2][4], al_[2][4];
#pragma unroll
            for (int mt = 0; mt < 2; mt++) {
                int r = m_base + mt * 16 + (lane >> 2);
                int c = k + (lane & 3);
                tf32_split(As[cur][r][c],       ah[mt][0], al_[mt][0]);
                tf32_split(As[cur][r + 8][c],   ah[mt][1], al_[mt][1]);
                tf32_split(As[cur][r][c + 4],   ah[mt][2], al_[mt][2]);
                tf32_split(As[cur][r + 8][c + 4], ah[mt][3], al_[mt][3]);
            }
            uint32_t bh[4][2], bl[4][2];
#pragma unroll
            for (int nt = 0; nt < 4; nt++) {
                int n = n_base + nt * 8 + (lane >> 2);
                tf32_split(Bs[cur][k + (lane & 3)][n],     bh[nt][0], bl[nt][0]);
                tf32_split(Bs[cur][k + (lane & 3) + 4][n], bh[nt][1], bl[nt][1]);
            }
#pragma unroll
            for (int mt = 0; mt < 2; mt++)
#pragma unroll
                for (int nt = 0; nt < 4; nt++) {
                    mma8(acc[mt][nt], ah[mt], bh[nt]);
                    mma8(acc[mt][nt], al_[mt], bh[nt]);
                    mma8(acc[mt][nt], ah[mt], bl[nt]);
                }
        }
        if (more) {
            int nxt = cur ^ 1;
            *(float4*)&As[nxt][ar][ac] = va;
            *(float4*)&As[nxt][ar + 64][ac] = vb;
            *(float4*)&Bs[nxt][br][bc] = vc;
        }
        __syncthreads();
    }

    // epilogue
#pragma unroll
    for (int mt = 0; mt < 2; mt++)
#pragma unroll
        for (int nt = 0; nt < 4; nt++) {
            int r = row0 + m_base + mt * 16 + (lane >> 2);
            int c = col0 + n_base + nt * 8 + 2 * (lane & 3);
            if (r < M)
                *(float2*)&C[(size_t)r * N + c] = make_float2(acc[mt][nt][0], acc[mt][nt][1]);
            if (r + 8 < M)
                *(float2*)&C[(size_t)(r + 8) * N + c] = make_float2(acc[mt][nt][2], acc[mt][nt][3]);
        }
}

// ---------------- fused dual small GEMM: C1/C2[N,16] = A[N,256] @ B1/B2 -----
__global__ void k_gemm16x2(const float* __restrict__ A, const float* __restrict__ B1,
                           const float* __restrict__ B2, float* __restrict__ C1,
                           float* __restrict__ C2) {
    __shared__ float Bs[256 * 32];
    for (int i = threadIdx.x; i < 256 * 16; i += blockDim.x) {
        Bs[(i >> 4) * 32 + (i & 15)] = B1[i];
        Bs[(i >> 4) * 32 + 16 + (i & 15)] = B2[i];
    }
    __syncthreads();
    int tid = blockIdx.x * blockDim.x + threadIdx.x;
    int f = tid & 31, node = tid >> 5;
    if (node >= NN) return;
    const float* a = A + (size_t)node * 256;
    float acc = 0.f;
#pragma unroll 8
    for (int k = 0; k < 256; k++) acc += a[k] * Bs[k * 32 + f];
    if (f < 16) C1[node * 16 + f] = acc;
    else        C2[node * 16 + f - 16] = acc;
}

// ---------------- el/er per (node, head) ------------------------------------
__global__ void k_elr(const float* __restrict__ feat, const float* __restrict__ al,
                      const float* __restrict__ ar, int H, int D) {
    int i = blockIdx.x * blockDim.x + threadIdx.x;
    if (i >= NN * H) return;
    int n = i / H, h = i % H;
    const float* fp = feat + n * (H * D) + h * D;
    float sl = 0.f, sr = 0.f;
    for (int d = 0; d < D; d++) {
        float v = fp[d];
        sl += v * al[h * D + d];
        sr += v * ar[h * D + d];
    }
    g_el[i] = sl;
    g_er[i] = sr;
}

// ---------------- fused segment-softmax + aggregate + residual + bias (+mish)
__device__ __forceinline__ float mishf(float x) {
    float sp = fmaxf(x, 0.f) + log1pf(__expf(-fabsf(x)));
    return x * tanhf(sp);
}

template <int H, int D, bool ACT>
__global__ void k_agg(const float* __restrict__ feat, const float* __restrict__ res,
                      const float* __restrict__ bias, float* __restrict__ out) {
    int w = (blockIdx.x * blockDim.x + threadIdx.x) >> 5;
    int lane = threadIdx.x & 31;
    if (w >= NN * H) return;
    int node = w / H, head = w % H;
    int start = g_rowptr[node], end = g_rowptr[node + 1];
    float er_n = g_er[node * H + head];

    // pass 1: max over incoming-edge scores (lane-strided)
    float m = -1e30f;
    for (int i = start + lane; i < end; i += 32) {
        int s = g_csr_src[i];
        float e = g_el[s * H + head] + er_n;
        e = (e > 0.f) ? e : 0.2f * e;
        m = fmaxf(m, e);
    }
#pragma unroll
    for (int o = 16; o; o >>= 1) m = fmaxf(m, __shfl_xor_sync(0xffffffffu, m, o));

    // pass 2: fused exp-sum + weighted feature accumulation
    float acc0 = 0.f, acc1 = 0.f, ssum = 0.f;
    for (int i = start; i < end; i++) {
        int s = g_csr_src[i];                       // broadcast
        float e = g_el[s * H + head] + er_n;        // broadcast
        e = (e > 0.f) ? e : 0.2f * e;
        float wgt = __expf(e - m);
        ssum += wgt;
        const float* fp = feat + s * (H * D) + head * D;
        if (D == 64) {
            acc0 += wgt * fp[lane];
            acc1 += wgt * fp[lane + 32];
        } else {
            if (lane < D) acc0 += wgt * fp[lane];
        }
    }
    float inv = (end > start) ? 1.f / ssum : 0.f;

    int base = node * (H * D) + head * D;
    if (D == 64) {
        float r0 = acc0 * inv + res[base + lane] + bias[head * D + lane];
        float r1 = acc1 * inv + res[base + lane + 32] + bias[head * D + lane + 32];
        if (ACT) { r0 = mishf(r0); r1 = mishf(r1); }
        out[base + lane] = r0;
        out[base + lane + 32] = r1;
    } else {
        if (lane < D) {
            float r0 = acc0 * inv + res[base + lane] + bias[head * D + lane];
            if (ACT) r0 = mishf(r0);
            out[base + lane] = r0;
        }
    }
}

// ---------------- launch -----------------------------------------------------
extern "C" void kernel_launch(void* const* d_in, const int* in_sizes, int n_in,
                              void* d_out, int out_size) {
    const float* x    = (const float*)d_in[0];
    const int*   src  = (const int*)d_in[1];
    const int*   dst  = (const int*)d_in[2];
    const float* W0   = (const float*)d_in[3];
    const float* al0  = (const float*)d_in[4];
    const float* ar0  = (const float*)d_in[5];
    const float* b0   = (const float*)d_in[6];
    const float* W1   = (const float*)d_in[7];
    const float* al1  = (const float*)d_in[8];
    const float* ar1  = (const float*)d_in[9];
    const float* b1   = (const float*)d_in[10];
    const float* W2   = (const float*)d_in[11];
    const float* al2  = (const float*)d_in[12];
    const float* ar2  = (const float*)d_in[13];
    const float* b2   = (const float*)d_in[14];
    const float* rW2  = (const float*)d_in[15];
    float* out = (float*)d_out;

    float *feat, *h1, *h2, *feat2, *res2;
    cudaGetSymbolAddress((void**)&feat,  g_feat);
    cudaGetSymbolAddress((void**)&h1,    g_h1);
    cudaGetSymbolAddress((void**)&h2,    g_h2);
    cudaGetSymbolAddress((void**)&feat2, g_feat2);
    cudaGetSymbolAddress((void**)&res2,  g_res2);

    // ---- CSR by dst
    k_zero_deg<<<(NN + 255) / 256, 256>>>();
    k_hist<<<(NE + 255) / 256, 256>>>(dst);
    k_scan<<<1, 1024>>>();
    k_scatter<<<(NE + 255) / 256, 256>>>(src, dst);

    dim3 gtc(256 / 64, (NN + 127) / 128);
    int aggBlocks01 = (NN * 4 * 32 + 255) / 256;
    int aggBlocks2  = (NN * 32 + 255) / 256;

    // ---- layer 0: 256 -> 4x64, identity residual, mish
    k_gemm_tc<<<gtc, 256>>>(x, W0, feat, NN, 256, 256);
    k_elr<<<(NN * 4 + 255) / 256, 256>>>(feat, al0, ar0, 4, 64);
    k_agg<4, 64, true><<<aggBlocks01, 256>>>(feat, x, b0, h1);

    // ---- layer 1: 256 -> 4x64, identity residual, mish
    k_gemm_tc<<<gtc, 256>>>(h1, W1, feat, NN, 256, 256);
    k_elr<<<(NN * 4 + 255) / 256, 256>>>(feat, al1, ar1, 4, 64);
    k_agg<4, 64, true><<<aggBlocks01, 256>>>(feat, h1, b1, h2);

    // ---- layer 2: 256 -> 1x16, projected residual, no act; mean over 1 head = id
    k_gemm16x2<<<(NN * 32 + 255) / 256, 256>>>(h2, W2, rW2, feat2, res2);
    k_elr<<<(NN + 255) / 256, 256>>>(feat2, al2, ar2, 1, 16);
    k_agg<1, 16, false><<<aggBlocks2, 256>>>(feat2, res2, b2, out);
}

// round 3
// speedup vs baseline: 1.5969x; 1.1849x over previous
#include <cuda_runtime.h>
#include <math.h>
#include <stdint.h>

#define NN 50000
#define NE 800000

// ---------------- scratch (static device globals; no allocation allowed) ----
__device__ __align__(16) float g_feat[NN * 256];   // GEMM output per layer
__device__ __align__(16) float g_h1[NN * 256];     // layer0 output
__device__ __align__(16) float g_h2[NN * 256];     // layer1 output
__device__ __align__(16) float g_feat2[NN * 16];   // layer2 feat
__device__ __align__(16) float g_res2[NN * 16];    // layer2 residual proj
__device__ __align__(16) float g_el[NN * 4];
__device__ __align__(16) float g_er[NN * 4];
__device__ int   g_deg[NN];
__device__ int   g_rowptr[NN + 1];
__device__ int   g_pos[NN];
__device__ int   g_csr_src[NE];

// ---------------- CSR build ------------------------------------------------
__global__ void k_zero_deg() {
    int i = blockIdx.x * blockDim.x + threadIdx.x;
    if (i < NN) g_deg[i] = 0;
}

__global__ void k_hist(const int* __restrict__ dst) {
    int e = blockIdx.x * blockDim.x + threadIdx.x;
    if (e < NE) atomicAdd(&g_deg[dst[e]], 1);
}

__global__ void k_scan() {
    __shared__ int sh[1024];
    __shared__ int carry;
    int t = threadIdx.x;
    if (t == 0) carry = 0;
    __syncthreads();
    for (int base = 0; base < NN; base += 1024) {
        int i = base + t;
        int v = (i < NN) ? g_deg[i] : 0;
        sh[t] = v;
        __syncthreads();
        for (int off = 1; off < 1024; off <<= 1) {
            int tmp = (t >= off) ? sh[t - off] : 0;
            __syncthreads();
            sh[t] += tmp;
            __syncthreads();
        }
        if (i < NN) {
            int ex = carry + sh[t] - v;   // exclusive prefix
            g_rowptr[i] = ex;
            g_pos[i] = ex;
        }
        __syncthreads();
        if (t == 0) carry += sh[1023];
        __syncthreads();
    }
    if (t == 0) g_rowptr[NN] = carry;
}

__global__ void k_scatter(const int* __restrict__ src, const int* __restrict__ dst) {
    int e = blockIdx.x * blockDim.x + threadIdx.x;
    if (e < NE) {
        int p = atomicAdd(&g_pos[dst[e]], 1);
        g_csr_src[p] = src[e];
    }
}

// ---------------- tensor-core GEMM (3xTF32 split, fp32-accurate) ------------
__device__ __forceinline__ void tf32_split(float x, uint32_t& hi, uint32_t& lo) {
    uint32_t h = __float_as_uint(x) & 0xFFFFE000u;
    hi = h;
    float r = x - __uint_as_float(h);
    uint32_t l;
    asm("cvt.rna.tf32.f32 %0, %1;" : "=r"(l) : "f"(r));
    lo = l;
}

__device__ __forceinline__ void mma8(float* d, const uint32_t* a, const uint32_t* b) {
    asm volatile(
        "mma.sync.aligned.m16n8k8.row.col.f32.tf32.tf32.f32 "
        "{%0,%1,%2,%3}, {%4,%5,%6,%7}, {%8,%9}, {%0,%1,%2,%3};\n"
        : "+f"(d[0]), "+f"(d[1]), "+f"(d[2]), "+f"(d[3])
        : "r"(a[0]), "r"(a[1]), "r"(a[2]), "r"(a[3]), "r"(b[0]), "r"(b[1]));
}

#define APAD 20
#define BPAD 72

__global__ __launch_bounds__(256, 2) void k_gemm_tc(
    const float* __restrict__ A, const float* __restrict__ B,
    float* __restrict__ C, int M, int K, int N) {
    __shared__ float As[2][128][APAD];
    __shared__ float Bs[2][16][BPAD];

    int tid = threadIdx.x;
    int lane = tid & 31;
    int wid = tid >> 5;
    int warp_m = wid >> 1;
    int warp_n = wid & 1;
    int m_base = warp_m * 32;
    int n_base = warp_n * 32;
    int row0 = blockIdx.y * 128;
    int col0 = blockIdx.x * 64;

    float acc[2][4][4];
#pragma unroll
    for (int mt = 0; mt < 2; mt++)
#pragma unroll
        for (int nt = 0; nt < 4; nt++)
#pragma unroll
            for (int i = 0; i < 4; i++) acc[mt][nt][i] = 0.f;

    int ar = tid >> 2;
    int ac = (tid & 3) * 4;
    int br = tid >> 4;
    int bc = (tid & 15) * 4;
    int gr0 = row0 + ar;
    int gr1 = gr0 + 64;
    const float4 f4z = make_float4(0.f, 0.f, 0.f, 0.f);

    {
        float4 va = (gr0 < M) ? *(const float4*)(A + (size_t)gr0 * K + ac) : f4z;
        float4 vb = (gr1 < M) ? *(const float4*)(A + (size_t)gr1 * K + ac) : f4z;
        float4 vc = *(const float4*)(B + (size_t)br * N + col0 + bc);
        *(float4*)&As[0][ar][ac] = va;
        *(float4*)&As[0][ar + 64][ac] = vb;
        *(float4*)&Bs[0][br][bc] = vc;
    }
    __syncthreads();

    int NS = K / 16;
    for (int s = 0; s < NS; s++) {
        int cur = s & 1;
        float4 va, vb, vc;
        bool more = (s + 1 < NS);
        if (more) {
            int k0 = (s + 1) * 16;
            va = (gr0 < M) ? *(const float4*)(A + (size_t)gr0 * K + k0 + ac) : f4z;
            vb = (gr1 < M) ? *(const float4*)(A + (size_t)gr1 * K + k0 + ac) : f4z;
            vc = *(const float4*)(B + (size_t)(k0 + br) * N + col0 + bc);
        }
#pragma unroll
        for (int kk = 0; kk < 2; kk++) {
            int k = kk * 8;
            uint32_t ah[2][4], al_[2][4];
#pragma unroll
            for (int mt = 0; mt < 2; mt++) {
                int r = m_base + mt * 16 + (lane >> 2);
                int c = k + (lane & 3);
                tf32_split(As[cur][r][c],         ah[mt][0], al_[mt][0]);
                tf32_split(As[cur][r + 8][c],     ah[mt][1], al_[mt][1]);
                tf32_split(As[cur][r][c + 4],     ah[mt][2], al_[mt][2]);
                tf32_split(As[cur][r + 8][c + 4], ah[mt][3], al_[mt][3]);
            }
            uint32_t bh[4][2], bl[4][2];
#pragma unroll
            for (int nt = 0; nt < 4; nt++) {
                int n = n_base + nt * 8 + (lane >> 2);
                tf32_split(Bs[cur][k + (lane & 3)][n],     bh[nt][0], bl[nt][0]);
                tf32_split(Bs[cur][k + (lane & 3) + 4][n], bh[nt][1], bl[nt][1]);
            }
#pragma unroll
            for (int mt = 0; mt < 2; mt++)
#pragma unroll
                for (int nt = 0; nt < 4; nt++) {
                    mma8(acc[mt][nt], ah[mt], bh[nt]);
                    mma8(acc[mt][nt], al_[mt], bh[nt]);
                    mma8(acc[mt][nt], ah[mt], bl[nt]);
                }
        }
        if (more) {
            int nxt = cur ^ 1;
            *(float4*)&As[nxt][ar][ac] = va;
            *(float4*)&As[nxt][ar + 64][ac] = vb;
            *(float4*)&Bs[nxt][br][bc] = vc;
        }
        __syncthreads();
    }

#pragma unroll
    for (int mt = 0; mt < 2; mt++)
#pragma unroll
        for (int nt = 0; nt < 4; nt++) {
            int r = row0 + m_base + mt * 16 + (lane >> 2);
            int c = col0 + n_base + nt * 8 + 2 * (lane & 3);
            if (r < M)
                *(float2*)&C[(size_t)r * N + c] = make_float2(acc[mt][nt][0], acc[mt][nt][1]);
            if (r + 8 < M)
                *(float2*)&C[(size_t)(r + 8) * N + c] = make_float2(acc[mt][nt][2], acc[mt][nt][3]);
        }
}

// ---------------- fused dual small GEMM: C1/C2[N,16] = A[N,256] @ B1/B2 -----
__global__ void k_gemm16x2(const float* __restrict__ A, const float* __restrict__ B1,
                           const float* __restrict__ B2, float* __restrict__ C1,
                           float* __restrict__ C2) {
    __shared__ float Bs[256 * 32];
    for (int i = threadIdx.x; i < 256 * 16; i += blockDim.x) {
        Bs[(i >> 4) * 32 + (i & 15)] = B1[i];
        Bs[(i >> 4) * 32 + 16 + (i & 15)] = B2[i];
    }
    __syncthreads();
    int tid = blockIdx.x * blockDim.x + threadIdx.x;
    int f = tid & 31, node = tid >> 5;
    if (node >= NN) return;
    const float* a = A + (size_t)node * 256;
    float acc = 0.f;
#pragma unroll 8
    for (int k = 0; k < 256; k++) acc += a[k] * Bs[k * 32 + f];
    if (f < 16) C1[node * 16 + f] = acc;
    else        C2[node * 16 + f - 16] = acc;
}

// ---------------- el/er, coalesced: warp per (node, head), H=4 D=64 ---------
__global__ void k_elr4(const float* __restrict__ feat, const float* __restrict__ al,
                       const float* __restrict__ ar) {
    int w = (blockIdx.x * blockDim.x + threadIdx.x) >> 5;
    if (w >= NN * 4) return;
    int lane = threadIdx.x & 31;
    int node = w >> 2, h = w & 3;
    const float* fp = feat + (size_t)node * 256 + h * 64;
    float v0 = fp[lane], v1 = fp[lane + 32];
    float sl = v0 * al[h * 64 + lane] + v1 * al[h * 64 + lane + 32];
    float sr = v0 * ar[h * 64 + lane] + v1 * ar[h * 64 + lane + 32];
#pragma unroll
    for (int o = 16; o; o >>= 1) {
        sl += __shfl_xor_sync(0xffffffffu, sl, o);
        sr += __shfl_xor_sync(0xffffffffu, sr, o);
    }
    if (lane == 0) { g_el[w] = sl; g_er[w] = sr; }
}

// ---- el/er for layer2 (H=1, D=16): thread per node --------------------------
__global__ void k_elr2(const float* __restrict__ feat, const float* __restrict__ al,
                       const float* __restrict__ ar) {
    int n = blockIdx.x * blockDim.x + threadIdx.x;
    if (n >= NN) return;
    const float* fp = feat + (size_t)n * 16;
    float sl = 0.f, sr = 0.f;
#pragma unroll
    for (int d = 0; d < 16; d++) {
        float v = fp[d];
        sl += v * al[d];
        sr += v * ar[d];
    }
    g_el[n] = sl;
    g_er[n] = sr;
}

// ---------------- fused softmax-aggregate, H=4 heads per warp ----------------
__device__ __forceinline__ float mishf(float x) {
    float sp = fmaxf(x, 0.f) + log1pf(__expf(-fabsf(x)));
    return x * tanhf(sp);
}

__device__ __forceinline__ float lrelu(float e) { return (e > 0.f) ? e : 0.2f * e; }

__global__ __launch_bounds__(256) void k_agg4(
    const float* __restrict__ feat, const float* __restrict__ res,
    const float* __restrict__ bias, float* __restrict__ out) {
    int node = (blockIdx.x * blockDim.x + threadIdx.x) >> 5;
    int lane = threadIdx.x & 31;
    if (node >= NN) return;
    int start = g_rowptr[node], end = g_rowptr[node + 1];
    float4 er4 = *(const float4*)&g_er[node * 4];

    // pass 1: per-head max over incoming-edge scores (lane-strided)
    float m0 = -1e30f, m1 = -1e30f, m2 = -1e30f, m3 = -1e30f;
    for (int i = start + lane; i < end; i += 32) {
        int s = g_csr_src[i];
        float4 el4 = *(const float4*)&g_el[s * 4];
        m0 = fmaxf(m0, lrelu(el4.x + er4.x));
        m1 = fmaxf(m1, lrelu(el4.y + er4.y));
        m2 = fmaxf(m2, lrelu(el4.z + er4.z));
        m3 = fmaxf(m3, lrelu(el4.w + er4.w));
    }
#pragma unroll
    for (int o = 16; o; o >>= 1) {
        m0 = fmaxf(m0, __shfl_xor_sync(0xffffffffu, m0, o));
        m1 = fmaxf(m1, __shfl_xor_sync(0xffffffffu, m1, o));
        m2 = fmaxf(m2, __shfl_xor_sync(0xffffffffu, m2, o));
        m3 = fmaxf(m3, __shfl_xor_sync(0xffffffffu, m3, o));
    }

    // pass 2: chunk of 32 edges -> lane-parallel weights, shfl-broadcast gathers
    float a00 = 0.f, a01 = 0.f, a10 = 0.f, a11 = 0.f;
    float a20 = 0.f, a21 = 0.f, a30 = 0.f, a31 = 0.f;
    float ss0 = 0.f, ss1 = 0.f, ss2 = 0.f, ss3 = 0.f;
    for (int base = start; base < end; base += 32) {
        int i = base + lane;
        int s = 0;
        float w0 = 0.f, w1 = 0.f, w2 = 0.f, w3 = 0.f;
        if (i < end) {
            s = g_csr_src[i];
            float4 el4 = *(const float4*)&g_el[s * 4];
            w0 = __expf(lrelu(el4.x + er4.x) - m0);
            w1 = __expf(lrelu(el4.y + er4.y) - m1);
            w2 = __expf(lrelu(el4.z + er4.z) - m2);
            w3 = __expf(lrelu(el4.w + er4.w) - m3);
            ss0 += w0; ss1 += w1; ss2 += w2; ss3 += w3;
        }
        int cnt = min(32, end - base);
        for (int j = 0; j < cnt; j++) {
            int   sj = __shfl_sync(0xffffffffu, s, j);
            float b0 = __shfl_sync(0xffffffffu, w0, j);
            float b1 = __shfl_sync(0xffffffffu, w1, j);
            float b2 = __shfl_sync(0xffffffffu, w2, j);
            float b3 = __shfl_sync(0xffffffffu, w3, j);
            const float* fp = feat + (size_t)sj * 256;
            a00 += b0 * fp[lane];        a01 += b0 * fp[lane + 32];
            a10 += b1 * fp[lane + 64];   a11 += b1 * fp[lane + 96];
            a20 += b2 * fp[lane + 128];  a21 += b2 * fp[lane + 160];
            a30 += b3 * fp[lane + 192];  a31 += b3 * fp[lane + 224];
        }
    }
#pragma unroll
    for (int o = 16; o; o >>= 1) {
        ss0 += __shfl_xor_sync(0xffffffffu, ss0, o);
        ss1 += __shfl_xor_sync(0xffffffffu, ss1, o);
        ss2 += __shfl_xor_sync(0xffffffffu, ss2, o);
        ss3 += __shfl_xor_sync(0xffffffffu, ss3, o);
    }
    bool has = (end > start);
    float i0 = has ? 1.f / ss0 : 0.f;
    float i1 = has ? 1.f / ss1 : 0.f;
    float i2 = has ? 1.f / ss2 : 0.f;
    float i3 = has ? 1.f / ss3 : 0.f;

    size_t ob = (size_t)node * 256;
    out[ob + lane]       = mishf(a00 * i0 + res[ob + lane]       + bias[lane]);
    out[ob + lane + 32]  = mishf(a01 * i0 + res[ob + lane + 32]  + bias[lane + 32]);
    out[ob + lane + 64]  = mishf(a10 * i1 + res[ob + lane + 64]  + bias[lane + 64]);
    out[ob + lane + 96]  = mishf(a11 * i1 + res[ob + lane + 96]  + bias[lane + 96]);
    out[ob + lane + 128] = mishf(a20 * i2 + res[ob + lane + 128] + bias[lane + 128]);
    out[ob + lane + 160] = mishf(a21 * i2 + res[ob + lane + 160] + bias[lane + 160]);
    out[ob + lane + 192] = mishf(a30 * i3 + res[ob + lane + 192] + bias[lane + 192]);
    out[ob + lane + 224] = mishf(a31 * i3 + res[ob + lane + 224] + bias[lane + 224]);
}

// ---------------- softmax-aggregate layer2, H=1 D=16 -------------------------
__global__ __launch_bounds__(256) void k_agg2(
    const float* __restrict__ feat, const float* __restrict__ res,
    const float* __restrict__ bias, float* __restrict__ out) {
    int node = (blockIdx.x * blockDim.x + threadIdx.x) >> 5;
    int lane = threadIdx.x & 31;
    if (node >= NN) return;
    int start = g_rowptr[node], end = g_rowptr[node + 1];
    float er_n = g_er[node];

    float m = -1e30f;
    for (int i = start + lane; i < end; i += 32) {
        int s = g_csr_src[i];
        m = fmaxf(m, lrelu(g_el[s] + er_n));
    }
#pragma unroll
    for (int o = 16; o; o >>= 1) m = fmaxf(m, __shfl_xor_sync(0xffffffffu, m, o));

    float acc = 0.f, ss = 0.f;
    for (int base = start; base < end; base += 32) {
        int i = base + lane;
        int s = 0;
        float w = 0.f;
        if (i < end) {
            s = g_csr_src[i];
            w = __expf(lrelu(g_el[s] + er_n) - m);
            ss += w;
        }
        int cnt = min(32, end - base);
        for (int j = 0; j < cnt; j++) {
            int   sj = __shfl_sync(0xffffffffu, s, j);
            float bw = __shfl_sync(0xffffffffu, w, j);
            if (lane < 16) acc += bw * feat[(size_t)sj * 16 + lane];
        }
    }
#pragma unroll
    for (int o = 16; o; o >>= 1) ss += __shfl_xor_sync(0xffffffffu, ss, o);
    float inv = (end > start) ? 1.f / ss : 0.f;
    if (lane < 16)
        out[(size_t)node * 16 + lane] = acc * inv + res[(size_t)node * 16 + lane] + bias[lane];
}

// ---------------- launch -----------------------------------------------------
extern "C" void kernel_launch(void* const* d_in, const int* in_sizes, int n_in,
                              void* d_out, int out_size) {
    const float* x    = (const float*)d_in[0];
    const int*   src  = (const int*)d_in[1];
    const int*   dst  = (const int*)d_in[2];
    const float* W0   = (const float*)d_in[3];
    const float* al0  = (const float*)d_in[4];
    const float* ar0  = (const float*)d_in[5];
    const float* b0   = (const float*)d_in[6];
    const float* W1   = (const float*)d_in[7];
    const float* al1  = (const float*)d_in[8];
    const float* ar1  = (const float*)d_in[9];
    const float* b1   = (const float*)d_in[10];
    const float* W2   = (const float*)d_in[11];
    const float* al2  = (const float*)d_in[12];
    const float* ar2  = (const float*)d_in[13];
    const float* b2   = (const float*)d_in[14];
    const float* rW2  = (const float*)d_in[15];
    float* out = (float*)d_out;

    float *feat, *h1, *h2, *feat2, *res2;
    cudaGetSymbolAddress((void**)&feat,  g_feat);
    cudaGetSymbolAddress((void**)&h1,    g_h1);
    cudaGetSymbolAddress((void**)&h2,    g_h2);
    cudaGetSymbolAddress((void**)&feat2, g_feat2);
    cudaGetSymbolAddress((void**)&res2,  g_res2);

    // ---- CSR by dst
    k_zero_deg<<<(NN + 255) / 256, 256>>>();
    k_hist<<<(NE + 255) / 256, 256>>>(dst);
    k_scan<<<1, 1024>>>();
    k_scatter<<<(NE + 255) / 256, 256>>>(src, dst);

    dim3 gtc(256 / 64, (NN + 127) / 128);
    int elrBlocks = (NN * 4 * 32 + 255) / 256;
    int aggBlocks = (NN * 32 + 255) / 256;

    // ---- layer 0: 256 -> 4x64, identity residual, mish
    k_gemm_tc<<<gtc, 256>>>(x, W0, feat, NN, 256, 256);
    k_elr4<<<elrBlocks, 256>>>(feat, al0, ar0);
    k_agg4<<<aggBlocks, 256>>>(feat, x, b0, h1);

    // ---- layer 1: 256 -> 4x64, identity residual, mish
    k_gemm_tc<<<gtc, 256>>>(h1, W1, feat, NN, 256, 256);
    k_elr4<<<elrBlocks, 256>>>(feat, al1, ar1);
    k_agg4<<<aggBlocks, 256>>>(feat, h1, b1, h2);

    // ---- layer 2: 256 -> 1x16, projected residual, no act
    k_gemm16x2<<<(NN * 32 + 255) / 256, 256>>>(h2, W2, rW2, feat2, res2);
    k_elr2<<<(NN + 255) / 256, 256>>>(feat2, al2, ar2);
    k_agg2<<<aggBlocks, 256>>>(feat2, res2, b2, out);
}

// round 4
// speedup vs baseline: 1.7029x; 1.0664x over previous
#include <cuda_runtime.h>
#include <cuda_fp16.h>
#include <math.h>
#include <stdint.h>

#define NN 50000
#define NE 800000

// ---------------- scratch (static device globals; no allocation allowed) ----
__device__ __align__(16) float g_feat[NN * 256];    // GEMM output per layer (fp32)
__device__ __align__(16) __half g_feat_h[NN * 256]; // fp16 gather copy
__device__ __align__(16) float g_h1[NN * 256];
__device__ __align__(16) float g_h2[NN * 256];
__device__ __align__(16) float g_feat2[NN * 16];
__device__ __align__(16) float g_res2[NN * 16];
__device__ __align__(16) float g_el[NN * 4];
__device__ __align__(16) float g_er[NN * 4];
__device__ int   g_deg[NN];
__device__ int   g_rowptr[NN + 1];
__device__ int   g_pos[NN];
__device__ int   g_csr_src[NE];

// ---------------- CSR build ------------------------------------------------
__global__ void k_zero_deg() {
    int i = blockIdx.x * blockDim.x + threadIdx.x;
    if (i < NN) g_deg[i] = 0;
}

__global__ void k_hist(const int* __restrict__ dst) {
    int e = blockIdx.x * blockDim.x + threadIdx.x;
    if (e < NE) atomicAdd(&g_deg[dst[e]], 1);
}

// single block, 1024 threads; serial per-thread chunk + shfl block scan
__global__ void k_scan() {
    __shared__ int warp_pref[32];
    const int T = 1024;
    int t = threadIdx.x;
    const int per = (NN + T - 1) / T;   // 49
    int begin = t * per;
    int end = min(begin + per, NN);
    if (begin > NN) begin = NN;
    if (end < begin) end = begin;

    int sum = 0;
    for (int i = begin; i < end; i++) sum += g_deg[i];

    int lane = t & 31, wid = t >> 5;
    int v = sum;
#pragma unroll
    for (int o = 1; o < 32; o <<= 1) {
        int u = __shfl_up_sync(0xffffffffu, v, o);
        if (lane >= o) v += u;
    }
    if (lane == 31) warp_pref[wid] = v;  // inclusive warp total
    __syncthreads();
    if (wid == 0) {
        int w = warp_pref[lane];
#pragma unroll
        for (int o = 1; o < 32; o <<= 1) {
            int u = __shfl_up_sync(0xffffffffu, w, o);
            if (lane >= o) w += u;
        }
        warp_pref[lane] = w;             // inclusive scan of warp totals
    }
    __syncthreads();
    int excl = v - sum + (wid ? warp_pref[wid - 1] : 0);

    int run = excl;
    for (int i = begin; i < end; i++) {
        g_rowptr[i] = run;
        g_pos[i] = run;
        run += g_deg[i];
    }
    if (t == T - 1) g_rowptr[NN] = run;  // == NE
}

__global__ void k_scatter(const int* __restrict__ src, const int* __restrict__ dst) {
    int e = blockIdx.x * blockDim.x + threadIdx.x;
    if (e < NE) {
        int p = atomicAdd(&g_pos[dst[e]], 1);
        g_csr_src[p] = src[e];
    }
}

// ---------------- tensor-core GEMM (3xTF32 split, fp32-accurate) ------------
__device__ __forceinline__ void tf32_split(float x, uint32_t& hi, uint32_t& lo) {
    uint32_t h = __float_as_uint(x) & 0xFFFFE000u;
    hi = h;
    float r = x - __uint_as_float(h);
    uint32_t l;
    asm("cvt.rna.tf32.f32 %0, %1;" : "=r"(l) : "f"(r));
    lo = l;
}

__device__ __forceinline__ void mma8(float* d, const uint32_t* a, const uint32_t* b) {
    asm volatile(
        "mma.sync.aligned.m16n8k8.row.col.f32.tf32.tf32.f32 "
        "{%0,%1,%2,%3}, {%4,%5,%6,%7}, {%8,%9}, {%0,%1,%2,%3};\n"
        : "+f"(d[0]), "+f"(d[1]), "+f"(d[2]), "+f"(d[3])
        : "r"(a[0]), "r"(a[1]), "r"(a[2]), "r"(a[3]), "r"(b[0]), "r"(b[1]));
}

#define APAD 20
#define BPAD 72

__global__ __launch_bounds__(256, 2) void k_gemm_tc(
    const float* __restrict__ A, const float* __restrict__ B,
    float* __restrict__ C, __half* __restrict__ Ch, int M, int K, int N) {
    __shared__ float As[2][128][APAD];
    __shared__ float Bs[2][16][BPAD];

    int tid = threadIdx.x;
    int lane = tid & 31;
    int wid = tid >> 5;
    int warp_m = wid >> 1;
    int warp_n = wid & 1;
    int m_base = warp_m * 32;
    int n_base = warp_n * 32;
    int row0 = blockIdx.y * 128;
    int col0 = blockIdx.x * 64;

    float acc[2][4][4];
#pragma unroll
    for (int mt = 0; mt < 2; mt++)
#pragma unroll
        for (int nt = 0; nt < 4; nt++)
#pragma unroll
            for (int i = 0; i < 4; i++) acc[mt][nt][i] = 0.f;

    int ar = tid >> 2;
    int ac = (tid & 3) * 4;
    int br = tid >> 4;
    int bc = (tid & 15) * 4;
    int gr0 = row0 + ar;
    int gr1 = gr0 + 64;
    const float4 f4z = make_float4(0.f, 0.f, 0.f, 0.f);

    {
        float4 va = (gr0 < M) ? *(const float4*)(A + (size_t)gr0 * K + ac) : f4z;
        float4 vb = (gr1 < M) ? *(const float4*)(A + (size_t)gr1 * K + ac) : f4z;
        float4 vc = *(const float4*)(B + (size_t)br * N + col0 + bc);
        *(float4*)&As[0][ar][ac] = va;
        *(float4*)&As[0][ar + 64][ac] = vb;
        *(float4*)&Bs[0][br][bc] = vc;
    }
    __syncthreads();

    int NS = K / 16;
    for (int s = 0; s < NS; s++) {
        int cur = s & 1;
        float4 va, vb, vc;
        bool more = (s + 1 < NS);
        if (more) {
            int k0 = (s + 1) * 16;
            va = (gr0 < M) ? *(const float4*)(A + (size_t)gr0 * K + k0 + ac) : f4z;
            vb = (gr1 < M) ? *(const float4*)(A + (size_t)gr1 * K + k0 + ac) : f4z;
            vc = *(const float4*)(B + (size_t)(k0 + br) * N + col0 + bc);
        }
#pragma unroll
        for (int kk = 0; kk < 2; kk++) {
            int k = kk * 8;
            uint32_t ah[2][4], al_[2][4];
#pragma unroll
            for (int mt = 0; mt < 2; mt++) {
                int r = m_base + mt * 16 + (lane >> 2);
                int c = k + (lane & 3);
                tf32_split(As[cur][r][c],         ah[mt][0], al_[mt][0]);
                tf32_split(As[cur][r + 8][c],     ah[mt][1], al_[mt][1]);
                tf32_split(As[cur][r][c + 4],     ah[mt][2], al_[mt][2]);
                tf32_split(As[cur][r + 8][c + 4], ah[mt][3], al_[mt][3]);
            }
            uint32_t bh[4][2], bl[4][2];
#pragma unroll
            for (int nt = 0; nt < 4; nt++) {
                int n = n_base + nt * 8 + (lane >> 2);
                tf32_split(Bs[cur][k + (lane & 3)][n],     bh[nt][0], bl[nt][0]);
                tf32_split(Bs[cur][k + (lane & 3) + 4][n], bh[nt][1], bl[nt][1]);
            }
#pragma unroll
            for (int mt = 0; mt < 2; mt++)
#pragma unroll
                for (int nt = 0; nt < 4; nt++) {
                    mma8(acc[mt][nt], ah[mt], bh[nt]);
                    mma8(acc[mt][nt], al_[mt], bh[nt]);
                    mma8(acc[mt][nt], ah[mt], bl[nt]);
                }
        }
        if (more) {
            int nxt = cur ^ 1;
            *(float4*)&As[nxt][ar][ac] = va;
            *(float4*)&As[nxt][ar + 64][ac] = vb;
            *(float4*)&Bs[nxt][br][bc] = vc;
        }
        __syncthreads();
    }

#pragma unroll
    for (int mt = 0; mt < 2; mt++)
#pragma unroll
        for (int nt = 0; nt < 4; nt++) {
            int r = row0 + m_base + mt * 16 + (lane >> 2);
            int c = col0 + n_base + nt * 8 + 2 * (lane & 3);
            if (r < M) {
                *(float2*)&C[(size_t)r * N + c] = make_float2(acc[mt][nt][0], acc[mt][nt][1]);
                *(__half2*)&Ch[(size_t)r * N + c] =
                    __floats2half2_rn(acc[mt][nt][0], acc[mt][nt][1]);
            }
            if (r + 8 < M) {
                *(float2*)&C[(size_t)(r + 8) * N + c] = make_float2(acc[mt][nt][2], acc[mt][nt][3]);
                *(__half2*)&Ch[(size_t)(r + 8) * N + c] =
                    __floats2half2_rn(acc[mt][nt][2], acc[mt][nt][3]);
            }
        }
}

// ---------------- fused dual small GEMM: C1/C2[N,16] = A[N,256] @ B1/B2 -----
__global__ void k_gemm16x2(const float* __restrict__ A, const float* __restrict__ B1,
                           const float* __restrict__ B2, float* __restrict__ C1,
                           float* __restrict__ C2) {
    __shared__ float Bs[256 * 32];
    for (int i = threadIdx.x; i < 256 * 16; i += blockDim.x) {
        Bs[(i >> 4) * 32 + (i & 15)] = B1[i];
        Bs[(i >> 4) * 32 + 16 + (i & 15)] = B2[i];
    }
    __syncthreads();
    int tid = blockIdx.x * blockDim.x + threadIdx.x;
    int f = tid & 31, node = tid >> 5;
    if (node >= NN) return;
    const float* a = A + (size_t)node * 256;
    float acc = 0.f;
#pragma unroll 8
    for (int k = 0; k < 256; k++) acc += a[k] * Bs[k * 32 + f];
    if (f < 16) C1[node * 16 + f] = acc;
    else        C2[node * 16 + f - 16] = acc;
}

// ---------------- el/er, coalesced: warp per (node, head), H=4 D=64 ---------
__global__ void k_elr4(const float* __restrict__ feat, const float* __restrict__ al,
                       const float* __restrict__ ar) {
    int w = (blockIdx.x * blockDim.x + threadIdx.x) >> 5;
    if (w >= NN * 4) return;
    int lane = threadIdx.x & 31;
    int node = w >> 2, h = w & 3;
    const float* fp = feat + (size_t)node * 256 + h * 64;
    float v0 = fp[lane], v1 = fp[lane + 32];
    float sl = v0 * al[h * 64 + lane] + v1 * al[h * 64 + lane + 32];
    float sr = v0 * ar[h * 64 + lane] + v1 * ar[h * 64 + lane + 32];
#pragma unroll
    for (int o = 16; o; o >>= 1) {
        sl += __shfl_xor_sync(0xffffffffu, sl, o);
        sr += __shfl_xor_sync(0xffffffffu, sr, o);
    }
    if (lane == 0) { g_el[w] = sl; g_er[w] = sr; }
}

__global__ void k_elr2(const float* __restrict__ feat, const float* __restrict__ al,
                       const float* __restrict__ ar) {
    int n = blockIdx.x * blockDim.x + threadIdx.x;
    if (n >= NN) return;
    const float* fp = feat + (size_t)n * 16;
    float sl = 0.f, sr = 0.f;
#pragma unroll
    for (int d = 0; d < 16; d++) {
        float v = fp[d];
        sl += v * al[d];
        sr += v * ar[d];
    }
    g_el[n] = sl;
    g_er[n] = sr;
}

// ---------------- fused softmax-aggregate, H=4 heads per warp (fp16 gather) --
__device__ __forceinline__ float mishf(float x) {
    float sp = fmaxf(x, 0.f) + log1pf(__expf(-fabsf(x)));
    return x * tanhf(sp);
}

__device__ __forceinline__ float lrelu(float e) { return (e > 0.f) ? e : 0.2f * e; }

__global__ __launch_bounds__(256) void k_agg4(
    const __half* __restrict__ feath, const float* __restrict__ res,
    const float* __restrict__ bias, float* __restrict__ out) {
    int node = (blockIdx.x * blockDim.x + threadIdx.x) >> 5;
    int lane = threadIdx.x & 31;
    if (node >= NN) return;
    int start = g_rowptr[node], end = g_rowptr[node + 1];
    float4 er4 = *(const float4*)&g_er[node * 4];

    // pass 1: per-head max
    float m0 = -1e30f, m1 = -1e30f, m2 = -1e30f, m3 = -1e30f;
    for (int i = start + lane; i < end; i += 32) {
        int s = g_csr_src[i];
        float4 el4 = *(const float4*)&g_el[s * 4];
        m0 = fmaxf(m0, lrelu(el4.x + er4.x));
        m1 = fmaxf(m1, lrelu(el4.y + er4.y));
        m2 = fmaxf(m2, lrelu(el4.z + er4.z));
        m3 = fmaxf(m3, lrelu(el4.w + er4.w));
    }
#pragma unroll
    for (int o = 16; o; o >>= 1) {
        m0 = fmaxf(m0, __shfl_xor_sync(0xffffffffu, m0, o));
        m1 = fmaxf(m1, __shfl_xor_sync(0xffffffffu, m1, o));
        m2 = fmaxf(m2, __shfl_xor_sync(0xffffffffu, m2, o));
        m3 = fmaxf(m3, __shfl_xor_sync(0xffffffffu, m3, o));
    }

    // pass 2: 32-edge chunks; lane handles feature pair (2*lane, 2*lane+1) per head
    float2 a0 = {0.f, 0.f}, a1 = {0.f, 0.f}, a2 = {0.f, 0.f}, a3 = {0.f, 0.f};
    float ss0 = 0.f, ss1 = 0.f, ss2 = 0.f, ss3 = 0.f;
    for (int base = start; base < end; base += 32) {
        int i = base + lane;
        int s = 0;
        float w0 = 0.f, w1 = 0.f, w2 = 0.f, w3 = 0.f;
        if (i < end) {
            s = g_csr_src[i];
            float4 el4 = *(const float4*)&g_el[s * 4];
            w0 = __expf(lrelu(el4.x + er4.x) - m0);
            w1 = __expf(lrelu(el4.y + er4.y) - m1);
            w2 = __expf(lrelu(el4.z + er4.z) - m2);
            w3 = __expf(lrelu(el4.w + er4.w) - m3);
            ss0 += w0; ss1 += w1; ss2 += w2; ss3 += w3;
        }
        int cnt = min(32, end - base);
        for (int j = 0; j < cnt; j++) {
            int   sj = __shfl_sync(0xffffffffu, s, j);
            float b0 = __shfl_sync(0xffffffffu, w0, j);
            float b1 = __shfl_sync(0xffffffffu, w1, j);
            float b2 = __shfl_sync(0xffffffffu, w2, j);
            float b3 = __shfl_sync(0xffffffffu, w3, j);
            const __half2* fp = (const __half2*)(feath + (size_t)sj * 256);
            float2 f0 = __half22float2(fp[lane]);
            float2 f1 = __half22float2(fp[lane + 32]);
            float2 f2 = __half22float2(fp[lane + 64]);
            float2 f3 = __half22float2(fp[lane + 96]);
            a0.x += b0 * f0.x; a0.y += b0 * f0.y;
            a1.x += b1 * f1.x; a1.y += b1 * f1.y;
            a2.x += b2 * f2.x; a2.y += b2 * f2.y;
            a3.x += b3 * f3.x; a3.y += b3 * f3.y;
        }
    }
#pragma unroll
    for (int o = 16; o; o >>= 1) {
        ss0 += __shfl_xor_sync(0xffffffffu, ss0, o);
        ss1 += __shfl_xor_sync(0xffffffffu, ss1, o);
        ss2 += __shfl_xor_sync(0xffffffffu, ss2, o);
        ss3 += __shfl_xor_sync(0xffffffffu, ss3, o);
    }
    bool has = (end > start);
    float i0 = has ? 1.f / ss0 : 0.f;
    float i1 = has ? 1.f / ss1 : 0.f;
    float i2 = has ? 1.f / ss2 : 0.f;
    float i3 = has ? 1.f / ss3 : 0.f;

    size_t ob = (size_t)node * 256;
    int c = 2 * lane;
    float2 r0 = *(const float2*)&res[ob + c];
    float2 r1 = *(const float2*)&res[ob + 64 + c];
    float2 r2 = *(const float2*)&res[ob + 128 + c];
    float2 r3 = *(const float2*)&res[ob + 192 + c];
    float2 o0 = make_float2(mishf(a0.x * i0 + r0.x + bias[c]),
                            mishf(a0.y * i0 + r0.y + bias[c + 1]));
    float2 o1 = make_float2(mishf(a1.x * i1 + r1.x + bias[64 + c]),
                            mishf(a1.y * i1 + r1.y + bias[64 + c + 1]));
    float2 o2 = make_float2(mishf(a2.x * i2 + r2.x + bias[128 + c]),
                            mishf(a2.y * i2 + r2.y + bias[128 + c + 1]));
    float2 o3 = make_float2(mishf(a3.x * i3 + r3.x + bias[192 + c]),
                            mishf(a3.y * i3 + r3.y + bias[192 + c + 1]));
    *(float2*)&out[ob + c]       = o0;
    *(float2*)&out[ob + 64 + c]  = o1;
    *(float2*)&out[ob + 128 + c] = o2;
    *(float2*)&out[ob + 192 + c] = o3;
}

// ---------------- softmax-aggregate layer2, H=1 D=16 -------------------------
__global__ __launch_bounds__(256) void k_agg2(
    const float* __restrict__ feat, const float* __restrict__ res,
    const float* __restrict__ bias, float* __restrict__ out) {
    int node = (blockIdx.x * blockDim.x + threadIdx.x) >> 5;
    int lane = threadIdx.x & 31;
    if (node >= NN) return;
    int start = g_rowptr[node], end = g_rowptr[node + 1];
    float er_n = g_er[node];

    float m = -1e30f;
    for (int i = start + lane; i < end; i += 32) {
        int s = g_csr_src[i];
        m = fmaxf(m, lrelu(g_el[s] + er_n));
    }
#pragma unroll
    for (int o = 16; o; o >>= 1) m = fmaxf(m, __shfl_xor_sync(0xffffffffu, m, o));

    float acc = 0.f, ss = 0.f;
    for (int base = start; base < end; base += 32) {
        int i = base + lane;
        int s = 0;
        float w = 0.f;
        if (i < end) {
            s = g_csr_src[i];
            w = __expf(lrelu(g_el[s] + er_n) - m);
            ss += w;
        }
        int cnt = min(32, end - base);
        for (int j = 0; j < cnt; j++) {
            int   sj = __shfl_sync(0xffffffffu, s, j);
            float bw = __shfl_sync(0xffffffffu, w, j);
            if (lane < 16) acc += bw * feat[(size_t)sj * 16 + lane];
        }
    }
#pragma unroll
    for (int o = 16; o; o >>= 1) ss += __shfl_xor_sync(0xffffffffu, ss, o);
    float inv = (end > start) ? 1.f / ss : 0.f;
    if (lane < 16)
        out[(size_t)node * 16 + lane] = acc * inv + res[(size_t)node * 16 + lane] + bias[lane];
}

// ---------------- launch -----------------------------------------------------
extern "C" void kernel_launch(void* const* d_in, const int* in_sizes, int n_in,
                              void* d_out, int out_size) {
    const float* x    = (const float*)d_in[0];
    const int*   src  = (const int*)d_in[1];
    const int*   dst  = (const int*)d_in[2];
    const float* W0   = (const float*)d_in[3];
    const float* al0  = (const float*)d_in[4];
    const float* ar0  = (const float*)d_in[5];
    const float* b0   = (const float*)d_in[6];
    const float* W1   = (const float*)d_in[7];
    const float* al1  = (const float*)d_in[8];
    const float* ar1  = (const float*)d_in[9];
    const float* b1   = (const float*)d_in[10];
    const float* W2   = (const float*)d_in[11];
    const float* al2  = (const float*)d_in[12];
    const float* ar2  = (const float*)d_in[13];
    const float* b2   = (const float*)d_in[14];
    const float* rW2  = (const float*)d_in[15];
    float* out = (float*)d_out;

    float *feat, *h1, *h2, *feat2, *res2;
    __half* feath;
    cudaGetSymbolAddress((void**)&feat,  g_feat);
    cudaGetSymbolAddress((void**)&feath, g_feat_h);
    cudaGetSymbolAddress((void**)&h1,    g_h1);
    cudaGetSymbolAddress((void**)&h2,    g_h2);
    cudaGetSymbolAddress((void**)&feat2, g_feat2);
    cudaGetSymbolAddress((void**)&res2,  g_res2);

    // ---- CSR by dst
    k_zero_deg<<<(NN + 255) / 256, 256>>>();
    k_hist<<<(NE + 255) / 256, 256>>>(dst);
    k_scan<<<1, 1024>>>();
    k_scatter<<<(NE + 255) / 256, 256>>>(src, dst);

    dim3 gtc(256 / 64, (NN + 127) / 128);
    int elrBlocks = (NN * 4 * 32 + 255) / 256;
    int aggBlocks = (NN * 32 + 255) / 256;

    // ---- layer 0
    k_gemm_tc<<<gtc, 256>>>(x, W0, feat, feath, NN, 256, 256);
    k_elr4<<<elrBlocks, 256>>>(feat, al0, ar0);
    k_agg4<<<aggBlocks, 256>>>(feath, x, b0, h1);

    // ---- layer 1
    k_gemm_tc<<<gtc, 256>>>(h1, W1, feat, feath, NN, 256, 256);
    k_elr4<<<elrBlocks, 256>>>(feat, al1, ar1);
    k_agg4<<<aggBlocks, 256>>>(feath, h1, b1, h2);

    // ---- layer 2
    k_gemm16x2<<<(NN * 32 + 255) / 256, 256>>>(h2, W2, rW2, feat2, res2);
    k_elr2<<<(NN + 255) / 256, 256>>>(feat2, al2, ar2);
    k_agg2<<<aggBlocks, 256>>>(feat2, res2, b2, out);
}

// round 5
// speedup vs baseline: 1.8547x; 1.0891x over previous
#include <cuda_runtime.h>
#include <cuda_fp16.h>
#include <math.h>
#include <stdint.h>

#define NN 50000
#define NE 800000

// ---------------- scratch (static device globals; no allocation allowed) ----
__device__ __align__(16) float g_feat[NN * 256];    // GEMM output per layer (fp32)
__device__ __align__(16) __half g_feat_h[NN * 256]; // fp16 gather copy
__device__ __align__(16) float g_h1[NN * 256];
__device__ __align__(16) float g_h2[NN * 256];
__device__ __align__(16) float g_feat2[NN * 16];
__device__ __align__(16) float g_res2[NN * 16];
__device__ __align__(16) float g_el[NN * 4];
__device__ __align__(16) float g_er[NN * 4];
__device__ int   g_deg[NN];
__device__ int   g_rowptr[NN + 1];
__device__ int   g_pos[NN];
__device__ int   g_csr_src[NE];

// ---------------- CSR build ------------------------------------------------
__global__ void k_zero_deg() {
    int i = blockIdx.x * blockDim.x + threadIdx.x;
    if (i < NN) g_deg[i] = 0;
}

__global__ void k_hist(const int* __restrict__ dst) {
    int e = blockIdx.x * blockDim.x + threadIdx.x;
    if (e < NE) atomicAdd(&g_deg[dst[e]], 1);
}

// single block, 1024 threads; serial per-thread chunk + shfl block scan
__global__ void k_scan() {
    __shared__ int warp_pref[32];
    const int T = 1024;
    int t = threadIdx.x;
    const int per = (NN + T - 1) / T;
    int begin = t * per;
    int end = min(begin + per, NN);
    if (begin > NN) begin = NN;
    if (end < begin) end = begin;

    int sum = 0;
    for (int i = begin; i < end; i++) sum += g_deg[i];

    int lane = t & 31, wid = t >> 5;
    int v = sum;
#pragma unroll
    for (int o = 1; o < 32; o <<= 1) {
        int u = __shfl_up_sync(0xffffffffu, v, o);
        if (lane >= o) v += u;
    }
    if (lane == 31) warp_pref[wid] = v;
    __syncthreads();
    if (wid == 0) {
        int w = warp_pref[lane];
#pragma unroll
        for (int o = 1; o < 32; o <<= 1) {
            int u = __shfl_up_sync(0xffffffffu, w, o);
            if (lane >= o) w += u;
        }
        warp_pref[lane] = w;
    }
    __syncthreads();
    int excl = v - sum + (wid ? warp_pref[wid - 1] : 0);

    int run = excl;
    for (int i = begin; i < end; i++) {
        g_rowptr[i] = run;
        g_pos[i] = run;
        run += g_deg[i];
    }
    if (t == T - 1) g_rowptr[NN] = run;
}

__global__ void k_scatter(const int* __restrict__ src, const int* __restrict__ dst) {
    int e = blockIdx.x * blockDim.x + threadIdx.x;
    if (e < NE) {
        int p = atomicAdd(&g_pos[dst[e]], 1);
        g_csr_src[p] = src[e];
    }
}

// ---------------- tensor-core GEMM (3-term fp16 split, ~fp32-accurate) ------
// C[M,N] = A[M,K] @ B[K,N]; BM=128 BN=64 BK=16, 8 warps (4 m x 2 n).
// Elements pre-split to (hi,lo) fp16 at smem staging, stored in MMA-fragment
// layout: Ah[row][half2 col-pair], Bh[k-pair][n].

__device__ __forceinline__ void mma16(float* d, const uint32_t* a, const uint32_t* b) {
    asm volatile(
        "mma.sync.aligned.m16n8k16.row.col.f32.f16.f16.f32 "
        "{%0,%1,%2,%3}, {%4,%5,%6,%7}, {%8,%9}, {%0,%1,%2,%3};\n"
        : "+f"(d[0]), "+f"(d[1]), "+f"(d[2]), "+f"(d[3])
        : "r"(a[0]), "r"(a[1]), "r"(a[2]), "r"(a[3]), "r"(b[0]), "r"(b[1]));
}

__device__ __forceinline__ void split2(float x, float y, __half2& hi, __half2& lo) {
    __half hx = __float2half_rn(x), hy = __float2half_rn(y);
    hi = __halves2half2(hx, hy);
    lo = __floats2half2_rn(x - __half2float(hx), y - __half2float(hy));
}

#define ASTR 9    // half2 words per A row (8 + 1 pad)
#define BSTR 72   // half2 words per B k-pair row (64 + 8 pad)

__global__ __launch_bounds__(256, 2) void k_gemm_tc(
    const float* __restrict__ A, const float* __restrict__ B,
    float* __restrict__ C, __half* __restrict__ Ch, int M, int K, int N) {
    __shared__ __half2 Ah[2][128][ASTR];
    __shared__ __half2 Al[2][128][ASTR];
    __shared__ __half2 Bh[2][8][BSTR];
    __shared__ __half2 Bl[2][8][BSTR];

    int tid = threadIdx.x;
    int lane = tid & 31;
    int wid = tid >> 5;
    int m_base = (wid >> 1) * 32;
    int n_base = (wid & 1) * 32;
    int row0 = blockIdx.y * 128;
    int col0 = blockIdx.x * 64;

    float acc[2][4][4];
#pragma unroll
    for (int mt = 0; mt < 2; mt++)
#pragma unroll
        for (int nt = 0; nt < 4; nt++)
#pragma unroll
            for (int i = 0; i < 4; i++) acc[mt][nt][i] = 0.f;

    // staging indices
    int ar = tid >> 2;            // 0..63 (A rows; +64 for second)
    int ac = (tid & 3) * 4;       // element col 0,4,8,12
    int br = tid >> 4;            // 0..15 (B k row)
    int bc = (tid & 15) * 4;      // element col 0..60
    int gr0 = row0 + ar;
    int gr1 = gr0 + 64;
    int kp = br >> 1, par = br & 1;
    const float4 f4z = make_float4(0.f, 0.f, 0.f, 0.f);

    // fragment indices
    int jq = lane >> 2;           // 0..7
    int jc = lane & 3;            // 0..3

    // stage into buffer st from registers
    auto stage = [&](int st, const float4& va, const float4& vb, const float4& vc) {
        __half2 h0, l0, h1, l1;
        split2(va.x, va.y, h0, l0); split2(va.z, va.w, h1, l1);
        Ah[st][ar][ac >> 1] = h0;  Ah[st][ar][(ac >> 1) + 1] = h1;
        Al[st][ar][ac >> 1] = l0;  Al[st][ar][(ac >> 1) + 1] = l1;
        split2(vb.x, vb.y, h0, l0); split2(vb.z, vb.w, h1, l1);
        Ah[st][ar + 64][ac >> 1] = h0;  Ah[st][ar + 64][(ac >> 1) + 1] = h1;
        Al[st][ar + 64][ac >> 1] = l0;  Al[st][ar + 64][(ac >> 1) + 1] = l1;
        // B: halves go into .x/.y of Bh[kp][n] by k parity
        __half* bhp = (__half*)&Bh[st][kp][0];
        __half* blp = (__half*)&Bl[st][kp][0];
        float bf[4] = {vc.x, vc.y, vc.z, vc.w};
#pragma unroll
        for (int i = 0; i < 4; i++) {
            __half hh = __float2half_rn(bf[i]);
            bhp[2 * (bc + i) + par] = hh;
            blp[2 * (bc + i) + par] = __float2half_rn(bf[i] - __half2float(hh));
        }
    };

    {
        float4 va = (gr0 < M) ? *(const float4*)(A + (size_t)gr0 * K + ac) : f4z;
        float4 vb = (gr1 < M) ? *(const float4*)(A + (size_t)gr1 * K + ac) : f4z;
        float4 vc = *(const float4*)(B + (size_t)br * N + col0 + bc);
        stage(0, va, vb, vc);
    }
    __syncthreads();

    int NS = K / 16;
    for (int s = 0; s < NS; s++) {
        int cur = s & 1;
        float4 va, vb, vc;
        bool more = (s + 1 < NS);
        if (more) {
            int k0 = (s + 1) * 16;
            va = (gr0 < M) ? *(const float4*)(A + (size_t)gr0 * K + k0 + ac) : f4z;
            vb = (gr1 < M) ? *(const float4*)(A + (size_t)gr1 * K + k0 + ac) : f4z;
            vc = *(const float4*)(B + (size_t)(k0 + br) * N + col0 + bc);
        }

        uint32_t ah[2][4], al_[2][4];
#pragma unroll
        for (int mt = 0; mt < 2; mt++) {
            int r = m_base + mt * 16 + jq;
            ah[mt][0] = *(const uint32_t*)&Ah[cur][r][jc];
            ah[mt][1] = *(const uint32_t*)&Ah[cur][r + 8][jc];
            ah[mt][2] = *(const uint32_t*)&Ah[cur][r][jc + 4];
            ah[mt][3] = *(const uint32_t*)&Ah[cur][r + 8][jc + 4];
            al_[mt][0] = *(const uint32_t*)&Al[cur][r][jc];
            al_[mt][1] = *(const uint32_t*)&Al[cur][r + 8][jc];
            al_[mt][2] = *(const uint32_t*)&Al[cur][r][jc + 4];
            al_[mt][3] = *(const uint32_t*)&Al[cur][r + 8][jc + 4];
        }
        uint32_t bh[4][2], bl[4][2];
#pragma unroll
        for (int nt = 0; nt < 4; nt++) {
            int n = n_base + nt * 8 + jq;
            bh[nt][0] = *(const uint32_t*)&Bh[cur][jc][n];
            bh[nt][1] = *(const uint32_t*)&Bh[cur][jc + 4][n];
            bl[nt][0] = *(const uint32_t*)&Bl[cur][jc][n];
            bl[nt][1] = *(const uint32_t*)&Bl[cur][jc + 4][n];
        }
#pragma unroll
        for (int mt = 0; mt < 2; mt++)
#pragma unroll
            for (int nt = 0; nt < 4; nt++) {
                mma16(acc[mt][nt], ah[mt], bh[nt]);
                mma16(acc[mt][nt], al_[mt], bh[nt]);
                mma16(acc[mt][nt], ah[mt], bl[nt]);
            }

        if (more) stage(cur ^ 1, va, vb, vc);
        __syncthreads();
    }

#pragma unroll
    for (int mt = 0; mt < 2; mt++)
#pragma unroll
        for (int nt = 0; nt < 4; nt++) {
            int r = row0 + m_base + mt * 16 + jq;
            int c = col0 + n_base + nt * 8 + 2 * jc;
            if (r < M) {
                *(float2*)&C[(size_t)r * N + c] = make_float2(acc[mt][nt][0], acc[mt][nt][1]);
                *(__half2*)&Ch[(size_t)r * N + c] =
                    __floats2half2_rn(acc[mt][nt][0], acc[mt][nt][1]);
            }
            if (r + 8 < M) {
                *(float2*)&C[(size_t)(r + 8) * N + c] = make_float2(acc[mt][nt][2], acc[mt][nt][3]);
                *(__half2*)&Ch[(size_t)(r + 8) * N + c] =
                    __floats2half2_rn(acc[mt][nt][2], acc[mt][nt][3]);
            }
        }
}

// ---------------- fused dual small GEMM: C1/C2[N,16] = A[N,256] @ B1/B2 -----
__global__ void k_gemm16x2(const float* __restrict__ A, const float* __restrict__ B1,
                           const float* __restrict__ B2, float* __restrict__ C1,
                           float* __restrict__ C2) {
    __shared__ float Bs[256 * 32];
    for (int i = threadIdx.x; i < 256 * 16; i += blockDim.x) {
        Bs[(i >> 4) * 32 + (i & 15)] = B1[i];
        Bs[(i >> 4) * 32 + 16 + (i & 15)] = B2[i];
    }
    __syncthreads();
    int tid = blockIdx.x * blockDim.x + threadIdx.x;
    int f = tid & 31, node = tid >> 5;
    if (node >= NN) return;
    const float* a = A + (size_t)node * 256;
    float acc = 0.f;
#pragma unroll 8
    for (int k = 0; k < 256; k++) acc += a[k] * Bs[k * 32 + f];
    if (f < 16) C1[node * 16 + f] = acc;
    else        C2[node * 16 + f - 16] = acc;
}

// ---------------- el/er, coalesced: warp per (node, head), H=4 D=64 ---------
__global__ void k_elr4(const float* __restrict__ feat, const float* __restrict__ al,
                       const float* __restrict__ ar) {
    int w = (blockIdx.x * blockDim.x + threadIdx.x) >> 5;
    if (w >= NN * 4) return;
    int lane = threadIdx.x & 31;
    int node = w >> 2, h = w & 3;
    const float* fp = feat + (size_t)node * 256 + h * 64;
    float v0 = fp[lane], v1 = fp[lane + 32];
    float sl = v0 * al[h * 64 + lane] + v1 * al[h * 64 + lane + 32];
    float sr = v0 * ar[h * 64 + lane] + v1 * ar[h * 64 + lane + 32];
#pragma unroll
    for (int o = 16; o; o >>= 1) {
        sl += __shfl_xor_sync(0xffffffffu, sl, o);
        sr += __shfl_xor_sync(0xffffffffu, sr, o);
    }
    if (lane == 0) { g_el[w] = sl; g_er[w] = sr; }
}

__global__ void k_elr2(const float* __restrict__ feat, const float* __restrict__ al,
                       const float* __restrict__ ar) {
    int n = blockIdx.x * blockDim.x + threadIdx.x;
    if (n >= NN) return;
    const float* fp = feat + (size_t)n * 16;
    float sl = 0.f, sr = 0.f;
#pragma unroll
    for (int d = 0; d < 16; d++) {
        float v = fp[d];
        sl += v * al[d];
        sr += v * ar[d];
    }
    g_el[n] = sl;
    g_er[n] = sr;
}

// ---------------- fused softmax-aggregate (no max pass; exp(e) is bounded) --
__device__ __forceinline__ float mishf(float x) {
    float sp = fmaxf(x, 0.f) + log1pf(__expf(-fabsf(x)));
    return x * tanhf(sp);
}

__device__ __forceinline__ float lrelu(float e) { return (e > 0.f) ? e : 0.2f * e; }

__global__ __launch_bounds__(256) void k_agg4(
    const __half* __restrict__ feath, const float* __restrict__ res,
    const float* __restrict__ bias, float* __restrict__ out) {
    int node = (blockIdx.x * blockDim.x + threadIdx.x) >> 5;
    int lane = threadIdx.x & 31;
    if (node >= NN) return;
    int start = g_rowptr[node], end = g_rowptr[node + 1];
    float4 er4 = *(const float4*)&g_er[node * 4];

    float2 a0 = {0.f, 0.f}, a1 = {0.f, 0.f}, a2 = {0.f, 0.f}, a3 = {0.f, 0.f};
    float ss0 = 0.f, ss1 = 0.f, ss2 = 0.f, ss3 = 0.f;
    for (int base = start; base < end; base += 32) {
        int i = base + lane;
        int s = 0;
        float w0 = 0.f, w1 = 0.f, w2 = 0.f, w3 = 0.f;
        if (i < end) {
            s = g_csr_src[i];
            float4 el4 = *(const float4*)&g_el[s * 4];
            w0 = __expf(lrelu(el4.x + er4.x));
            w1 = __expf(lrelu(el4.y + er4.y));
            w2 = __expf(lrelu(el4.z + er4.z));
            w3 = __expf(lrelu(el4.w + er4.w));
            ss0 += w0; ss1 += w1; ss2 += w2; ss3 += w3;
        }
        int cnt = min(32, end - base);
        for (int j = 0; j < cnt; j++) {
            int   sj = __shfl_sync(0xffffffffu, s, j);
            float b0 = __shfl_sync(0xffffffffu, w0, j);
            float b1 = __shfl_sync(0xffffffffu, w1, j);
            float b2 = __shfl_sync(0xffffffffu, w2, j);
            float b3 = __shfl_sync(0xffffffffu, w3, j);
            const __half2* fp = (const __half2*)(feath + (size_t)sj * 256);
            float2 f0 = __half22float2(fp[lane]);
            float2 f1 = __half22float2(fp[lane + 32]);
            float2 f2 = __half22float2(fp[lane + 64]);
            float2 f3 = __half22float2(fp[lane + 96]);
            a0.x += b0 * f0.x; a0.y += b0 * f0.y;
            a1.x += b1 * f1.x; a1.y += b1 * f1.y;
            a2.x += b2 * f2.x; a2.y += b2 * f2.y;
            a3.x += b3 * f3.x; a3.y += b3 * f3.y;
        }
    }
#pragma unroll
    for (int o = 16; o; o >>= 1) {
        ss0 += __shfl_xor_sync(0xffffffffu, ss0, o);
        ss1 += __shfl_xor_sync(0xffffffffu, ss1, o);
        ss2 += __shfl_xor_sync(0xffffffffu, ss2, o);
        ss3 += __shfl_xor_sync(0xffffffffu, ss3, o);
    }
    bool has = (end > start);
    float i0 = has ? 1.f / ss0 : 0.f;
    float i1 = has ? 1.f / ss1 : 0.f;
    float i2 = has ? 1.f / ss2 : 0.f;
    float i3 = has ? 1.f / ss3 : 0.f;

    size_t ob = (size_t)node * 256;
    int c = 2 * lane;
    float2 r0 = *(const float2*)&res[ob + c];
    float2 r1 = *(const float2*)&res[ob + 64 + c];
    float2 r2 = *(const float2*)&res[ob + 128 + c];
    float2 r3 = *(const float2*)&res[ob + 192 + c];
    float2 o0 = make_float2(mishf(a0.x * i0 + r0.x + bias[c]),
                            mishf(a0.y * i0 + r0.y + bias[c + 1]));
    float2 o1 = make_float2(mishf(a1.x * i1 + r1.x + bias[64 + c]),
                            mishf(a1.y * i1 + r1.y + bias[64 + c + 1]));
    float2 o2 = make_float2(mishf(a2.x * i2 + r2.x + bias[128 + c]),
                            mishf(a2.y * i2 + r2.y + bias[128 + c + 1]));
    float2 o3 = make_float2(mishf(a3.x * i3 + r3.x + bias[192 + c]),
                            mishf(a3.y * i3 + r3.y + bias[192 + c + 1]));
    *(float2*)&out[ob + c]       = o0;
    *(float2*)&out[ob + 64 + c]  = o1;
    *(float2*)&out[ob + 128 + c] = o2;
    *(float2*)&out[ob + 192 + c] = o3;
}

// ---------------- softmax-aggregate layer2, H=1 D=16 -------------------------
__global__ __launch_bounds__(256) void k_agg2(
    const float* __restrict__ feat, const float* __restrict__ res,
    const float* __restrict__ bias, float* __restrict__ out) {
    int node = (blockIdx.x * blockDim.x + threadIdx.x) >> 5;
    int lane = threadIdx.x & 31;
    if (node >= NN) return;
    int start = g_rowptr[node], end = g_rowptr[node + 1];
    float er_n = g_er[node];

    float acc = 0.f, ss = 0.f;
    for (int base = start; base < end; base += 32) {
        int i = base + lane;
        int s = 0;
        float w = 0.f;
        if (i < end) {
            s = g_csr_src[i];
            w = __expf(lrelu(g_el[s] + er_n));
            ss += w;
        }
        int cnt = min(32, end - base);
        for (int j = 0; j < cnt; j++) {
            int   sj = __shfl_sync(0xffffffffu, s, j);
            float bw = __shfl_sync(0xffffffffu, w, j);
            if (lane < 16) acc += bw * feat[(size_t)sj * 16 + lane];
        }
    }
#pragma unroll
    for (int o = 16; o; o >>= 1) ss += __shfl_xor_sync(0xffffffffu, ss, o);
    float inv = (end > start) ? 1.f / ss : 0.f;
    if (lane < 16)
        out[(size_t)node * 16 + lane] = acc * inv + res[(size_t)node * 16 + lane] + bias[lane];
}

// ---------------- launch -----------------------------------------------------
extern "C" void kernel_launch(void* const* d_in, const int* in_sizes, int n_in,
                              void* d_out, int out_size) {
    const float* x    = (const float*)d_in[0];
    const int*   src  = (const int*)d_in[1];
    const int*   dst  = (const int*)d_in[2];
    const float* W0   = (const float*)d_in[3];
    const float* al0  = (const float*)d_in[4];
    const float* ar0  = (const float*)d_in[5];
    const float* b0   = (const float*)d_in[6];
    const float* W1   = (const float*)d_in[7];
    const float* al1  = (const float*)d_in[8];
    const float* ar1  = (const float*)d_in[9];
    const float* b1   = (const float*)d_in[10];
    const float* W2   = (const float*)d_in[11];
    const float* al2  = (const float*)d_in[12];
    const float* ar2  = (const float*)d_in[13];
    const float* b2   = (const float*)d_in[14];
    const float* rW2  = (const float*)d_in[15];
    float* out = (float*)d_out;

    float *feat, *h1, *h2, *feat2, *res2;
    __half* feath;
    cudaGetSymbolAddress((void**)&feat,  g_feat);
    cudaGetSymbolAddress((void**)&feath, g_feat_h);
    cudaGetSymbolAddress((void**)&h1,    g_h1);
    cudaGetSymbolAddress((void**)&h2,    g_h2);
    cudaGetSymbolAddress((void**)&feat2, g_feat2);
    cudaGetSymbolAddress((void**)&res2,  g_res2);

    // ---- CSR by dst
    k_zero_deg<<<(NN + 255) / 256, 256>>>();
    k_hist<<<(NE + 255) / 256, 256>>>(dst);
    k_scan<<<1, 1024>>>();
    k_scatter<<<(NE + 255) / 256, 256>>>(src, dst);

    dim3 gtc(256 / 64, (NN + 127) / 128);
    int elrBlocks = (NN * 4 * 32 + 255) / 256;
    int aggBlocks = (NN * 32 + 255) / 256;

    // ---- layer 0
    k_gemm_tc<<<gtc, 256>>>(x, W0, feat, feath, NN, 256, 256);
    k_elr4<<<elrBlocks, 256>>>(feat, al0, ar0);
    k_agg4<<<aggBlocks, 256>>>(feath, x, b0, h1);

    // ---- layer 1
    k_gemm_tc<<<gtc, 256>>>(h1, W1, feat, feath, NN, 256, 256);
    k_elr4<<<elrBlocks, 256>>>(feat, al1, ar1);
    k_agg4<<<aggBlocks, 256>>>(feath, h1, b1, h2);

    // ---- layer 2
    k_gemm16x2<<<(NN * 32 + 255) / 256, 256>>>(h2, W2, rW2, feat2, res2);
    k_elr2<<<(NN + 255) / 256, 256>>>(feat2, al2, ar2);
    k_agg2<<<aggBlocks, 256>>>(feat2, res2, b2, out);
}

// round 6
// speedup vs baseline: 1.9563x; 1.0548x over previous
#include <cuda_runtime.h>
#include <cuda_fp16.h>
#include <math.h>
#include <stdint.h>

#define NN 50000
#define NE 800000

// ---------------- scratch (static device globals; no allocation allowed) ----
__device__ __align__(16) __half g_feat_h[NN * 256]; // fp16 gather copy (layers 0/1)
__device__ __align__(16) float g_h1[NN * 256];
__device__ __align__(16) float g_h2[NN * 256];
__device__ __align__(16) float g_feat2[NN * 16];
__device__ __align__(16) float g_res2[NN * 16];
__device__ __align__(16) float g_el[NN * 4];
__device__ __align__(16) float g_er[NN * 4];
__device__ int   g_deg[NN];
__device__ int   g_rowptr[NN + 1];
__device__ int   g_pos[NN];
__device__ int   g_csr_src[NE];

// ---------------- CSR build ------------------------------------------------
__global__ void k_zero_deg() {
    int i = blockIdx.x * blockDim.x + threadIdx.x;
    if (i < NN) g_deg[i] = 0;
}

__global__ void k_hist(const int* __restrict__ dst) {
    int e = blockIdx.x * blockDim.x + threadIdx.x;
    if (e < NE) atomicAdd(&g_deg[dst[e]], 1);
}

__global__ void k_scan() {
    __shared__ int warp_pref[32];
    const int T = 1024;
    int t = threadIdx.x;
    const int per = (NN + T - 1) / T;
    int begin = t * per;
    int end = min(begin + per, NN);
    if (begin > NN) begin = NN;
    if (end < begin) end = begin;

    int sum = 0;
    for (int i = begin; i < end; i++) sum += g_deg[i];

    int lane = t & 31, wid = t >> 5;
    int v = sum;
#pragma unroll
    for (int o = 1; o < 32; o <<= 1) {
        int u = __shfl_up_sync(0xffffffffu, v, o);
        if (lane >= o) v += u;
    }
    if (lane == 31) warp_pref[wid] = v;
    __syncthreads();
    if (wid == 0) {
        int w = warp_pref[lane];
#pragma unroll
        for (int o = 1; o < 32; o <<= 1) {
            int u = __shfl_up_sync(0xffffffffu, w, o);
            if (lane >= o) w += u;
        }
        warp_pref[lane] = w;
    }
    __syncthreads();
    int excl = v - sum + (wid ? warp_pref[wid - 1] : 0);

    int run = excl;
    for (int i = begin; i < end; i++) {
        g_rowptr[i] = run;
        g_pos[i] = run;
        run += g_deg[i];
    }
    if (t == T - 1) g_rowptr[NN] = run;
}

__global__ void k_scatter(const int* __restrict__ src, const int* __restrict__ dst) {
    int e = blockIdx.x * blockDim.x + threadIdx.x;
    if (e < NE) {
        int p = atomicAdd(&g_pos[dst[e]], 1);
        g_csr_src[p] = src[e];
    }
}

// ---------------- tensor-core GEMM (3-term fp16 split) + fused el/er --------
__device__ __forceinline__ void mma16(float* d, const uint32_t* a, const uint32_t* b) {
    asm volatile(
        "mma.sync.aligned.m16n8k16.row.col.f32.f16.f16.f32 "
        "{%0,%1,%2,%3}, {%4,%5,%6,%7}, {%8,%9}, {%0,%1,%2,%3};\n"
        : "+f"(d[0]), "+f"(d[1]), "+f"(d[2]), "+f"(d[3])
        : "r"(a[0]), "r"(a[1]), "r"(a[2]), "r"(a[3]), "r"(b[0]), "r"(b[1]));
}

__device__ __forceinline__ void split2(float x, float y, __half2& hi, __half2& lo) {
    __half hx = __float2half_rn(x), hy = __float2half_rn(y);
    hi = __halves2half2(hx, hy);
    lo = __floats2half2_rn(x - __half2float(hx), y - __half2float(hy));
}

#define ASTR 9
#define BSTR 72

__global__ __launch_bounds__(256, 2) void k_gemm_tc(
    const float* __restrict__ A, const float* __restrict__ B,
    __half* __restrict__ Ch, const float* __restrict__ pal,
    const float* __restrict__ pare, int M, int K, int N) {
    __shared__ __half2 Ah[2][128][ASTR];
    __shared__ __half2 Al[2][128][ASTR];
    __shared__ __half2 Bh[2][8][BSTR];
    __shared__ __half2 Bl[2][8][BSTR];
    __shared__ float s_el[2][128];
    __shared__ float s_er[2][128];

    int tid = threadIdx.x;
    int lane = tid & 31;
    int wid = tid >> 5;
    int warp_n = wid & 1;
    int m_base = (wid >> 1) * 32;
    int n_base = warp_n * 32;
    int row0 = blockIdx.y * 128;
    int col0 = blockIdx.x * 64;
    int head = col0 >> 6;

    float acc[2][4][4];
#pragma unroll
    for (int mt = 0; mt < 2; mt++)
#pragma unroll
        for (int nt = 0; nt < 4; nt++)
#pragma unroll
            for (int i = 0; i < 4; i++) acc[mt][nt][i] = 0.f;

    int ar = tid >> 2;
    int ac = (tid & 3) * 4;
    int br = tid >> 4;
    int bc = (tid & 15) * 4;
    int gr0 = row0 + ar;
    int gr1 = gr0 + 64;
    int kp = br >> 1, par = br & 1;
    const float4 f4z = make_float4(0.f, 0.f, 0.f, 0.f);

    int jq = lane >> 2;
    int jc = lane & 3;

    auto stage = [&](int st, const float4& va, const float4& vb, const float4& vc) {
        __half2 h0, l0, h1, l1;
        split2(va.x, va.y, h0, l0); split2(va.z, va.w, h1, l1);
        Ah[st][ar][ac >> 1] = h0;  Ah[st][ar][(ac >> 1) + 1] = h1;
        Al[st][ar][ac >> 1] = l0;  Al[st][ar][(ac >> 1) + 1] = l1;
        split2(vb.x, vb.y, h0, l0); split2(vb.z, vb.w, h1, l1);
        Ah[st][ar + 64][ac >> 1] = h0;  Ah[st][ar + 64][(ac >> 1) + 1] = h1;
        Al[st][ar + 64][ac >> 1] = l0;  Al[st][ar + 64][(ac >> 1) + 1] = l1;
        __half* bhp = (__half*)&Bh[st][kp][0];
        __half* blp = (__half*)&Bl[st][kp][0];
        float bf[4] = {vc.x, vc.y, vc.z, vc.w};
#pragma unroll
        for (int i = 0; i < 4; i++) {
            __half hh = __float2half_rn(bf[i]);
            bhp[2 * (bc + i) + par] = hh;
            blp[2 * (bc + i) + par] = __float2half_rn(bf[i] - __half2float(hh));
        }
    };

    {
        float4 va = (gr0 < M) ? *(const float4*)(A + (size_t)gr0 * K + ac) : f4z;
        float4 vb = (gr1 < M) ? *(const float4*)(A + (size_t)gr1 * K + ac) : f4z;
        float4 vc = *(const float4*)(B + (size_t)br * N + col0 + bc);
        stage(0, va, vb, vc);
    }
    __syncthreads();

    int NS = K / 16;
    for (int s = 0; s < NS; s++) {
        int cur = s & 1;
        float4 va, vb, vc;
        bool more = (s + 1 < NS);
        if (more) {
            int k0 = (s + 1) * 16;
            va = (gr0 < M) ? *(const float4*)(A + (size_t)gr0 * K + k0 + ac) : f4z;
            vb = (gr1 < M) ? *(const float4*)(A + (size_t)gr1 * K + k0 + ac) : f4z;
            vc = *(const float4*)(B + (size_t)(k0 + br) * N + col0 + bc);
        }

        uint32_t ah[2][4], al_[2][4];
#pragma unroll
        for (int mt = 0; mt < 2; mt++) {
            int r = m_base + mt * 16 + jq;
            ah[mt][0] = *(const uint32_t*)&Ah[cur][r][jc];
            ah[mt][1] = *(const uint32_t*)&Ah[cur][r + 8][jc];
            ah[mt][2] = *(const uint32_t*)&Ah[cur][r][jc + 4];
            ah[mt][3] = *(const uint32_t*)&Ah[cur][r + 8][jc + 4];
            al_[mt][0] = *(const uint32_t*)&Al[cur][r][jc];
            al_[mt][1] = *(const uint32_t*)&Al[cur][r + 8][jc];
            al_[mt][2] = *(const uint32_t*)&Al[cur][r][jc + 4];
            al_[mt][3] = *(const uint32_t*)&Al[cur][r + 8][jc + 4];
        }
        uint32_t bh[4][2], bl[4][2];
#pragma unroll
        for (int nt = 0; nt < 4; nt++) {
            int n = n_base + nt * 8 + jq;
            bh[nt][0] = *(const uint32_t*)&Bh[cur][jc][n];
            bh[nt][1] = *(const uint32_t*)&Bh[cur][jc + 4][n];
            bl[nt][0] = *(const uint32_t*)&Bl[cur][jc][n];
            bl[nt][1] = *(const uint32_t*)&Bl[cur][jc + 4][n];
        }
#pragma unroll
        for (int mt = 0; mt < 2; mt++)
#pragma unroll
            for (int nt = 0; nt < 4; nt++) {
                mma16(acc[mt][nt], ah[mt], bh[nt]);
                mma16(acc[mt][nt], al_[mt], bh[nt]);
                mma16(acc[mt][nt], ah[mt], bl[nt]);
            }

        if (more) stage(cur ^ 1, va, vb, vc);
        __syncthreads();
    }

    // ---- fp16 feature store + fused el/er -----------------------------------
    float elv[4] = {0.f, 0.f, 0.f, 0.f}, erv[4] = {0.f, 0.f, 0.f, 0.f};
#pragma unroll
    for (int mt = 0; mt < 2; mt++)
#pragma unroll
        for (int nt = 0; nt < 4; nt++) {
            int r = row0 + m_base + mt * 16 + jq;
            int cl = n_base + nt * 8 + 2 * jc;      // 0..63 within head
            int c = col0 + cl;
            if (r < M)
                *(__half2*)&Ch[(size_t)r * N + c] =
                    __floats2half2_rn(acc[mt][nt][0], acc[mt][nt][1]);
            if (r + 8 < M)
                *(__half2*)&Ch[(size_t)(r + 8) * N + c] =
                    __floats2half2_rn(acc[mt][nt][2], acc[mt][nt][3]);
            float w0 = pal[c], w1 = pal[c + 1];
            float u0 = pare[c], u1 = pare[c + 1];
            elv[mt * 2]     += acc[mt][nt][0] * w0 + acc[mt][nt][1] * w1;
            elv[mt * 2 + 1] += acc[mt][nt][2] * w0 + acc[mt][nt][3] * w1;
            erv[mt * 2]     += acc[mt][nt][0] * u0 + acc[mt][nt][1] * u1;
            erv[mt * 2 + 1] += acc[mt][nt][2] * u0 + acc[mt][nt][3] * u1;
        }
#pragma unroll
    for (int o = 1; o <= 2; o <<= 1) {
#pragma unroll
        for (int i = 0; i < 4; i++) {
            elv[i] += __shfl_xor_sync(0xffffffffu, elv[i], o);
            erv[i] += __shfl_xor_sync(0xffffffffu, erv[i], o);
        }
    }
    if (jc == 0) {
#pragma unroll
        for (int i = 0; i < 4; i++) {
            int lr = m_base + (i >> 1) * 16 + (i & 1) * 8 + jq;
            s_el[warp_n][lr] = elv[i];
            s_er[warp_n][lr] = erv[i];
        }
    }
    __syncthreads();
    if (tid < 128) {
        int r = row0 + tid;
        if (r < M) {
            g_el[r * 4 + head] = s_el[0][tid] + s_el[1][tid];
            g_er[r * 4 + head] = s_er[0][tid] + s_er[1][tid];
        }
    }
}

// ---------------- fused dual small GEMM + layer2 el/er -----------------------
__global__ void k_gemm16x2(const float* __restrict__ A, const float* __restrict__ B1,
                           const float* __restrict__ B2, float* __restrict__ C1,
                           float* __restrict__ C2, const float* __restrict__ al2,
                           const float* __restrict__ ar2) {
    __shared__ float Bs[256 * 32];
    for (int i = threadIdx.x; i < 256 * 16; i += blockDim.x) {
        Bs[(i >> 4) * 32 + (i & 15)] = B1[i];
        Bs[(i >> 4) * 32 + 16 + (i & 15)] = B2[i];
    }
    __syncthreads();
    int tid = blockIdx.x * blockDim.x + threadIdx.x;
    int f = tid & 31, node = tid >> 5;
    if (node >= NN) return;
    const float* a = A + (size_t)node * 256;
    float acc = 0.f;
#pragma unroll 8
    for (int k = 0; k < 256; k++) acc += a[k] * Bs[k * 32 + f];
    float elv = 0.f, erv = 0.f;
    if (f < 16) {
        C1[node * 16 + f] = acc;
        elv = acc * al2[f];
        erv = acc * ar2[f];
    } else {
        C2[node * 16 + f - 16] = acc;
    }
#pragma unroll
    for (int o = 8; o; o >>= 1) {
        elv += __shfl_xor_sync(0xffffffffu, elv, o, 16);
        erv += __shfl_xor_sync(0xffffffffu, erv, o, 16);
    }
    if (f == 0) { g_el[node] = elv; g_er[node] = erv; }
}

// ---------------- fused softmax-aggregate (no max pass) ----------------------
__device__ __forceinline__ float mishf(float x) {
    float sp = fmaxf(x, 0.f) + log1pf(__expf(-fabsf(x)));
    return x * tanhf(sp);
}

__device__ __forceinline__ float lrelu(float e) { return (e > 0.f) ? e : 0.2f * e; }

__global__ __launch_bounds__(256) void k_agg4(
    const __half* __restrict__ feath, const float* __restrict__ res,
    const float* __restrict__ bias, float* __restrict__ out) {
    int node = (blockIdx.x * blockDim.x + threadIdx.x) >> 5;
    int lane = threadIdx.x & 31;
    if (node >= NN) return;
    int start = g_rowptr[node], end = g_rowptr[node + 1];
    float4 er4 = *(const float4*)&g_er[node * 4];

    float2 a0 = {0.f, 0.f}, a1 = {0.f, 0.f}, a2 = {0.f, 0.f}, a3 = {0.f, 0.f};
    float ss0 = 0.f, ss1 = 0.f, ss2 = 0.f, ss3 = 0.f;
    for (int base = start; base < end; base += 32) {
        int i = base + lane;
        int s = 0;
        float w0 = 0.f, w1 = 0.f, w2 = 0.f, w3 = 0.f;
        if (i < end) {
            s = g_csr_src[i];
            float4 el4 = *(const float4*)&g_el[s * 4];
            w0 = __expf(lrelu(el4.x + er4.x));
            w1 = __expf(lrelu(el4.y + er4.y));
            w2 = __expf(lrelu(el4.z + er4.z));
            w3 = __expf(lrelu(el4.w + er4.w));
            ss0 += w0; ss1 += w1; ss2 += w2; ss3 += w3;
        }
        int cnt = min(32, end - base);
        int j = 0;
        for (; j + 1 < cnt; j += 2) {
            int   sjA = __shfl_sync(0xffffffffu, s, j);
            int   sjB = __shfl_sync(0xffffffffu, s, j + 1);
            float bA0 = __shfl_sync(0xffffffffu, w0, j);
            float bA1 = __shfl_sync(0xffffffffu, w1, j);
            float bA2 = __shfl_sync(0xffffffffu, w2, j);
            float bA3 = __shfl_sync(0xffffffffu, w3, j);
            float bB0 = __shfl_sync(0xffffffffu, w0, j + 1);
            float bB1 = __shfl_sync(0xffffffffu, w1, j + 1);
            float bB2 = __shfl_sync(0xffffffffu, w2, j + 1);
            float bB3 = __shfl_sync(0xffffffffu, w3, j + 1);
            const __half2* fpA = (const __half2*)(feath + (size_t)sjA * 256);
            const __half2* fpB = (const __half2*)(feath + (size_t)sjB * 256);
            __half2 hA0 = fpA[lane], hA1 = fpA[lane + 32],
                    hA2 = fpA[lane + 64], hA3 = fpA[lane + 96];
            __half2 hB0 = fpB[lane], hB1 = fpB[lane + 32],
                    hB2 = fpB[lane + 64], hB3 = fpB[lane + 96];
            float2 f0 = __half22float2(hA0), f1 = __half22float2(hA1);
            float2 f2 = __half22float2(hA2), f3 = __half22float2(hA3);
            a0.x += bA0 * f0.x; a0.y += bA0 * f0.y;
            a1.x += bA1 * f1.x; a1.y += bA1 * f1.y;
            a2.x += bA2 * f2.x; a2.y += bA2 * f2.y;
            a3.x += bA3 * f3.x; a3.y += bA3 * f3.y;
            f0 = __half22float2(hB0); f1 = __half22float2(hB1);
            f2 = __half22float2(hB2); f3 = __half22float2(hB3);
            a0.x += bB0 * f0.x; a0.y += bB0 * f0.y;
            a1.x += bB1 * f1.x; a1.y += bB1 * f1.y;
            a2.x += bB2 * f2.x; a2.y += bB2 * f2.y;
            a3.x += bB3 * f3.x; a3.y += bB3 * f3.y;
        }
        if (j < cnt) {
            int   sj = __shfl_sync(0xffffffffu, s, j);
            float b0 = __shfl_sync(0xffffffffu, w0, j);
            float b1 = __shfl_sync(0xffffffffu, w1, j);
            float b2 = __shfl_sync(0xffffffffu, w2, j);
            float b3 = __shfl_sync(0xffffffffu, w3, j);
            const __half2* fp = (const __half2*)(feath + (size_t)sj * 256);
            float2 f0 = __half22float2(fp[lane]);
            float2 f1 = __half22float2(fp[lane + 32]);
            float2 f2 = __half22float2(fp[lane + 64]);
            float2 f3 = __half22float2(fp[lane + 96]);
            a0.x += b0 * f0.x; a0.y += b0 * f0.y;
            a1.x += b1 * f1.x; a1.y += b1 * f1.y;
            a2.x += b2 * f2.x; a2.y += b2 * f2.y;
            a3.x += b3 * f3.x; a3.y += b3 * f3.y;
        }
    }
#pragma unroll
    for (int o = 16; o; o >>= 1) {
        ss0 += __shfl_xor_sync(0xffffffffu, ss0, o);
        ss1 += __shfl_xor_sync(0xffffffffu, ss1, o);
        ss2 += __shfl_xor_sync(0xffffffffu, ss2, o);
        ss3 += __shfl_xor_sync(0xffffffffu, ss3, o);
    }
    bool has = (end > start);
    float i0 = has ? 1.f / ss0 : 0.f;
    float i1 = has ? 1.f / ss1 : 0.f;
    float i2 = has ? 1.f / ss2 : 0.f;
    float i3 = has ? 1.f / ss3 : 0.f;

    size_t ob = (size_t)node * 256;
    int c = 2 * lane;
    float2 r0 = *(const float2*)&res[ob + c];
    float2 r1 = *(const float2*)&res[ob + 64 + c];
    float2 r2 = *(const float2*)&res[ob + 128 + c];
    float2 r3 = *(const float2*)&res[ob + 192 + c];
    float2 o0 = make_float2(mishf(a0.x * i0 + r0.x + bias[c]),
                            mishf(a0.y * i0 + r0.y + bias[c + 1]));
    float2 o1 = make_float2(mishf(a1.x * i1 + r1.x + bias[64 + c]),
                            mishf(a1.y * i1 + r1.y + bias[64 + c + 1]));
    float2 o2 = make_float2(mishf(a2.x * i2 + r2.x + bias[128 + c]),
                            mishf(a2.y * i2 + r2.y + bias[128 + c + 1]));
    float2 o3 = make_float2(mishf(a3.x * i3 + r3.x + bias[192 + c]),
                            mishf(a3.y * i3 + r3.y + bias[192 + c + 1]));
    *(float2*)&out[ob + c]       = o0;
    *(float2*)&out[ob + 64 + c]  = o1;
    *(float2*)&out[ob + 128 + c] = o2;
    *(float2*)&out[ob + 192 + c] = o3;
}

// ---------------- softmax-aggregate layer2, H=1 D=16 -------------------------
__global__ __launch_bounds__(256) void k_agg2(
    const float* __restrict__ feat, const float* __restrict__ res,
    const float* __restrict__ bias, float* __restrict__ out) {
    int node = (blockIdx.x * blockDim.x + threadIdx.x) >> 5;
    int lane = threadIdx.x & 31;
    if (node >= NN) return;
    int start = g_rowptr[node], end = g_rowptr[node + 1];
    float er_n = g_er[node];

    float acc = 0.f, ss = 0.f;
    for (int base = start; base < end; base += 32) {
        int i = base + lane;
        int s = 0;
        float w = 0.f;
        if (i < end) {
            s = g_csr_src[i];
            w = __expf(lrelu(g_el[s] + er_n));
            ss += w;
        }
        int cnt = min(32, end - base);
        for (int j = 0; j < cnt; j++) {
            int   sj = __shfl_sync(0xffffffffu, s, j);
            float bw = __shfl_sync(0xffffffffu, w, j);
            if (lane < 16) acc += bw * feat[(size_t)sj * 16 + lane];
        }
    }
#pragma unroll
    for (int o = 16; o; o >>= 1) ss += __shfl_xor_sync(0xffffffffu, ss, o);
    float inv = (end > start) ? 1.f / ss : 0.f;
    if (lane < 16)
        out[(size_t)node * 16 + lane] = acc * inv + res[(size_t)node * 16 + lane] + bias[lane];
}

// ---------------- launch -----------------------------------------------------
extern "C" void kernel_launch(void* const* d_in, const int* in_sizes, int n_in,
                              void* d_out, int out_size) {
    const float* x    = (const float*)d_in[0];
    const int*   src  = (const int*)d_in[1];
    const int*   dst  = (const int*)d_in[2];
    const float* W0   = (const float*)d_in[3];
    const float* al0  = (const float*)d_in[4];
    const float* ar0  = (const float*)d_in[5];
    const float* b0   = (const float*)d_in[6];
    const float* W1   = (const float*)d_in[7];
    const float* al1  = (const float*)d_in[8];
    const float* ar1  = (const float*)d_in[9];
    const float* b1   = (const float*)d_in[10];
    const float* W2   = (const float*)d_in[11];
    const float* al2  = (const float*)d_in[12];
    const float* ar2  = (const float*)d_in[13];
    const float* b2   = (const float*)d_in[14];
    const float* rW2  = (const float*)d_in[15];
    float* out = (float*)d_out;

    float *h1, *h2, *feat2, *res2;
    __half* feath;
    cudaGetSymbolAddress((void**)&feath, g_feat_h);
    cudaGetSymbolAddress((void**)&h1,    g_h1);
    cudaGetSymbolAddress((void**)&h2,    g_h2);
    cudaGetSymbolAddress((void**)&feat2, g_feat2);
    cudaGetSymbolAddress((void**)&res2,  g_res2);

    // ---- CSR by dst
    k_zero_deg<<<(NN + 255) / 256, 256>>>();
    k_hist<<<(NE + 255) / 256, 256>>>(dst);
    k_scan<<<1, 1024>>>();
    k_scatter<<<(NE + 255) / 256, 256>>>(src, dst);

    dim3 gtc(256 / 64, (NN + 127) / 128);
    int aggBlocks = (NN * 32 + 255) / 256;

    // ---- layer 0
    k_gemm_tc<<<gtc, 256>>>(x, W0, feath, al0, ar0, NN, 256, 256);
    k_agg4<<<aggBlocks, 256>>>(feath, x, b0, h1);

    // ---- layer 1
    k_gemm_tc<<<gtc, 256>>>(h1, W1, feath, al1, ar1, NN, 256, 256);
    k_agg4<<<aggBlocks, 256>>>(feath, h1, b1, h2);

    // ---- layer 2
    k_gemm16x2<<<(NN * 32 + 255) / 256, 256>>>(h2, W2, rW2, feat2, res2, al2, ar2);
    k_agg2<<<aggBlocks, 256>>>(feat2, res2, b2, out);
}

// round 7
// speedup vs baseline: 2.2378x; 1.1439x over previous
#include <cuda_runtime.h>
#include <cuda_fp16.h>
#include <math.h>
#include <stdint.h>

#define NN 50000
#define NE 800000

// ---------------- scratch ----------------------------------------------------
__device__ __align__(16) __half g_feat_h[NN * 256]; // GEMM output (fp16) for gathers
__device__ __align__(16) __half g_xh[NN * 256];     // presplit A hi (layer0)
__device__ __align__(16) __half g_xl[NN * 256];     // presplit A lo
__device__ __align__(16) __half g_h1h[NN * 256];    // layer0 out hi (= layer1 A hi)
__device__ __align__(16) __half g_h1l[NN * 256];    // layer0 out lo
__device__ __align__(16) float  g_h2[NN * 256];     // layer1 out (fp32)
__device__ __align__(16) float  g_feat2[NN * 16];
__device__ __align__(16) float  g_res2[NN * 16];
__device__ __align__(16) __half2 g_w0h[128 * 256];  // W packed k-pairs, hi/lo
__device__ __align__(16) __half2 g_w0l[128 * 256];
__device__ __align__(16) __half2 g_w1h[128 * 256];
__device__ __align__(16) __half2 g_w1l[128 * 256];
__device__ __align__(16) float g_el[NN * 4];
__device__ __align__(16) float g_er[NN * 4];
__device__ int g_deg[NN];
__device__ int g_rowptr[NN + 1];
__device__ int g_pos[NN];
__device__ int g_csr_src[NE];

// ---------------- CSR build --------------------------------------------------
__global__ void k_hist(const int* __restrict__ dst) {
    int e = blockIdx.x * blockDim.x + threadIdx.x;
    if (e < NE) atomicAdd(&g_deg[dst[e]], 1);
}

__global__ void k_scan() {
    __shared__ int warp_pref[32];
    const int T = 1024;
    int t = threadIdx.x;
    const int per = (NN + T - 1) / T;
    int begin = t * per;
    int end = min(begin + per, NN);
    if (begin > NN) begin = NN;
    if (end < begin) end = begin;

    int sum = 0;
    for (int i = begin; i < end; i++) sum += g_deg[i];

    int lane = t & 31, wid = t >> 5;
    int v = sum;
#pragma unroll
    for (int o = 1; o < 32; o <<= 1) {
        int u = __shfl_up_sync(0xffffffffu, v, o);
        if (lane >= o) v += u;
    }
    if (lane == 31) warp_pref[wid] = v;
    __syncthreads();
    if (wid == 0) {
        int w = warp_pref[lane];
#pragma unroll
        for (int o = 1; o < 32; o <<= 1) {
            int u = __shfl_up_sync(0xffffffffu, w, o);
            if (lane >= o) w += u;
        }
        warp_pref[lane] = w;
    }
    __syncthreads();
    int excl = v - sum + (wid ? warp_pref[wid - 1] : 0);

    int run = excl;
    for (int i = begin; i < end; i++) {
        g_rowptr[i] = run;
        g_pos[i] = run;
        run += g_deg[i];
    }
    if (t == T - 1) g_rowptr[NN] = run;
}

__global__ void k_scatter(const int* __restrict__ src, const int* __restrict__ dst) {
    int e = blockIdx.x * blockDim.x + threadIdx.x;
    if (e < NE) {
        int p = atomicAdd(&g_pos[dst[e]], 1);
        g_csr_src[p] = src[e];
    }
}

// ---------------- presplit helpers -------------------------------------------
__device__ __forceinline__ void split2(float x, float y, __half2& hi, __half2& lo) {
    __half hx = __float2half_rn(x), hy = __float2half_rn(y);
    hi = __halves2half2(hx, hy);
    lo = __floats2half2_rn(x - __half2float(hx), y - __half2float(hy));
}

__global__ void k_presplit(const float4* __restrict__ A, uint2* __restrict__ H,
                           uint2* __restrict__ L, int n4) {
    int i = blockIdx.x * blockDim.x + threadIdx.x;
    if (i >= n4) return;
    float4 v = A[i];
    __half2 h0, l0, h1, l1;
    split2(v.x, v.y, h0, l0);
    split2(v.z, v.w, h1, l1);
    H[i] = make_uint2(*(uint32_t*)&h0, *(uint32_t*)&h1);
    L[i] = make_uint2(*(uint32_t*)&l0, *(uint32_t*)&l1);
}

// W[256][256] -> packed k-pair form: P[kp][n] = half2(W[2kp][n], W[2kp+1][n])
__global__ void k_presplitW(const float* __restrict__ W, __half2* __restrict__ Ph,
                            __half2* __restrict__ Pl) {
    int idx = blockIdx.x * blockDim.x + threadIdx.x;
    if (idx >= 128 * 256) return;
    int kp = idx >> 8, n = idx & 255;
    float a = W[(2 * kp) * 256 + n];
    float b = W[(2 * kp + 1) * 256 + n];
    __half ha = __float2half_rn(a), hb = __float2half_rn(b);
    Ph[idx] = __halves2half2(ha, hb);
    Pl[idx] = __floats2half2_rn(a - __half2float(ha), b - __half2float(hb));
}

// ---------------- tensor-core GEMM (3-term fp16, presplit inputs) ------------
__device__ __forceinline__ void mma16(float* d, const uint32_t* a, const uint32_t* b) {
    asm volatile(
        "mma.sync.aligned.m16n8k16.row.col.f32.f16.f16.f32 "
        "{%0,%1,%2,%3}, {%4,%5,%6,%7}, {%8,%9}, {%0,%1,%2,%3};\n"
        : "+f"(d[0]), "+f"(d[1]), "+f"(d[2]), "+f"(d[3])
        : "r"(a[0]), "r"(a[1]), "r"(a[2]), "r"(a[3]), "r"(b[0]), "r"(b[1]));
}

#define ASTR 12   // half2 per A smem row (16B-aligned rows, conflict-free frags)
#define BSTR 72   // half2 per B smem k-pair row

__global__ __launch_bounds__(256, 2) void k_gemm_tc(
    const __half* __restrict__ Axh, const __half* __restrict__ Axl,
    const __half2* __restrict__ Wph, const __half2* __restrict__ Wpl,
    __half* __restrict__ Ch, const float* __restrict__ pal,
    const float* __restrict__ pare, int M) {
    const int K = 256, N = 256;
    __shared__ __half2 Ah[2][128][ASTR];
    __shared__ __half2 Al[2][128][ASTR];
    __shared__ __half2 Bh[2][8][BSTR];
    __shared__ __half2 Bl[2][8][BSTR];
    __shared__ float s_el[2][128];
    __shared__ float s_er[2][128];

    int tid = threadIdx.x;
    int lane = tid & 31;
    int wid = tid >> 5;
    int warp_n = wid & 1;
    int m_base = (wid >> 1) * 32;
    int n_base = warp_n * 32;
    int row0 = blockIdx.y * 128;
    int col0 = blockIdx.x * 64;
    int head = col0 >> 6;

    float acc[2][4][4];
#pragma unroll
    for (int mt = 0; mt < 2; mt++)
#pragma unroll
        for (int nt = 0; nt < 4; nt++)
#pragma unroll
            for (int i = 0; i < 4; i++) acc[mt][nt][i] = 0.f;

    // staging indices: A per thread = 8 halves hi + 8 lo from one row
    int ar = tid >> 1;            // 0..127
    int ac8 = (tid & 1) * 8;      // element offset 0 or 8
    int gr = row0 + ar;
    bool aval = gr < M;
    // B: first 128 threads copy hi, second 128 copy lo
    int t2 = tid & 127;
    int kp = t2 >> 4;             // 0..7
    int nq = (t2 & 15) * 4;       // half2 offset 0..60
    bool isHi = tid < 128;
    const uint4 z4 = make_uint4(0, 0, 0, 0);

    int jq = lane >> 2;
    int jc = lane & 3;

    // prologue
    {
        uint4 va = aval ? *(const uint4*)(Axh + (size_t)gr * K + ac8) : z4;
        uint4 vl = aval ? *(const uint4*)(Axl + (size_t)gr * K + ac8) : z4;
        *(uint4*)&Ah[0][ar][ac8 >> 1] = va;
        *(uint4*)&Al[0][ar][ac8 >> 1] = vl;
        const __half2* Wsrc = isHi ? Wph : Wpl;
        uint4 vb = *(const uint4*)(Wsrc + (size_t)kp * N + col0 + nq);
        if (isHi) *(uint4*)&Bh[0][kp][nq] = vb;
        else      *(uint4*)&Bl[0][kp][nq] = vb;
    }
    __syncthreads();

    const int NS = K / 16;
    for (int s = 0; s < NS; s++) {
        int cur = s & 1;
        uint4 va, vl, vb;
        bool more = (s + 1 < NS);
        if (more) {
            int k0 = (s + 1) * 16;
            va = aval ? *(const uint4*)(Axh + (size_t)gr * K + k0 + ac8) : z4;
            vl = aval ? *(const uint4*)(Axl + (size_t)gr * K + k0 + ac8) : z4;
            const __half2* Wsrc = isHi ? Wph : Wpl;
            vb = *(const uint4*)(Wsrc + ((size_t)(k0 >> 1) + kp) * N + col0 + nq);
        }

        uint32_t ah[2][4], al_[2][4];
#pragma unroll
        for (int mt = 0; mt < 2; mt++) {
            int r = m_base + mt * 16 + jq;
            ah[mt][0] = *(const uint32_t*)&Ah[cur][r][jc];
            ah[mt][1] = *(const uint32_t*)&Ah[cur][r + 8][jc];
            ah[mt][2] = *(const uint32_t*)&Ah[cur][r][jc + 4];
            ah[mt][3] = *(const uint32_t*)&Ah[cur][r + 8][jc + 4];
            al_[mt][0] = *(const uint32_t*)&Al[cur][r][jc];
            al_[mt][1] = *(const uint32_t*)&Al[cur][r + 8][jc];
            al_[mt][2] = *(const uint32_t*)&Al[cur][r][jc + 4];
            al_[mt][3] = *(const uint32_t*)&Al[cur][r + 8][jc + 4];
        }
        uint32_t bh[4][2], bl[4][2];
#pragma unroll
        for (int nt = 0; nt < 4; nt++) {
            int n = n_base + nt * 8 + jq;
            bh[nt][0] = *(const uint32_t*)&Bh[cur][jc][n];
            bh[nt][1] = *(const uint32_t*)&Bh[cur][jc + 4][n];
            bl[nt][0] = *(const uint32_t*)&Bl[cur][jc][n];
            bl[nt][1] = *(const uint32_t*)&Bl[cur][jc + 4][n];
        }
#pragma unroll
        for (int mt = 0; mt < 2; mt++)
#pragma unroll
            for (int nt = 0; nt < 4; nt++) {
                mma16(acc[mt][nt], ah[mt], bh[nt]);
                mma16(acc[mt][nt], al_[mt], bh[nt]);
                mma16(acc[mt][nt], ah[mt], bl[nt]);
            }

        if (more) {
            int nxt = cur ^ 1;
            *(uint4*)&Ah[nxt][ar][ac8 >> 1] = va;
            *(uint4*)&Al[nxt][ar][ac8 >> 1] = vl;
            if (isHi) *(uint4*)&Bh[nxt][kp][nq] = vb;
            else      *(uint4*)&Bl[nxt][kp][nq] = vb;
        }
        __syncthreads();
    }

    // ---- fp16 feature store + fused el/er ------------------------------------
    float elv[4] = {0.f, 0.f, 0.f, 0.f}, erv[4] = {0.f, 0.f, 0.f, 0.f};
#pragma unroll
    for (int mt = 0; mt < 2; mt++)
#pragma unroll
        for (int nt = 0; nt < 4; nt++) {
            int r = row0 + m_base + mt * 16 + jq;
            int cl = n_base + nt * 8 + 2 * jc;
            int c = col0 + cl;
            if (r < M)
                *(__half2*)&Ch[(size_t)r * N + c] =
                    __floats2half2_rn(acc[mt][nt][0], acc[mt][nt][1]);
            if (r + 8 < M)
                *(__half2*)&Ch[(size_t)(r + 8) * N + c] =
                    __floats2half2_rn(acc[mt][nt][2], acc[mt][nt][3]);
            float w0 = pal[c], w1 = pal[c + 1];
            float u0 = pare[c], u1 = pare[c + 1];
            elv[mt * 2]     += acc[mt][nt][0] * w0 + acc[mt][nt][1] * w1;
            elv[mt * 2 + 1] += acc[mt][nt][2] * w0 + acc[mt][nt][3] * w1;
            erv[mt * 2]     += acc[mt][nt][0] * u0 + acc[mt][nt][1] * u1;
            erv[mt * 2 + 1] += acc[mt][nt][2] * u0 + acc[mt][nt][3] * u1;
        }
#pragma unroll
    for (int o = 1; o <= 2; o <<= 1) {
#pragma unroll
        for (int i = 0; i < 4; i++) {
            elv[i] += __shfl_xor_sync(0xffffffffu, elv[i], o);
            erv[i] += __shfl_xor_sync(0xffffffffu, erv[i], o);
        }
    }
    if (jc == 0) {
#pragma unroll
        for (int i = 0; i < 4; i++) {
            int lr = m_base + (i >> 1) * 16 + (i & 1) * 8 + jq;
            s_el[warp_n][lr] = elv[i];
            s_er[warp_n][lr] = erv[i];
        }
    }
    __syncthreads();
    if (tid < 128) {
        int r = row0 + tid;
        if (r < M) {
            g_el[r * 4 + head] = s_el[0][tid] + s_el[1][tid];
            g_er[r * 4 + head] = s_er[0][tid] + s_er[1][tid];
        }
    }
}

// ---------------- fused dual small GEMM + layer2 el/er -----------------------
__global__ void k_gemm16x2(const float* __restrict__ A, const float* __restrict__ B1,
                           const float* __restrict__ B2, float* __restrict__ C1,
                           float* __restrict__ C2, const float* __restrict__ al2,
                           const float* __restrict__ ar2) {
    __shared__ float Bs[256 * 32];
    for (int i = threadIdx.x; i < 256 * 16; i += blockDim.x) {
        Bs[(i >> 4) * 32 + (i & 15)] = B1[i];
        Bs[(i >> 4) * 32 + 16 + (i & 15)] = B2[i];
    }
    __syncthreads();
    int tid = blockIdx.x * blockDim.x + threadIdx.x;
    int f = tid & 31, node = tid >> 5;
    if (node >= NN) return;
    const float* a = A + (size_t)node * 256;
    float acc = 0.f;
#pragma unroll 8
    for (int k = 0; k < 256; k++) acc += a[k] * Bs[k * 32 + f];
    float elv = 0.f, erv = 0.f;
    if (f < 16) {
        C1[node * 16 + f] = acc;
        elv = acc * al2[f];
        erv = acc * ar2[f];
    } else {
        C2[node * 16 + f - 16] = acc;
    }
#pragma unroll
    for (int o = 8; o; o >>= 1) {
        elv += __shfl_xor_sync(0xffffffffu, elv, o, 16);
        erv += __shfl_xor_sync(0xffffffffu, erv, o, 16);
    }
    if (f == 0) { g_el[node] = elv; g_er[node] = erv; }
}

// ---------------- fused softmax-aggregate ------------------------------------
__device__ __forceinline__ float mishf(float x) {
    float sp = fmaxf(x, 0.f) + log1pf(__expf(-fabsf(x)));
    return x * tanhf(sp);
}

__device__ __forceinline__ float lrelu(float e) { return (e > 0.f) ? e : 0.2f * e; }

// MODE 0: res from fp32 resf; output split (outh, outl)
// MODE 1: res from (resh + resl); output fp32 outf
template <int MODE>
__global__ __launch_bounds__(256) void k_agg4(
    const __half* __restrict__ feath, const float* __restrict__ resf,
    const __half* __restrict__ resh, const __half* __restrict__ resl,
    const float* __restrict__ bias, float* __restrict__ outf,
    __half* __restrict__ outh, __half* __restrict__ outl) {
    int node = (blockIdx.x * blockDim.x + threadIdx.x) >> 5;
    int lane = threadIdx.x & 31;
    if (node >= NN) return;
    int start = g_rowptr[node], end = g_rowptr[node + 1];
    float4 er4 = *(const float4*)&g_er[node * 4];

    float2 a0 = {0.f, 0.f}, a1 = {0.f, 0.f}, a2 = {0.f, 0.f}, a3 = {0.f, 0.f};
    float ss0 = 0.f, ss1 = 0.f, ss2 = 0.f, ss3 = 0.f;
    for (int base = start; base < end; base += 32) {
        int i = base + lane;
        int s = 0;
        float w0 = 0.f, w1 = 0.f, w2 = 0.f, w3 = 0.f;
        if (i < end) {
            s = g_csr_src[i];
            float4 el4 = *(const float4*)&g_el[s * 4];
            w0 = __expf(lrelu(el4.x + er4.x));
            w1 = __expf(lrelu(el4.y + er4.y));
            w2 = __expf(lrelu(el4.z + er4.z));
            w3 = __expf(lrelu(el4.w + er4.w));
            ss0 += w0; ss1 += w1; ss2 += w2; ss3 += w3;
        }
        int cnt = min(32, end - base);
        int j = 0;
        for (; j + 1 < cnt; j += 2) {
            int   sjA = __shfl_sync(0xffffffffu, s, j);
            int   sjB = __shfl_sync(0xffffffffu, s, j + 1);
            float bA0 = __shfl_sync(0xffffffffu, w0, j);
            float bA1 = __shfl_sync(0xffffffffu, w1, j);
            float bA2 = __shfl_sync(0xffffffffu, w2, j);
            float bA3 = __shfl_sync(0xffffffffu, w3, j);
            float bB0 = __shfl_sync(0xffffffffu, w0, j + 1);
            float bB1 = __shfl_sync(0xffffffffu, w1, j + 1);
            float bB2 = __shfl_sync(0xffffffffu, w2, j + 1);
            float bB3 = __shfl_sync(0xffffffffu, w3, j + 1);
            const __half2* fpA = (const __half2*)(feath + (size_t)sjA * 256);
            const __half2* fpB = (const __half2*)(feath + (size_t)sjB * 256);
            __half2 hA0 = fpA[lane], hA1 = fpA[lane + 32],
                    hA2 = fpA[lane + 64], hA3 = fpA[lane + 96];
            __half2 hB0 = fpB[lane], hB1 = fpB[lane + 32],
                    hB2 = fpB[lane + 64], hB3 = fpB[lane + 96];
            float2 f0 = __half22float2(hA0), f1 = __half22float2(hA1);
            float2 f2 = __half22float2(hA2), f3 = __half22float2(hA3);
            a0.x += bA0 * f0.x; a0.y += bA0 * f0.y;
            a1.x += bA1 * f1.x; a1.y += bA1 * f1.y;
            a2.x += bA2 * f2.x; a2.y += bA2 * f2.y;
            a3.x += bA3 * f3.x; a3.y += bA3 * f3.y;
            f0 = __half22float2(hB0); f1 = __half22float2(hB1);
            f2 = __half22float2(hB2); f3 = __half22float2(hB3);
            a0.x += bB0 * f0.x; a0.y += bB0 * f0.y;
            a1.x += bB1 * f1.x; a1.y += bB1 * f1.y;
            a2.x += bB2 * f2.x; a2.y += bB2 * f2.y;
            a3.x += bB3 * f3.x; a3.y += bB3 * f3.y;
        }
        if (j < cnt) {
            int   sj = __shfl_sync(0xffffffffu, s, j);
            float b0 = __shfl_sync(0xffffffffu, w0, j);
            float b1 = __shfl_sync(0xffffffffu, w1, j);
            float b2 = __shfl_sync(0xffffffffu, w2, j);
            float b3 = __shfl_sync(0xffffffffu, w3, j);
            const __half2* fp = (const __half2*)(feath + (size_t)sj * 256);
            float2 f0 = __half22float2(fp[lane]);
            float2 f1 = __half22float2(fp[lane + 32]);
            float2 f2 = __half22float2(fp[lane + 64]);
            float2 f3 = __half22float2(fp[lane + 96]);
            a0.x += b0 * f0.x; a0.y += b0 * f0.y;
            a1.x += b1 * f1.x; a1.y += b1 * f1.y;
            a2.x += b2 * f2.x; a2.y += b2 * f2.y;
            a3.x += b3 * f3.x; a3.y += b3 * f3.y;
        }
    }
#pragma unroll
    for (int o = 16; o; o >>= 1) {
        ss0 += __shfl_xor_sync(0xffffffffu, ss0, o);
        ss1 += __shfl_xor_sync(0xffffffffu, ss1, o);
        ss2 += __shfl_xor_sync(0xffffffffu, ss2, o);
        ss3 += __shfl_xor_sync(0xffffffffu, ss3, o);
    }
    bool has = (end > start);
    float i0 = has ? 1.f / ss0 : 0.f;
    float i1 = has ? 1.f / ss1 : 0.f;
    float i2 = has ? 1.f / ss2 : 0.f;
    float i3 = has ? 1.f / ss3 : 0.f;

    size_t ob = (size_t)node * 256;
    int c = 2 * lane;
    float av[4][2] = {{a0.x * i0, a0.y * i0}, {a1.x * i1, a1.y * i1},
                      {a2.x * i2, a2.y * i2}, {a3.x * i3, a3.y * i3}};
#pragma unroll
    for (int g = 0; g < 4; g++) {
        size_t off = ob + g * 64 + c;
        float rx, ry;
        if (MODE == 0) {
            float2 r = *(const float2*)&resf[off];
            rx = r.x; ry = r.y;
        } else {
            float2 rh = __half22float2(*(const __half2*)&resh[off]);
            float2 rl = __half22float2(*(const __half2*)&resl[off]);
            rx = rh.x + rl.x; ry = rh.y + rl.y;
        }
        float ox = mishf(av[g][0] + rx + bias[g * 64 + c]);
        float oy = mishf(av[g][1] + ry + bias[g * 64 + c + 1]);
        if (MODE == 0) {
            __half2 hi, lo;
            split2(ox, oy, hi, lo);
            *(__half2*)&outh[off] = hi;
            *(__half2*)&outl[off] = lo;
        } else {
            *(float2*)&outf[off] = make_float2(ox, oy);
        }
    }
}

// ---------------- softmax-aggregate layer2, H=1 D=16 -------------------------
__global__ __launch_bounds__(256) void k_agg2(
    const float* __restrict__ feat, const float* __restrict__ res,
    const float* __restrict__ bias, float* __restrict__ out) {
    int node = (blockIdx.x * blockDim.x + threadIdx.x) >> 5;
    int lane = threadIdx.x & 31;
    if (node >= NN) return;
    int start = g_rowptr[node], end = g_rowptr[node + 1];
    float er_n = g_er[node];

    float acc = 0.f, ss = 0.f;
    for (int base = start; base < end; base += 32) {
        int i = base + lane;
        int s = 0;
        float w = 0.f;
        if (i < end) {
            s = g_csr_src[i];
            w = __expf(lrelu(g_el[s] + er_n));
            ss += w;
        }
        int cnt = min(32, end - base);
        for (int j = 0; j < cnt; j++) {
            int   sj = __shfl_sync(0xffffffffu, s, j);
            float bw = __shfl_sync(0xffffffffu, w, j);
            if (lane < 16) acc += bw * feat[(size_t)sj * 16 + lane];
        }
    }
#pragma unroll
    for (int o = 16; o; o >>= 1) ss += __shfl_xor_sync(0xffffffffu, ss, o);
    float inv = (end > start) ? 1.f / ss : 0.f;
    if (lane < 16)
        out[(size_t)node * 16 + lane] = acc * inv + res[(size_t)node * 16 + lane] + bias[lane];
}

// ---------------- launch -----------------------------------------------------
extern "C" void kernel_launch(void* const* d_in, const int* in_sizes, int n_in,
                              void* d_out, int out_size) {
    const float* x    = (const float*)d_in[0];
    const int*   src  = (const int*)d_in[1];
    const int*   dst  = (const int*)d_in[2];
    const float* W0   = (const float*)d_in[3];
    const float* al0  = (const float*)d_in[4];
    const float* ar0  = (const float*)d_in[5];
    const float* b0   = (const float*)d_in[6];
    const float* W1   = (const float*)d_in[7];
    const float* al1  = (const float*)d_in[8];
    const float* ar1  = (const float*)d_in[9];
    const float* b1   = (const float*)d_in[10];
    const float* W2   = (const float*)d_in[11];
    const float* al2  = (const float*)d_in[12];
    const float* ar2  = (const float*)d_in[13];
    const float* b2   = (const float*)d_in[14];
    const float* rW2  = (const float*)d_in[15];
    float* out = (float*)d_out;

    __half *feath, *xh, *xl, *h1h, *h1l;
    float *h2, *feat2, *res2;
    __half2 *w0h, *w0l, *w1h, *w1l;
    void* degp;
    cudaGetSymbolAddress((void**)&feath, g_feat_h);
    cudaGetSymbolAddress((void**)&xh, g_xh);
    cudaGetSymbolAddress((void**)&xl, g_xl);
    cudaGetSymbolAddress((void**)&h1h, g_h1h);
    cudaGetSymbolAddress((void**)&h1l, g_h1l);
    cudaGetSymbolAddress((void**)&h2, g_h2);
    cudaGetSymbolAddress((void**)&feat2, g_feat2);
    cudaGetSymbolAddress((void**)&res2, g_res2);
    cudaGetSymbolAddress((void**)&w0h, g_w0h);
    cudaGetSymbolAddress((void**)&w0l, g_w0l);
    cudaGetSymbolAddress((void**)&w1h, g_w1h);
    cudaGetSymbolAddress((void**)&w1l, g_w1l);
    cudaGetSymbolAddress(&degp, g_deg);

    // fork a side stream for the CSR build (independent of GEMM path)
    cudaStream_t s2 = 0;
    cudaEvent_t evF = 0, evJ = 0;
    bool forked = (cudaStreamCreateWithFlags(&s2, cudaStreamNonBlocking) == cudaSuccess) &&
                  (cudaEventCreateWithFlags(&evF, cudaEventDisableTiming) == cudaSuccess) &&
                  (cudaEventCreateWithFlags(&evJ, cudaEventDisableTiming) == cudaSuccess);
    cudaStream_t sc = forked ? s2 : 0;

    if (forked) {
        cudaEventRecord(evF, 0);
        cudaStreamWaitEvent(s2, evF, 0);
    }
    cudaMemsetAsync(degp, 0, NN * sizeof(int), sc);
    k_hist<<<(NE + 255) / 256, 256, 0, sc>>>(dst);
    k_scan<<<1, 1024, 0, sc>>>();
    k_scatter<<<(NE + 255) / 256, 256, 0, sc>>>(src, dst);
    if (forked) cudaEventRecord(evJ, s2);

    // main stream: presplit + layer0 GEMM (independent of CSR)
    k_presplitW<<<(128 * 256 + 255) / 256, 256>>>(W0, w0h, w0l);
    k_presplitW<<<(128 * 256 + 255) / 256, 256>>>(W1, w1h, w1l);
    k_presplit<<<(NN * 64 + 255) / 256, 256>>>((const float4*)x, (uint2*)xh, (uint2*)xl, NN * 64);

    dim3 gtc(4, (NN + 127) / 128);
    int aggBlocks = (NN * 32 + 255) / 256;

    k_gemm_tc<<<gtc, 256>>>(xh, xl, w0h, w0l, feath, al0, ar0, NN);

    if (forked) cudaStreamWaitEvent(0, evJ, 0);

    // layer 0 aggregate: res = x (fp32), out = split h1
    k_agg4<0><<<aggBlocks, 256>>>(feath, x, nullptr, nullptr, b0, nullptr, h1h, h1l);

    // layer 1
    k_gemm_tc<<<gtc, 256>>>(h1h, h1l, w1h, w1l, feath, al1, ar1, NN);
    k_agg4<1><<<aggBlocks, 256>>>(feath, nullptr, h1h, h1l, b1, h2, nullptr, nullptr);

    // layer 2
    k_gemm16x2<<<(NN * 32 + 255) / 256, 256>>>(h2, W2, rW2, feat2, res2, al2, ar2);
    k_agg2<<<aggBlocks, 256>>>(feat2, res2, b2, out);
}

// round 8
// speedup vs baseline: 2.3003x; 1.0279x over previous
#include <cuda_runtime.h>
#include <cuda_fp16.h>
#include <math.h>
#include <stdint.h>

#define NN 50000
#define NE 800000

// ---------------- scratch ----------------------------------------------------
__device__ __align__(16) __half g_feat_h[NN * 256]; // GEMM output (fp16) for gathers
__device__ __align__(16) __half g_xh[NN * 256];     // presplit A hi (layer0)
__device__ __align__(16) __half g_xl[NN * 256];     // presplit A lo
__device__ __align__(16) __half g_h1h[NN * 256];    // layer0 out hi (= layer1 A hi)
__device__ __align__(16) __half g_h1l[NN * 256];    // layer0 out lo
__device__ __align__(16) float  g_h2[NN * 256];     // layer1 out (fp32)
__device__ __align__(16) float  g_feat2[NN * 16];
__device__ __align__(16) float  g_res2[NN * 16];
__device__ __align__(16) __half2 g_w0h[128 * 256];  // W packed k-pairs, hi/lo
__device__ __align__(16) __half2 g_w0l[128 * 256];
__device__ __align__(16) __half2 g_w1h[128 * 256];
__device__ __align__(16) __half2 g_w1l[128 * 256];
__device__ __align__(16) float g_el[NN * 4];
__device__ __align__(16) float g_er[NN * 4];
__device__ int g_deg[NN];
__device__ int g_rowptr[NN + 1];
__device__ int g_pos[NN];
__device__ int g_csr_src[NE];

// ---------------- CSR build --------------------------------------------------
__global__ void k_hist(const int* __restrict__ dst) {
    int e = blockIdx.x * blockDim.x + threadIdx.x;
    if (e < NE) atomicAdd(&g_deg[dst[e]], 1);
}

__global__ void k_scan() {
    __shared__ int warp_pref[32];
    const int T = 1024;
    int t = threadIdx.x;
    const int per = (NN + T - 1) / T;
    int begin = t * per;
    int end = min(begin + per, NN);
    if (begin > NN) begin = NN;
    if (end < begin) end = begin;

    int sum = 0;
    for (int i = begin; i < end; i++) sum += g_deg[i];

    int lane = t & 31, wid = t >> 5;
    int v = sum;
#pragma unroll
    for (int o = 1; o < 32; o <<= 1) {
        int u = __shfl_up_sync(0xffffffffu, v, o);
        if (lane >= o) v += u;
    }
    if (lane == 31) warp_pref[wid] = v;
    __syncthreads();
    if (wid == 0) {
        int w = warp_pref[lane];
#pragma unroll
        for (int o = 1; o < 32; o <<= 1) {
            int u = __shfl_up_sync(0xffffffffu, w, o);
            if (lane >= o) w += u;
        }
        warp_pref[lane] = w;
    }
    __syncthreads();
    int excl = v - sum + (wid ? warp_pref[wid - 1] : 0);

    int run = excl;
    for (int i = begin; i < end; i++) {
        g_rowptr[i] = run;
        g_pos[i] = run;
        run += g_deg[i];
    }
    if (t == T - 1) g_rowptr[NN] = run;
}

__global__ void k_scatter(const int* __restrict__ src, const int* __restrict__ dst) {
    int e = blockIdx.x * blockDim.x + threadIdx.x;
    if (e < NE) {
        int p = atomicAdd(&g_pos[dst[e]], 1);
        g_csr_src[p] = src[e];
    }
}

// ---------------- presplit helpers -------------------------------------------
__device__ __forceinline__ void split2(float x, float y, __half2& hi, __half2& lo) {
    __half hx = __float2half_rn(x), hy = __float2half_rn(y);
    hi = __halves2half2(hx, hy);
    lo = __floats2half2_rn(x - __half2float(hx), y - __half2float(hy));
}

__global__ void k_presplit(const float4* __restrict__ A, uint2* __restrict__ H,
                           uint2* __restrict__ L, int n4) {
    int i = blockIdx.x * blockDim.x + threadIdx.x;
    if (i >= n4) return;
    float4 v = A[i];
    __half2 h0, l0, h1, l1;
    split2(v.x, v.y, h0, l0);
    split2(v.z, v.w, h1, l1);
    H[i] = make_uint2(*(uint32_t*)&h0, *(uint32_t*)&h1);
    L[i] = make_uint2(*(uint32_t*)&l0, *(uint32_t*)&l1);
}

__global__ void k_presplitW(const float* __restrict__ W, __half2* __restrict__ Ph,
                            __half2* __restrict__ Pl) {
    int idx = blockIdx.x * blockDim.x + threadIdx.x;
    if (idx >= 128 * 256) return;
    int kp = idx >> 8, n = idx & 255;
    float a = W[(2 * kp) * 256 + n];
    float b = W[(2 * kp + 1) * 256 + n];
    __half ha = __float2half_rn(a), hb = __float2half_rn(b);
    Ph[idx] = __halves2half2(ha, hb);
    Pl[idx] = __floats2half2_rn(a - __half2float(ha), b - __half2float(hb));
}

// ---------------- tensor-core GEMM: cp.async staging + ldmatrix frags --------
__device__ __forceinline__ void mma16(float* d, const uint32_t* a, const uint32_t* b) {
    asm volatile(
        "mma.sync.aligned.m16n8k16.row.col.f32.f16.f16.f32 "
        "{%0,%1,%2,%3}, {%4,%5,%6,%7}, {%8,%9}, {%0,%1,%2,%3};\n"
        : "+f"(d[0]), "+f"(d[1]), "+f"(d[2]), "+f"(d[3])
        : "r"(a[0]), "r"(a[1]), "r"(a[2]), "r"(a[3]), "r"(b[0]), "r"(b[1]));
}

#define LDSM4(r0, r1, r2, r3, addr)                                           \
    asm volatile("ldmatrix.sync.aligned.m8n8.x4.shared.b16 {%0,%1,%2,%3}, [%4];" \
                 : "=r"(r0), "=r"(r1), "=r"(r2), "=r"(r3) : "r"(addr))

#define CP16(dst, src, n)                                                     \
    asm volatile("cp.async.cg.shared.global [%0], [%1], 16, %2;\n"            \
                 :: "r"(dst), "l"(src), "r"(n))
#define CPCOMMIT() asm volatile("cp.async.commit_group;\n" ::: "memory")
#define CPWAIT0()  asm volatile("cp.async.wait_group 0;\n" ::: "memory")

#define A_ROWB 48          // bytes per A smem row (12 half2)
#define A_STAGEB (128 * A_ROWB)
#define B_ROWB 288         // bytes per B smem k-pair row (72 half2)
#define B_STAGEB (8 * B_ROWB)

__global__ __launch_bounds__(256, 2) void k_gemm_tc(
    const __half* __restrict__ Axh, const __half* __restrict__ Axl,
    const __half2* __restrict__ Wph, const __half2* __restrict__ Wpl,
    __half* __restrict__ Ch, const float* __restrict__ pal,
    const float* __restrict__ pare, int M) {
    const int K = 256, N = 256;
    __shared__ __half2 Ah[2][128][12];
    __shared__ __half2 Al[2][128][12];
    __shared__ __half2 Bh[2][8][72];
    __shared__ __half2 Bl[2][8][72];
    __shared__ float s_el[2][128];
    __shared__ float s_er[2][128];

    int tid = threadIdx.x;
    int lane = tid & 31;
    int wid = tid >> 5;
    int warp_n = wid & 1;
    int m_base = (wid >> 1) * 32;
    int n_base = warp_n * 32;
    int row0 = blockIdx.y * 128;
    int col0 = blockIdx.x * 64;
    int head = col0 >> 6;

    float acc[2][4][4];
#pragma unroll
    for (int mt = 0; mt < 2; mt++)
#pragma unroll
        for (int nt = 0; nt < 4; nt++)
#pragma unroll
            for (int i = 0; i < 4; i++) acc[mt][nt][i] = 0.f;

    // staging indices (cp.async): A = 2x16B per thread, B = 1x16B
    int ar = tid >> 1;            // 0..127
    int acq = (tid & 1);          // 0/1 -> 16B chunk within 32B k-halfrow
    int gr = row0 + ar;
    int aok = (gr < M) ? 16 : 0;
    int grc = min(gr, M - 1);
    int t2 = tid & 127;
    int kp = t2 >> 4;             // 0..7
    int nq = (t2 & 15) * 4;       // half2 offset 0..60
    bool isHi = tid < 128;
    const __half2* Wsrc = isHi ? Wph : Wpl;

    uint32_t ah_b = (uint32_t)__cvta_generic_to_shared(&Ah[0][0][0]);
    uint32_t al_b = (uint32_t)__cvta_generic_to_shared(&Al[0][0][0]);
    uint32_t bh_b = (uint32_t)__cvta_generic_to_shared(&Bh[0][0][0]);
    uint32_t bl_b = (uint32_t)__cvta_generic_to_shared(&Bl[0][0][0]);
    uint32_t a_dst = ar * A_ROWB + acq * 16;
    uint32_t b_dst = (isHi ? bh_b : bl_b) + kp * B_ROWB + nq * 4;

    // ldmatrix per-lane source offsets (within one A stage)
    uint32_t lm_off = (uint32_t)(m_base + (lane & 7) + ((lane >> 3) & 1) * 8) * A_ROWB
                      + (lane >> 4) * 16;

    // fragment indices for B LDS + epilogue
    int jq = lane >> 2;
    int jc = lane & 3;

    // prologue: stage 0
    {
        const __half* sa = Axh + (size_t)grc * K + acq * 8;
        const __half* sl = Axl + (size_t)grc * K + acq * 8;
        CP16(ah_b + a_dst, sa, aok);
        CP16(al_b + a_dst, sl, aok);
        CP16(b_dst, Wsrc + (size_t)kp * N + col0 + nq, 16);
        CPCOMMIT();
    }

    const int NS = K / 16;
    for (int s = 0; s < NS; s++) {
        int cur = s & 1;
        CPWAIT0();
        __syncthreads();
        if (s + 1 < NS) {
            int k0 = (s + 1) * 16;
            uint32_t stoff = (cur ^ 1) ? A_STAGEB : 0;
            const __half* sa = Axh + (size_t)grc * K + k0 + acq * 8;
            const __half* sl = Axl + (size_t)grc * K + k0 + acq * 8;
            CP16(ah_b + stoff + a_dst, sa, aok);
            CP16(al_b + stoff + a_dst, sl, aok);
            uint32_t bst = (cur ^ 1) ? B_STAGEB : 0;
            CP16(b_dst + bst, Wsrc + ((size_t)(k0 >> 1) + kp) * N + col0 + nq, 16);
            CPCOMMIT();
        }

        uint32_t ah[2][4], al_[2][4];
        uint32_t a_st = cur ? A_STAGEB : 0;
#pragma unroll
        for (int mt = 0; mt < 2; mt++) {
            uint32_t off = a_st + lm_off + mt * (16 * A_ROWB);
            LDSM4(ah[mt][0], ah[mt][1], ah[mt][2], ah[mt][3], ah_b + off);
            LDSM4(al_[mt][0], al_[mt][1], al_[mt][2], al_[mt][3], al_b + off);
        }
        uint32_t bh[4][2], bl[4][2];
#pragma unroll
        for (int nt = 0; nt < 4; nt++) {
            int n = n_base + nt * 8 + jq;
            bh[nt][0] = *(const uint32_t*)&Bh[cur][jc][n];
            bh[nt][1] = *(const uint32_t*)&Bh[cur][jc + 4][n];
            bl[nt][0] = *(const uint32_t*)&Bl[cur][jc][n];
            bl[nt][1] = *(const uint32_t*)&Bl[cur][jc + 4][n];
        }
#pragma unroll
        for (int mt = 0; mt < 2; mt++)
#pragma unroll
            for (int nt = 0; nt < 4; nt++) {
                mma16(acc[mt][nt], ah[mt], bh[nt]);
                mma16(acc[mt][nt], al_[mt], bh[nt]);
                mma16(acc[mt][nt], ah[mt], bl[nt]);
            }
    }

    // ---- fp16 feature store + fused el/er ------------------------------------
    float elv[4] = {0.f, 0.f, 0.f, 0.f}, erv[4] = {0.f, 0.f, 0.f, 0.f};
#pragma unroll
    for (int mt = 0; mt < 2; mt++)
#pragma unroll
        for (int nt = 0; nt < 4; nt++) {
            int r = row0 + m_base + mt * 16 + jq;
            int cl = n_base + nt * 8 + 2 * jc;
            int c = col0 + cl;
            if (r < M)
                *(__half2*)&Ch[(size_t)r * N + c] =
                    __floats2half2_rn(acc[mt][nt][0], acc[mt][nt][1]);
            if (r + 8 < M)
                *(__half2*)&Ch[(size_t)(r + 8) * N + c] =
                    __floats2half2_rn(acc[mt][nt][2], acc[mt][nt][3]);
            float w0 = pal[c], w1 = pal[c + 1];
            float u0 = pare[c], u1 = pare[c + 1];
            elv[mt * 2]     += acc[mt][nt][0] * w0 + acc[mt][nt][1] * w1;
            elv[mt * 2 + 1] += acc[mt][nt][2] * w0 + acc[mt][nt][3] * w1;
            erv[mt * 2]     += acc[mt][nt][0] * u0 + acc[mt][nt][1] * u1;
            erv[mt * 2 + 1] += acc[mt][nt][2] * u0 + acc[mt][nt][3] * u1;
        }
#pragma unroll
    for (int o = 1; o <= 2; o <<= 1) {
#pragma unroll
        for (int i = 0; i < 4; i++) {
            elv[i] += __shfl_xor_sync(0xffffffffu, elv[i], o);
            erv[i] += __shfl_xor_sync(0xffffffffu, erv[i], o);
        }
    }
    if (jc == 0) {
#pragma unroll
        for (int i = 0; i < 4; i++) {
            int lr = m_base + (i >> 1) * 16 + (i & 1) * 8 + jq;
            s_el[warp_n][lr] = elv[i];
            s_er[warp_n][lr] = erv[i];
        }
    }
    __syncthreads();
    if (tid < 128) {
        int r = row0 + tid;
        if (r < M) {
            g_el[r * 4 + head] = s_el[0][tid] + s_el[1][tid];
            g_er[r * 4 + head] = s_er[0][tid] + s_er[1][tid];
        }
    }
}

// ---------------- fused dual small GEMM + layer2 el/er -----------------------
__global__ void k_gemm16x2(const float* __restrict__ A, const float* __restrict__ B1,
                           const float* __restrict__ B2, float* __restrict__ C1,
                           float* __restrict__ C2, const float* __restrict__ al2,
                           const float* __restrict__ ar2) {
    __shared__ float Bs[256 * 32];
    for (int i = threadIdx.x; i < 256 * 16; i += blockDim.x) {
        Bs[(i >> 4) * 32 + (i & 15)] = B1[i];
        Bs[(i >> 4) * 32 + 16 + (i & 15)] = B2[i];
    }
    __syncthreads();
    int tid = blockIdx.x * blockDim.x + threadIdx.x;
    int f = tid & 31, node = tid >> 5;
    if (node >= NN) return;
    const float* a = A + (size_t)node * 256;
    float acc = 0.f;
#pragma unroll 8
    for (int k = 0; k < 256; k++) acc += a[k] * Bs[k * 32 + f];
    float elv = 0.f, erv = 0.f;
    if (f < 16) {
        C1[node * 16 + f] = acc;
        elv = acc * al2[f];
        erv = acc * ar2[f];
    } else {
        C2[node * 16 + f - 16] = acc;
    }
#pragma unroll
    for (int o = 8; o; o >>= 1) {
        elv += __shfl_xor_sync(0xffffffffu, elv, o, 16);
        erv += __shfl_xor_sync(0xffffffffu, erv, o, 16);
    }
    if (f == 0) { g_el[node] = elv; g_er[node] = erv; }
}

// ---------------- fused softmax-aggregate ------------------------------------
__device__ __forceinline__ float mishf(float x) {
    float sp = fmaxf(x, 0.f) + log1pf(__expf(-fabsf(x)));
    return x * tanhf(sp);
}

__device__ __forceinline__ float lrelu(float e) { return (e > 0.f) ? e : 0.2f * e; }

// MODE 0: res fp32 -> out split; MODE 1: res split -> out fp32
template <int MODE>
__global__ __launch_bounds__(256) void k_agg4(
    const __half* __restrict__ feath, const float* __restrict__ resf,
    const __half* __restrict__ resh, const __half* __restrict__ resl,
    const float* __restrict__ bias, float* __restrict__ outf,
    __half* __restrict__ outh, __half* __restrict__ outl) {
    int node = (blockIdx.x * blockDim.x + threadIdx.x) >> 5;
    int lane = threadIdx.x & 31;
    if (node >= NN) return;
    int start = g_rowptr[node], end = g_rowptr[node + 1];
    float4 er4 = *(const float4*)&g_er[node * 4];

    float2 a0 = {0.f, 0.f}, a1 = {0.f, 0.f}, a2 = {0.f, 0.f}, a3 = {0.f, 0.f};
    float ss0 = 0.f, ss1 = 0.f, ss2 = 0.f, ss3 = 0.f;
    for (int base = start; base < end; base += 32) {
        int i = base + lane;
        int s = 0;
        float w0 = 0.f, w1 = 0.f, w2 = 0.f, w3 = 0.f;
        if (i < end) {
            s = g_csr_src[i];
            float4 el4 = *(const float4*)&g_el[s * 4];
            w0 = __expf(lrelu(el4.x + er4.x));
            w1 = __expf(lrelu(el4.y + er4.y));
            w2 = __expf(lrelu(el4.z + er4.z));
            w3 = __expf(lrelu(el4.w + er4.w));
            ss0 += w0; ss1 += w1; ss2 += w2; ss3 += w3;
        }
        int cnt = min(32, end - base);
        int j = 0;
        for (; j + 3 < cnt; j += 4) {
            int sj[4];
            float b0[4], b1[4], b2[4], b3[4];
            __half2 h0[4], h1[4], h2_[4], h3[4];
#pragma unroll
            for (int q = 0; q < 4; q++) {
                sj[q] = __shfl_sync(0xffffffffu, s, j + q);
                b0[q] = __shfl_sync(0xffffffffu, w0, j + q);
                b1[q] = __shfl_sync(0xffffffffu, w1, j + q);
                b2[q] = __shfl_sync(0xffffffffu, w2, j + q);
                b3[q] = __shfl_sync(0xffffffffu, w3, j + q);
            }
#pragma unroll
            for (int q = 0; q < 4; q++) {
                const __half2* fp = (const __half2*)(feath + (size_t)sj[q] * 256);
                h0[q] = fp[lane];
                h1[q] = fp[lane + 32];
                h2_[q] = fp[lane + 64];
                h3[q] = fp[lane + 96];
            }
#pragma unroll
            for (int q = 0; q < 4; q++) {
                float2 f0 = __half22float2(h0[q]);
                float2 f1 = __half22float2(h1[q]);
                float2 f2 = __half22float2(h2_[q]);
                float2 f3 = __half22float2(h3[q]);
                a0.x += b0[q] * f0.x; a0.y += b0[q] * f0.y;
                a1.x += b1[q] * f1.x; a1.y += b1[q] * f1.y;
                a2.x += b2[q] * f2.x; a2.y += b2[q] * f2.y;
                a3.x += b3[q] * f3.x; a3.y += b3[q] * f3.y;
            }
        }
        for (; j < cnt; j++) {
            int   sj = __shfl_sync(0xffffffffu, s, j);
            float c0 = __shfl_sync(0xffffffffu, w0, j);
            float c1 = __shfl_sync(0xffffffffu, w1, j);
            float c2 = __shfl_sync(0xffffffffu, w2, j);
            float c3 = __shfl_sync(0xffffffffu, w3, j);
            const __half2* fp = (const __half2*)(feath + (size_t)sj * 256);
            float2 f0 = __half22float2(fp[lane]);
            float2 f1 = __half22float2(fp[lane + 32]);
            float2 f2 = __half22float2(fp[lane + 64]);
            float2 f3 = __half22float2(fp[lane + 96]);
            a0.x += c0 * f0.x; a0.y += c0 * f0.y;
            a1.x += c1 * f1.x; a1.y += c1 * f1.y;
            a2.x += c2 * f2.x; a2.y += c2 * f2.y;
            a3.x += c3 * f3.x; a3.y += c3 * f3.y;
        }
    }
#pragma unroll
    for (int o = 16; o; o >>= 1) {
        ss0 += __shfl_xor_sync(0xffffffffu, ss0, o);
        ss1 += __shfl_xor_sync(0xffffffffu, ss1, o);
        ss2 += __shfl_xor_sync(0xffffffffu, ss2, o);
        ss3 += __shfl_xor_sync(0xffffffffu, ss3, o);
    }
    bool has = (end > start);
    float i0 = has ? 1.f / ss0 : 0.f;
    float i1 = has ? 1.f / ss1 : 0.f;
    float i2 = has ? 1.f / ss2 : 0.f;
    float i3 = has ? 1.f / ss3 : 0.f;

    size_t ob = (size_t)node * 256;
    int c = 2 * lane;
    float av[4][2] = {{a0.x * i0, a0.y * i0}, {a1.x * i1, a1.y * i1},
                      {a2.x * i2, a2.y * i2}, {a3.x * i3, a3.y * i3}};
#pragma unroll
    for (int g = 0; g < 4; g++) {
        size_t off = ob + g * 64 + c;
        float rx, ry;
        if (MODE == 0) {
            float2 r = *(const float2*)&resf[off];
            rx = r.x; ry = r.y;
        } else {
            float2 rh = __half22float2(*(const __half2*)&resh[off]);
            float2 rl = __half22float2(*(const __half2*)&resl[off]);
            rx = rh.x + rl.x; ry = rh.y + rl.y;
        }
        float ox = mishf(av[g][0] + rx + bias[g * 64 + c]);
        float oy = mishf(av[g][1] + ry + bias[g * 64 + c + 1]);
        if (MODE == 0) {
            __half2 hi, lo;
            split2(ox, oy, hi, lo);
            *(__half2*)&outh[off] = hi;
            *(__half2*)&outl[off] = lo;
        } else {
            *(float2*)&outf[off] = make_float2(ox, oy);
        }
    }
}

// ---------------- softmax-aggregate layer2, H=1 D=16 -------------------------
__global__ __launch_bounds__(256) void k_agg2(
    const float* __restrict__ feat, const float* __restrict__ res,
    const float* __restrict__ bias, float* __restrict__ out) {
    int node = (blockIdx.x * blockDim.x + threadIdx.x) >> 5;
    int lane = threadIdx.x & 31;
    if (node >= NN) return;
    int start = g_rowptr[node], end = g_rowptr[node + 1];
    float er_n = g_er[node];

    float acc = 0.f, ss = 0.f;
    for (int base = start; base < end; base += 32) {
        int i = base + lane;
        int s = 0;
        float w = 0.f;
        if (i < end) {
            s = g_csr_src[i];
            w = __expf(lrelu(g_el[s] + er_n));
            ss += w;
        }
        int cnt = min(32, end - base);
        for (int j = 0; j < cnt; j++) {
            int   sj = __shfl_sync(0xffffffffu, s, j);
            float bw = __shfl_sync(0xffffffffu, w, j);
            if (lane < 16) acc += bw * feat[(size_t)sj * 16 + lane];
        }
    }
#pragma unroll
    for (int o = 16; o; o >>= 1) ss += __shfl_xor_sync(0xffffffffu, ss, o);
    float inv = (end > start) ? 1.f / ss : 0.f;
    if (lane < 16)
        out[(size_t)node * 16 + lane] = acc * inv + res[(size_t)node * 16 + lane] + bias[lane];
}

// ---------------- launch -----------------------------------------------------
extern "C" void kernel_launch(void* const* d_in, const int* in_sizes, int n_in,
                              void* d_out, int out_size) {
    const float* x    = (const float*)d_in[0];
    const int*   src  = (const int*)d_in[1];
    const int*   dst  = (const int*)d_in[2];
    const float* W0   = (const float*)d_in[3];
    const float* al0  = (const float*)d_in[4];
    const float* ar0  = (const float*)d_in[5];
    const float* b0   = (const float*)d_in[6];
    const float* W1   = (const float*)d_in[7];
    const float* al1  = (const float*)d_in[8];
    const float* ar1  = (const float*)d_in[9];
    const float* b1   = (const float*)d_in[10];
    const float* W2   = (const float*)d_in[11];
    const float* al2  = (const float*)d_in[12];
    const float* ar2  = (const float*)d_in[13];
    const float* b2   = (const float*)d_in[14];
    const float* rW2  = (const float*)d_in[15];
    float* out = (float*)d_out;

    __half *feath, *xh, *xl, *h1h, *h1l;
    float *h2, *feat2, *res2;
    __half2 *w0h, *w0l, *w1h, *w1l;
    void* degp;
    cudaGetSymbolAddress((void**)&feath, g_feat_h);
    cudaGetSymbolAddress((void**)&xh, g_xh);
    cudaGetSymbolAddress((void**)&xl, g_xl);
    cudaGetSymbolAddress((void**)&h1h, g_h1h);
    cudaGetSymbolAddress((void**)&h1l, g_h1l);
    cudaGetSymbolAddress((void**)&h2, g_h2);
    cudaGetSymbolAddress((void**)&feat2, g_feat2);
    cudaGetSymbolAddress((void**)&res2, g_res2);
    cudaGetSymbolAddress((void**)&w0h, g_w0h);
    cudaGetSymbolAddress((void**)&w0l, g_w0l);
    cudaGetSymbolAddress((void**)&w1h, g_w1h);
    cudaGetSymbolAddress((void**)&w1l, g_w1l);
    cudaGetSymbolAddress(&degp, g_deg);

    // fork a side stream for the CSR build
    cudaStream_t s2 = 0;
    cudaEvent_t evF = 0, evJ = 0;
    bool forked = (cudaStreamCreateWithFlags(&s2, cudaStreamNonBlocking) == cudaSuccess) &&
                  (cudaEventCreateWithFlags(&evF, cudaEventDisableTiming) == cudaSuccess) &&
                  (cudaEventCreateWithFlags(&evJ, cudaEventDisableTiming) == cudaSuccess);
    cudaStream_t sc = forked ? s2 : 0;

    if (forked) {
        cudaEventRecord(evF, 0);
        cudaStreamWaitEvent(s2, evF, 0);
    }
    cudaMemsetAsync(degp, 0, NN * sizeof(int), sc);
    k_hist<<<(NE + 255) / 256, 256, 0, sc>>>(dst);
    k_scan<<<1, 1024, 0, sc>>>();
    k_scatter<<<(NE + 255) / 256, 256, 0, sc>>>(src, dst);
    if (forked) cudaEventRecord(evJ, s2);

    // main stream: presplit + layer0 GEMM
    k_presplitW<<<(128 * 256 + 255) / 256, 256>>>(W0, w0h, w0l);
    k_presplitW<<<(128 * 256 + 255) / 256, 256>>>(W1, w1h, w1l);
    k_presplit<<<(NN * 64 + 255) / 256, 256>>>((const float4*)x, (uint2*)xh, (uint2*)xl, NN * 64);

    dim3 gtc(4, (NN + 127) / 128);
    int aggBlocks = (NN * 32 + 255) / 256;

    k_gemm_tc<<<gtc, 256>>>(xh, xl, w0h, w0l, feath, al0, ar0, NN);

    if (forked) cudaStreamWaitEvent(0, evJ, 0);

    k_agg4<0><<<aggBlocks, 256>>>(feath, x, nullptr, nullptr, b0, nullptr, h1h, h1l);

    k_gemm_tc<<<gtc, 256>>>(h1h, h1l, w1h, w1l, feath, al1, ar1, NN);
    k_agg4<1><<<aggBlocks, 256>>>(feath, nullptr, h1h, h1l, b1, h2, nullptr, nullptr);

    k_gemm16x2<<<(NN * 32 + 255) / 256, 256>>>(h2, W2, rW2, feat2, res2, al2, ar2);
    k_agg2<<<aggBlocks, 256>>>(feat2, res2, b2, out);
}

// round 9
// speedup vs baseline: 2.4329x; 1.0576x over previous
#include <cuda_runtime.h>
#include <cuda_fp16.h>
#include <math.h>
#include <stdint.h>

#define NN 50000
#define NE 800000

// ---------------- scratch ----------------------------------------------------
__device__ __align__(16) __half g_feat_h[NN * 256]; // GEMM output (fp16) for gathers
__device__ __align__(16) __half g_xh[NN * 256];     // presplit A hi (layer0)
__device__ __align__(16) __half g_xl[NN * 256];     // presplit A lo
__device__ __align__(16) __half g_h1h[NN * 256];    // layer0 out hi (= layer1 A hi)
__device__ __align__(16) __half g_h1l[NN * 256];    // layer0 out lo
__device__ __align__(16) float  g_h2[NN * 256];     // layer1 out (fp32)
__device__ __align__(16) float  g_feat2[NN * 16];
__device__ __align__(16) float  g_res2[NN * 16];
__device__ __align__(16) __half2 g_w0h[128 * 256];  // W packed k-pairs, hi/lo
__device__ __align__(16) __half2 g_w0l[128 * 256];
__device__ __align__(16) __half2 g_w1h[128 * 256];
__device__ __align__(16) __half2 g_w1l[128 * 256];
__device__ __align__(16) float g_el[NN * 4];
__device__ __align__(16) float g_er[NN * 4];
__device__ int g_deg[NN];
__device__ int g_rowptr[NN + 1];
__device__ int g_pos[NN];
__device__ int g_csr_src[NE];

// ---------------- CSR build --------------------------------------------------
__global__ void k_hist(const int* __restrict__ dst) {
    int e = blockIdx.x * blockDim.x + threadIdx.x;
    if (e < NE) atomicAdd(&g_deg[dst[e]], 1);
}

__global__ void k_scan() {
    __shared__ int warp_pref[32];
    const int T = 1024;
    int t = threadIdx.x;
    const int per = (NN + T - 1) / T;
    int begin = t * per;
    int end = min(begin + per, NN);
    if (begin > NN) begin = NN;
    if (end < begin) end = begin;

    int sum = 0;
    for (int i = begin; i < end; i++) sum += g_deg[i];

    int lane = t & 31, wid = t >> 5;
    int v = sum;
#pragma unroll
    for (int o = 1; o < 32; o <<= 1) {
        int u = __shfl_up_sync(0xffffffffu, v, o);
        if (lane >= o) v += u;
    }
    if (lane == 31) warp_pref[wid] = v;
    __syncthreads();
    if (wid == 0) {
        int w = warp_pref[lane];
#pragma unroll
        for (int o = 1; o < 32; o <<= 1) {
            int u = __shfl_up_sync(0xffffffffu, w, o);
            if (lane >= o) w += u;
        }
        warp_pref[lane] = w;
    }
    __syncthreads();
    int excl = v - sum + (wid ? warp_pref[wid - 1] : 0);

    int run = excl;
    for (int i = begin; i < end; i++) {
        g_rowptr[i] = run;
        g_pos[i] = run;
        run += g_deg[i];
    }
    if (t == T - 1) g_rowptr[NN] = run;
}

__global__ void k_scatter(const int* __restrict__ src, const int* __restrict__ dst) {
    int e = blockIdx.x * blockDim.x + threadIdx.x;
    if (e < NE) {
        int p = atomicAdd(&g_pos[dst[e]], 1);
        g_csr_src[p] = src[e];
    }
}

// ---------------- presplit helpers -------------------------------------------
__device__ __forceinline__ void split2(float x, float y, __half2& hi, __half2& lo) {
    __half hx = __float2half_rn(x), hy = __float2half_rn(y);
    hi = __halves2half2(hx, hy);
    lo = __floats2half2_rn(x - __half2float(hx), y - __half2float(hy));
}

__global__ void k_presplit(const float4* __restrict__ A, uint2* __restrict__ H,
                           uint2* __restrict__ L, int n4) {
    int i = blockIdx.x * blockDim.x + threadIdx.x;
    if (i >= n4) return;
    float4 v = A[i];
    __half2 h0, l0, h1, l1;
    split2(v.x, v.y, h0, l0);
    split2(v.z, v.w, h1, l1);
    H[i] = make_uint2(*(uint32_t*)&h0, *(uint32_t*)&h1);
    L[i] = make_uint2(*(uint32_t*)&l0, *(uint32_t*)&l1);
}

__global__ void k_presplitW(const float* __restrict__ W, __half2* __restrict__ Ph,
                            __half2* __restrict__ Pl) {
    int idx = blockIdx.x * blockDim.x + threadIdx.x;
    if (idx >= 128 * 256) return;
    int kp = idx >> 8, n = idx & 255;
    float a = W[(2 * kp) * 256 + n];
    float b = W[(2 * kp + 1) * 256 + n];
    __half ha = __float2half_rn(a), hb = __float2half_rn(b);
    Ph[idx] = __halves2half2(ha, hb);
    Pl[idx] = __floats2half2_rn(a - __half2float(ha), b - __half2float(hb));
}

// ---------------- tensor-core GEMM: cp.async staging + ldmatrix frags --------
__device__ __forceinline__ void mma16(float* d, const uint32_t* a, const uint32_t* b) {
    asm volatile(
        "mma.sync.aligned.m16n8k16.row.col.f32.f16.f16.f32 "
        "{%0,%1,%2,%3}, {%4,%5,%6,%7}, {%8,%9}, {%0,%1,%2,%3};\n"
        : "+f"(d[0]), "+f"(d[1]), "+f"(d[2]), "+f"(d[3])
        : "r"(a[0]), "r"(a[1]), "r"(a[2]), "r"(a[3]), "r"(b[0]), "r"(b[1]));
}

#define LDSM4(r0, r1, r2, r3, addr)                                           \
    asm volatile("ldmatrix.sync.aligned.m8n8.x4.shared.b16 {%0,%1,%2,%3}, [%4];" \
                 : "=r"(r0), "=r"(r1), "=r"(r2), "=r"(r3) : "r"(addr))

#define CP16(dst, src, n)                                                     \
    asm volatile("cp.async.cg.shared.global [%0], [%1], 16, %2;\n"            \
                 :: "r"(dst), "l"(src), "r"(n))
#define CPCOMMIT() asm volatile("cp.async.commit_group;\n" ::: "memory")
#define CPWAIT0()  asm volatile("cp.async.wait_group 0;\n" ::: "memory")

#define A_ROWB 48          // bytes per A smem row (12 half2)
#define A_STAGEB (128 * A_ROWB)
#define B_ROWB 288         // bytes per B smem k-pair row (72 half2)
#define B_STAGEB (8 * B_ROWB)

__global__ __launch_bounds__(256, 2) void k_gemm_tc(
    const __half* __restrict__ Axh, const __half* __restrict__ Axl,
    const __half2* __restrict__ Wph, const __half2* __restrict__ Wpl,
    __half* __restrict__ Ch, const float* __restrict__ pal,
    const float* __restrict__ pare, int M) {
    const int K = 256, N = 256;
    __shared__ __half2 Ah[2][128][12];
    __shared__ __half2 Al[2][128][12];
    __shared__ __half2 Bh[2][8][72];
    __shared__ __half2 Bl[2][8][72];
    __shared__ float s_el[2][128];
    __shared__ float s_er[2][128];

    int tid = threadIdx.x;
    int lane = tid & 31;
    int wid = tid >> 5;
    int warp_n = wid & 1;
    int m_base = (wid >> 1) * 32;
    int n_base = warp_n * 32;
    int row0 = blockIdx.y * 128;
    int col0 = blockIdx.x * 64;
    int head = col0 >> 6;

    float acc[2][4][4];
#pragma unroll
    for (int mt = 0; mt < 2; mt++)
#pragma unroll
        for (int nt = 0; nt < 4; nt++)
#pragma unroll
            for (int i = 0; i < 4; i++) acc[mt][nt][i] = 0.f;

    int ar = tid >> 1;
    int acq = (tid & 1);
    int gr = row0 + ar;
    int aok = (gr < M) ? 16 : 0;
    int grc = min(gr, M - 1);
    int t2 = tid & 127;
    int kp = t2 >> 4;
    int nq = (t2 & 15) * 4;
    bool isHi = tid < 128;
    const __half2* Wsrc = isHi ? Wph : Wpl;

    uint32_t ah_b = (uint32_t)__cvta_generic_to_shared(&Ah[0][0][0]);
    uint32_t al_b = (uint32_t)__cvta_generic_to_shared(&Al[0][0][0]);
    uint32_t bh_b = (uint32_t)__cvta_generic_to_shared(&Bh[0][0][0]);
    uint32_t bl_b = (uint32_t)__cvta_generic_to_shared(&Bl[0][0][0]);
    uint32_t a_dst = ar * A_ROWB + acq * 16;
    uint32_t b_dst = (isHi ? bh_b : bl_b) + kp * B_ROWB + nq * 4;

    uint32_t lm_off = (uint32_t)(m_base + (lane & 7) + ((lane >> 3) & 1) * 8) * A_ROWB
                      + (lane >> 4) * 16;

    int jq = lane >> 2;
    int jc = lane & 3;

    {
        const __half* sa = Axh + (size_t)grc * K + acq * 8;
        const __half* sl = Axl + (size_t)grc * K + acq * 8;
        CP16(ah_b + a_dst, sa, aok);
        CP16(al_b + a_dst, sl, aok);
        CP16(b_dst, Wsrc + (size_t)kp * N + col0 + nq, 16);
        CPCOMMIT();
    }

    const int NS = K / 16;
    for (int s = 0; s < NS; s++) {
        int cur = s & 1;
        CPWAIT0();
        __syncthreads();
        if (s + 1 < NS) {
            int k0 = (s + 1) * 16;
            uint32_t stoff = (cur ^ 1) ? A_STAGEB : 0;
            const __half* sa = Axh + (size_t)grc * K + k0 + acq * 8;
            const __half* sl = Axl + (size_t)grc * K + k0 + acq * 8;
            CP16(ah_b + stoff + a_dst, sa, aok);
            CP16(al_b + stoff + a_dst, sl, aok);
            uint32_t bst = (cur ^ 1) ? B_STAGEB : 0;
            CP16(b_dst + bst, Wsrc + ((size_t)(k0 >> 1) + kp) * N + col0 + nq, 16);
            CPCOMMIT();
        }

        uint32_t ah[2][4], al_[2][4];
        uint32_t a_st = cur ? A_STAGEB : 0;
#pragma unroll
        for (int mt = 0; mt < 2; mt++) {
            uint32_t off = a_st + lm_off + mt * (16 * A_ROWB);
            LDSM4(ah[mt][0], ah[mt][1], ah[mt][2], ah[mt][3], ah_b + off);
            LDSM4(al_[mt][0], al_[mt][1], al_[mt][2], al_[mt][3], al_b + off);
        }
        uint32_t bh[4][2], bl[4][2];
#pragma unroll
        for (int nt = 0; nt < 4; nt++) {
            int n = n_base + nt * 8 + jq;
            bh[nt][0] = *(const uint32_t*)&Bh[cur][jc][n];
            bh[nt][1] = *(const uint32_t*)&Bh[cur][jc + 4][n];
            bl[nt][0] = *(const uint32_t*)&Bl[cur][jc][n];
            bl[nt][1] = *(const uint32_t*)&Bl[cur][jc + 4][n];
        }
#pragma unroll
        for (int mt = 0; mt < 2; mt++)
#pragma unroll
            for (int nt = 0; nt < 4; nt++) {
                mma16(acc[mt][nt], ah[mt], bh[nt]);
                mma16(acc[mt][nt], al_[mt], bh[nt]);
                mma16(acc[mt][nt], ah[mt], bl[nt]);
            }
    }

    // ---- fp16 feature store + fused el/er ------------------------------------
    float elv[4] = {0.f, 0.f, 0.f, 0.f}, erv[4] = {0.f, 0.f, 0.f, 0.f};
#pragma unroll
    for (int mt = 0; mt < 2; mt++)
#pragma unroll
        for (int nt = 0; nt < 4; nt++) {
            int r = row0 + m_base + mt * 16 + jq;
            int cl = n_base + nt * 8 + 2 * jc;
            int c = col0 + cl;
            if (r < M)
                *(__half2*)&Ch[(size_t)r * N + c] =
                    __floats2half2_rn(acc[mt][nt][0], acc[mt][nt][1]);
            if (r + 8 < M)
                *(__half2*)&Ch[(size_t)(r + 8) * N + c] =
                    __floats2half2_rn(acc[mt][nt][2], acc[mt][nt][3]);
            float w0 = pal[c], w1 = pal[c + 1];
            float u0 = pare[c], u1 = pare[c + 1];
            elv[mt * 2]     += acc[mt][nt][0] * w0 + acc[mt][nt][1] * w1;
            elv[mt * 2 + 1] += acc[mt][nt][2] * w0 + acc[mt][nt][3] * w1;
            erv[mt * 2]     += acc[mt][nt][0] * u0 + acc[mt][nt][1] * u1;
            erv[mt * 2 + 1] += acc[mt][nt][2] * u0 + acc[mt][nt][3] * u1;
        }
#pragma unroll
    for (int o = 1; o <= 2; o <<= 1) {
#pragma unroll
        for (int i = 0; i < 4; i++) {
            elv[i] += __shfl_xor_sync(0xffffffffu, elv[i], o);
            erv[i] += __shfl_xor_sync(0xffffffffu, erv[i], o);
        }
    }
    if (jc == 0) {
#pragma unroll
        for (int i = 0; i < 4; i++) {
            int lr = m_base + (i >> 1) * 16 + (i & 1) * 8 + jq;
            s_el[warp_n][lr] = elv[i];
            s_er[warp_n][lr] = erv[i];
        }
    }
    __syncthreads();
    if (tid < 128) {
        int r = row0 + tid;
        if (r < M) {
            g_el[r * 4 + head] = s_el[0][tid] + s_el[1][tid];
            g_er[r * 4 + head] = s_er[0][tid] + s_er[1][tid];
        }
    }
}

// ---------------- fused dual small GEMM + layer2 el/er -----------------------
__global__ void k_gemm16x2(const float* __restrict__ A, const float* __restrict__ B1,
                           const float* __restrict__ B2, float* __restrict__ C1,
                           float* __restrict__ C2, const float* __restrict__ al2,
                           const float* __restrict__ ar2) {
    __shared__ float Bs[256 * 32];
    for (int i = threadIdx.x; i < 256 * 16; i += blockDim.x) {
        Bs[(i >> 4) * 32 + (i & 15)] = B1[i];
        Bs[(i >> 4) * 32 + 16 + (i & 15)] = B2[i];
    }
    __syncthreads();
    int tid = blockIdx.x * blockDim.x + threadIdx.x;
    int f = tid & 31, node = tid >> 5;
    if (node >= NN) return;
    const float* a = A + (size_t)node * 256;
    float acc = 0.f;
#pragma unroll 8
    for (int k = 0; k < 256; k++) acc += a[k] * Bs[k * 32 + f];
    float elv = 0.f, erv = 0.f;
    if (f < 16) {
        C1[node * 16 + f] = acc;
        elv = acc * al2[f];
        erv = acc * ar2[f];
    } else {
        C2[node * 16 + f - 16] = acc;
    }
#pragma unroll
    for (int o = 8; o; o >>= 1) {
        elv += __shfl_xor_sync(0xffffffffu, elv, o, 16);
        erv += __shfl_xor_sync(0xffffffffu, erv, o, 16);
    }
    if (f == 0) { g_el[node] = elv; g_er[node] = erv; }
}

// ---------------- fused softmax-aggregate ------------------------------------
__device__ __forceinline__ float mishf(float x) {
    float sp = fmaxf(x, 0.f) + log1pf(__expf(-fabsf(x)));
    return x * tanhf(sp);
}

__device__ __forceinline__ float lrelu(float e) { return (e > 0.f) ? e : 0.2f * e; }

// lane l owns output columns [8l, 8l+8). One LDG.128 per edge per warp.
// MODE 0: res fp32 -> out split; MODE 1: res split -> out fp32
template <int MODE>
__global__ __launch_bounds__(256) void k_agg4(
    const __half* __restrict__ feath, const float* __restrict__ resf,
    const __half* __restrict__ resh, const __half* __restrict__ resl,
    const float* __restrict__ bias, float* __restrict__ outf,
    __half* __restrict__ outh, __half* __restrict__ outl) {
    __shared__ float4 sw[8][32];   // per-warp per-edge weights (4 heads)
    int node = (blockIdx.x * blockDim.x + threadIdx.x) >> 5;
    int lane = threadIdx.x & 31;
    int warp = (threadIdx.x >> 5);
    if (node >= NN) return;
    int start = g_rowptr[node], end = g_rowptr[node + 1];
    float4 er4 = *(const float4*)&g_er[node * 4];
    int h = lane >> 3;             // my head
    float acc[8] = {0.f, 0.f, 0.f, 0.f, 0.f, 0.f, 0.f, 0.f};
    float ss0 = 0.f, ss1 = 0.f, ss2 = 0.f, ss3 = 0.f;

    for (int base = start; base < end; base += 32) {
        int i = base + lane;
        int s = 0;
        float w0 = 0.f, w1 = 0.f, w2 = 0.f, w3 = 0.f;
        if (i < end) {
            s = g_csr_src[i];
            float4 el4 = *(const float4*)&g_el[s * 4];
            w0 = __expf(lrelu(el4.x + er4.x));
            w1 = __expf(lrelu(el4.y + er4.y));
            w2 = __expf(lrelu(el4.z + er4.z));
            w3 = __expf(lrelu(el4.w + er4.w));
            ss0 += w0; ss1 += w1; ss2 += w2; ss3 += w3;
        }
        __syncwarp();
        sw[warp][lane] = make_float4(w0, w1, w2, w3);
        __syncwarp();
        int cnt = min(32, end - base);
        const float* swp = (const float*)&sw[warp][0];
        int j = 0;
        for (; j + 1 < cnt; j += 2) {
            int sjA = __shfl_sync(0xffffffffu, s, j);
            int sjB = __shfl_sync(0xffffffffu, s, j + 1);
            uint4 vA = *(const uint4*)(feath + (size_t)sjA * 256 + lane * 8);
            uint4 vB = *(const uint4*)(feath + (size_t)sjB * 256 + lane * 8);
            float wA = swp[j * 4 + h];
            float wB = swp[(j + 1) * 4 + h];
            float2 f0 = __half22float2(*(__half2*)&vA.x);
            float2 f1 = __half22float2(*(__half2*)&vA.y);
            float2 f2 = __half22float2(*(__half2*)&vA.z);
            float2 f3 = __half22float2(*(__half2*)&vA.w);
            acc[0] += wA * f0.x; acc[1] += wA * f0.y;
            acc[2] += wA * f1.x; acc[3] += wA * f1.y;
            acc[4] += wA * f2.x; acc[5] += wA * f2.y;
            acc[6] += wA * f3.x; acc[7] += wA * f3.y;
            f0 = __half22float2(*(__half2*)&vB.x);
            f1 = __half22float2(*(__half2*)&vB.y);
            f2 = __half22float2(*(__half2*)&vB.z);
            f3 = __half22float2(*(__half2*)&vB.w);
            acc[0] += wB * f0.x; acc[1] += wB * f0.y;
            acc[2] += wB * f1.x; acc[3] += wB * f1.y;
            acc[4] += wB * f2.x; acc[5] += wB * f2.y;
            acc[6] += wB * f3.x; acc[7] += wB * f3.y;
        }
        if (j < cnt) {
            int sj = __shfl_sync(0xffffffffu, s, j);
            uint4 v = *(const uint4*)(feath + (size_t)sj * 256 + lane * 8);
            float w = swp[j * 4 + h];
            float2 f0 = __half22float2(*(__half2*)&v.x);
            float2 f1 = __half22float2(*(__half2*)&v.y);
            float2 f2 = __half22float2(*(__half2*)&v.z);
            float2 f3 = __half22float2(*(__half2*)&v.w);
            acc[0] += w * f0.x; acc[1] += w * f0.y;
            acc[2] += w * f1.x; acc[3] += w * f1.y;
            acc[4] += w * f2.x; acc[5] += w * f2.y;
            acc[6] += w * f3.x; acc[7] += w * f3.y;
        }
    }
#pragma unroll
    for (int o = 16; o; o >>= 1) {
        ss0 += __shfl_xor_sync(0xffffffffu, ss0, o);
        ss1 += __shfl_xor_sync(0xffffffffu, ss1, o);
        ss2 += __shfl_xor_sync(0xffffffffu, ss2, o);
        ss3 += __shfl_xor_sync(0xffffffffu, ss3, o);
    }
    bool has = (end > start);
    float inv;
    {
        float sssel = (h == 0) ? ss0 : (h == 1) ? ss1 : (h == 2) ? ss2 : ss3;
        inv = has ? 1.f / sssel : 0.f;
    }

    size_t off = (size_t)node * 256 + lane * 8;
    int bc = lane * 8;
    float o[8];
    if (MODE == 0) {
        float4 r0 = *(const float4*)&resf[off];
        float4 r1 = *(const float4*)&resf[off + 4];
        o[0] = mishf(acc[0] * inv + r0.x + bias[bc]);
        o[1] = mishf(acc[1] * inv + r0.y + bias[bc + 1]);
        o[2] = mishf(acc[2] * inv + r0.z + bias[bc + 2]);
        o[3] = mishf(acc[3] * inv + r0.w + bias[bc + 3]);
        o[4] = mishf(acc[4] * inv + r1.x + bias[bc + 4]);
        o[5] = mishf(acc[5] * inv + r1.y + bias[bc + 5]);
        o[6] = mishf(acc[6] * inv + r1.z + bias[bc + 6]);
        o[7] = mishf(acc[7] * inv + r1.w + bias[bc + 7]);
        uint4 vh, vl;
        __half2 hh, ll;
        split2(o[0], o[1], hh, ll); vh.x = *(uint32_t*)&hh; vl.x = *(uint32_t*)&ll;
        split2(o[2], o[3], hh, ll); vh.y = *(uint32_t*)&hh; vl.y = *(uint32_t*)&ll;
        split2(o[4], o[5], hh, ll); vh.z = *(uint32_t*)&hh; vl.z = *(uint32_t*)&ll;
        split2(o[6], o[7], hh, ll); vh.w = *(uint32_t*)&hh; vl.w = *(uint32_t*)&ll;
        *(uint4*)(outh + off) = vh;
        *(uint4*)(outl + off) = vl;
    } else {
        uint4 vh = *(const uint4*)(resh + off);
        uint4 vl = *(const uint4*)(resl + off);
        float2 rh[4], rl[4];
        rh[0] = __half22float2(*(__half2*)&vh.x); rl[0] = __half22float2(*(__half2*)&vl.x);
        rh[1] = __half22float2(*(__half2*)&vh.y); rl[1] = __half22float2(*(__half2*)&vl.y);
        rh[2] = __half22float2(*(__half2*)&vh.z); rl[2] = __half22float2(*(__half2*)&vl.z);
        rh[3] = __half22float2(*(__half2*)&vh.w); rl[3] = __half22float2(*(__half2*)&vl.w);
#pragma unroll
        for (int q = 0; q < 4; q++) {
            o[2 * q]     = mishf(acc[2 * q] * inv + rh[q].x + rl[q].x + bias[bc + 2 * q]);
            o[2 * q + 1] = mishf(acc[2 * q + 1] * inv + rh[q].y + rl[q].y + bias[bc + 2 * q + 1]);
        }
        *(float4*)&outf[off] = make_float4(o[0], o[1], o[2], o[3]);
        *(float4*)&outf[off + 4] = make_float4(o[4], o[5], o[6], o[7]);
    }
}

// ---------------- softmax-aggregate layer2, H=1 D=16 -------------------------
__global__ __launch_bounds__(256) void k_agg2(
    const float* __restrict__ feat, const float* __restrict__ res,
    const float* __restrict__ bias, float* __restrict__ out) {
    int node = (blockIdx.x * blockDim.x + threadIdx.x) >> 5;
    int lane = threadIdx.x & 31;
    if (node >= NN) return;
    int start = g_rowptr[node], end = g_rowptr[node + 1];
    float er_n = g_er[node];

    float acc = 0.f, ss = 0.f;
    for (int base = start; base < end; base += 32) {
        int i = base + lane;
        int s = 0;
        float w = 0.f;
        if (i < end) {
            s = g_csr_src[i];
            w = __expf(lrelu(g_el[s] + er_n));
            ss += w;
        }
        int cnt = min(32, end - base);
        for (int j = 0; j < cnt; j++) {
            int   sj = __shfl_sync(0xffffffffu, s, j);
            float bw = __shfl_sync(0xffffffffu, w, j);
            if (lane < 16) acc += bw * feat[(size_t)sj * 16 + lane];
        }
    }
#pragma unroll
    for (int o = 16; o; o >>= 1) ss += __shfl_xor_sync(0xffffffffu, ss, o);
    float inv = (end > start) ? 1.f / ss : 0.f;
    if (lane < 16)
        out[(size_t)node * 16 + lane] = acc * inv + res[(size_t)node * 16 + lane] + bias[lane];
}

// ---------------- launch -----------------------------------------------------
extern "C" void kernel_launch(void* const* d_in, const int* in_sizes, int n_in,
                              void* d_out, int out_size) {
    const float* x    = (const float*)d_in[0];
    const int*   src  = (const int*)d_in[1];
    const int*   dst  = (const int*)d_in[2];
    const float* W0   = (const float*)d_in[3];
    const float* al0  = (const float*)d_in[4];
    const float* ar0  = (const float*)d_in[5];
    const float* b0   = (const float*)d_in[6];
    const float* W1   = (const float*)d_in[7];
    const float* al1  = (const float*)d_in[8];
    const float* ar1  = (const float*)d_in[9];
    const float* b1   = (const float*)d_in[10];
    const float* W2   = (const float*)d_in[11];
    const float* al2  = (const float*)d_in[12];
    const float* ar2  = (const float*)d_in[13];
    const float* b2   = (const float*)d_in[14];
    const float* rW2  = (const float*)d_in[15];
    float* out = (float*)d_out;

    __half *feath, *xh, *xl, *h1h, *h1l;
    float *h2, *feat2, *res2;
    __half2 *w0h, *w0l, *w1h, *w1l;
    void* degp;
    cudaGetSymbolAddress((void**)&feath, g_feat_h);
    cudaGetSymbolAddress((void**)&xh, g_xh);
    cudaGetSymbolAddress((void**)&xl, g_xl);
    cudaGetSymbolAddress((void**)&h1h, g_h1h);
    cudaGetSymbolAddress((void**)&h1l, g_h1l);
    cudaGetSymbolAddress((void**)&h2, g_h2);
    cudaGetSymbolAddress((void**)&feat2, g_feat2);
    cudaGetSymbolAddress((void**)&res2, g_res2);
    cudaGetSymbolAddress((void**)&w0h, g_w0h);
    cudaGetSymbolAddress((void**)&w0l, g_w0l);
    cudaGetSymbolAddress((void**)&w1h, g_w1h);
    cudaGetSymbolAddress((void**)&w1l, g_w1l);
    cudaGetSymbolAddress(&degp, g_deg);

    // fork a side stream for the CSR build
    cudaStream_t s2 = 0;
    cudaEvent_t evF = 0, evJ = 0;
    bool forked = (cudaStreamCreateWithFlags(&s2, cudaStreamNonBlocking) == cudaSuccess) &&
                  (cudaEventCreateWithFlags(&evF, cudaEventDisableTiming) == cudaSuccess) &&
                  (cudaEventCreateWithFlags(&evJ, cudaEventDisableTiming) == cudaSuccess);
    cudaStream_t sc = forked ? s2 : 0;

    if (forked) {
        cudaEventRecord(evF, 0);
        cudaStreamWaitEvent(s2, evF, 0);
    }
    cudaMemsetAsync(degp, 0, NN * sizeof(int), sc);
    k_hist<<<(NE + 255) / 256, 256, 0, sc>>>(dst);
    k_scan<<<1, 1024, 0, sc>>>();
    k_scatter<<<(NE + 255) / 256, 256, 0, sc>>>(src, dst);
    if (forked) cudaEventRecord(evJ, s2);

    // main stream: presplit + layer0 GEMM
    k_presplitW<<<(128 * 256 + 255) / 256, 256>>>(W0, w0h, w0l);
    k_presplitW<<<(128 * 256 + 255) / 256, 256>>>(W1, w1h, w1l);
    k_presplit<<<(NN * 64 + 255) / 256, 256>>>((const float4*)x, (uint2*)xh, (uint2*)xl, NN * 64);

    dim3 gtc(4, (NN + 127) / 128);
    int aggBlocks = (NN * 32 + 255) / 256;

    k_gemm_tc<<<gtc, 256>>>(xh, xl, w0h, w0l, feath, al0, ar0, NN);

    if (forked) cudaStreamWaitEvent(0, evJ, 0);

    k_agg4<0><<<aggBlocks, 256>>>(feath, x, nullptr, nullptr, b0, nullptr, h1h, h1l);

    k_gemm_tc<<<gtc, 256>>>(h1h, h1l, w1h, w1l, feath, al1, ar1, NN);
    k_agg4<1><<<aggBlocks, 256>>>(feath, nullptr, h1h, h1l, b1, h2, nullptr, nullptr);

    k_gemm16x2<<<(NN * 32 + 255) / 256, 256>>>(h2, W2, rW2, feat2, res2, al2, ar2);
    k_agg2<<<aggBlocks, 256>>>(feat2, res2, b2, out);
}

// round 10
// speedup vs baseline: 2.5242x; 1.0375x over previous
#include <cuda_runtime.h>
#include <cuda_fp16.h>
#include <math.h>
#include <stdint.h>

#define NN 50000
#define NE 800000

// ---------------- scratch ----------------------------------------------------
__device__ __align__(16) __half g_feat_h[NN * 256]; // GEMM output (fp16) for gathers
__device__ __align__(16) __half g_xh[NN * 256];     // presplit A hi (layer0)
__device__ __align__(16) __half g_xl[NN * 256];     // presplit A lo
__device__ __align__(16) __half g_h1h[NN * 256];    // layer0 out hi (= layer1 A hi)
__device__ __align__(16) __half g_h1l[NN * 256];    // layer0 out lo
__device__ __align__(16) float  g_h2[NN * 256];     // layer1 out (fp32)
__device__ __align__(16) float  g_feat2[NN * 16];
__device__ __align__(16) float  g_res2[NN * 16];
__device__ __align__(16) __half2 g_w0h[128 * 256];  // W packed k-pairs (hi only)
__device__ __align__(16) __half2 g_w1h[128 * 256];
__device__ __align__(16) float g_el[NN * 4];
__device__ __align__(16) float g_er[NN * 4];
__device__ int g_deg[NN];
__device__ int g_rowptr[NN + 1];
__device__ int g_pos[NN];
__device__ int g_csr_src[NE];

// ---------------- CSR build --------------------------------------------------
__global__ void k_hist(const int* __restrict__ dst) {
    int e = blockIdx.x * blockDim.x + threadIdx.x;
    if (e < NE) atomicAdd(&g_deg[dst[e]], 1);
}

__global__ void k_scan() {
    __shared__ int warp_pref[32];
    const int T = 1024;
    int t = threadIdx.x;
    const int per = (NN + T - 1) / T;
    int begin = t * per;
    int end = min(begin + per, NN);
    if (begin > NN) begin = NN;
    if (end < begin) end = begin;

    int sum = 0;
    for (int i = begin; i < end; i++) sum += g_deg[i];

    int lane = t & 31, wid = t >> 5;
    int v = sum;
#pragma unroll
    for (int o = 1; o < 32; o <<= 1) {
        int u = __shfl_up_sync(0xffffffffu, v, o);
        if (lane >= o) v += u;
    }
    if (lane == 31) warp_pref[wid] = v;
    __syncthreads();
    if (wid == 0) {
        int w = warp_pref[lane];
#pragma unroll
        for (int o = 1; o < 32; o <<= 1) {
            int u = __shfl_up_sync(0xffffffffu, w, o);
            if (lane >= o) w += u;
        }
        warp_pref[lane] = w;
    }
    __syncthreads();
    int excl = v - sum + (wid ? warp_pref[wid - 1] : 0);

    int run = excl;
    for (int i = begin; i < end; i++) {
        g_rowptr[i] = run;
        g_pos[i] = run;
        run += g_deg[i];
    }
    if (t == T - 1) g_rowptr[NN] = run;
}

__global__ void k_scatter(const int* __restrict__ src, const int* __restrict__ dst) {
    int e = blockIdx.x * blockDim.x + threadIdx.x;
    if (e < NE) {
        int p = atomicAdd(&g_pos[dst[e]], 1);
        g_csr_src[p] = src[e];
    }
}

// ---------------- presplit helpers -------------------------------------------
__device__ __forceinline__ void split2(float x, float y, __half2& hi, __half2& lo) {
    __half hx = __float2half_rn(x), hy = __float2half_rn(y);
    hi = __halves2half2(hx, hy);
    lo = __floats2half2_rn(x - __half2float(hx), y - __half2float(hy));
}

__global__ void k_presplit(const float4* __restrict__ A, uint2* __restrict__ H,
                           uint2* __restrict__ L, int n4) {
    int i = blockIdx.x * blockDim.x + threadIdx.x;
    if (i >= n4) return;
    float4 v = A[i];
    __half2 h0, l0, h1, l1;
    split2(v.x, v.y, h0, l0);
    split2(v.z, v.w, h1, l1);
    H[i] = make_uint2(*(uint32_t*)&h0, *(uint32_t*)&h1);
    L[i] = make_uint2(*(uint32_t*)&l0, *(uint32_t*)&l1);
}

// W[256][256] -> packed k-pair form, hi only: P[kp][n] = half2(W[2kp][n], W[2kp+1][n])
__global__ void k_presplitW(const float* __restrict__ W, __half2* __restrict__ Ph) {
    int idx = blockIdx.x * blockDim.x + threadIdx.x;
    if (idx >= 128 * 256) return;
    int kp = idx >> 8, n = idx & 255;
    float a = W[(2 * kp) * 256 + n];
    float b = W[(2 * kp + 1) * 256 + n];
    Ph[idx] = __halves2half2(__float2half_rn(a), __float2half_rn(b));
}

// ---------------- tensor-core GEMM: 2-term (exact-A x fp16-W) ----------------
__device__ __forceinline__ void mma16(float* d, const uint32_t* a, const uint32_t* b) {
    asm volatile(
        "mma.sync.aligned.m16n8k16.row.col.f32.f16.f16.f32 "
        "{%0,%1,%2,%3}, {%4,%5,%6,%7}, {%8,%9}, {%0,%1,%2,%3};\n"
        : "+f"(d[0]), "+f"(d[1]), "+f"(d[2]), "+f"(d[3])
        : "r"(a[0]), "r"(a[1]), "r"(a[2]), "r"(a[3]), "r"(b[0]), "r"(b[1]));
}

#define LDSM4(r0, r1, r2, r3, addr)                                           \
    asm volatile("ldmatrix.sync.aligned.m8n8.x4.shared.b16 {%0,%1,%2,%3}, [%4];" \
                 : "=r"(r0), "=r"(r1), "=r"(r2), "=r"(r3) : "r"(addr))

#define CP16(dst, src, n)                                                     \
    asm volatile("cp.async.cg.shared.global [%0], [%1], 16, %2;\n"            \
                 :: "r"(dst), "l"(src), "r"(n))
#define CPCOMMIT() asm volatile("cp.async.commit_group;\n" ::: "memory")
#define CPWAIT0()  asm volatile("cp.async.wait_group 0;\n" ::: "memory")

#define A_ROWB 48          // bytes per A smem row (12 half2)
#define A_STAGEB (128 * A_ROWB)
#define B_ROWB 288         // bytes per B smem k-pair row (72 half2)
#define B_STAGEB (8 * B_ROWB)

__global__ __launch_bounds__(256, 2) void k_gemm_tc(
    const __half* __restrict__ Axh, const __half* __restrict__ Axl,
    const __half2* __restrict__ Wph,
    __half* __restrict__ Ch, const float* __restrict__ pal,
    const float* __restrict__ pare, int M) {
    const int K = 256, N = 256;
    __shared__ __half2 Ah[2][128][12];
    __shared__ __half2 Al[2][128][12];
    __shared__ __half2 Bh[2][8][72];
    __shared__ float s_el[2][128];
    __shared__ float s_er[2][128];

    int tid = threadIdx.x;
    int lane = tid & 31;
    int wid = tid >> 5;
    int warp_n = wid & 1;
    int m_base = (wid >> 1) * 32;
    int n_base = warp_n * 32;
    int row0 = blockIdx.y * 128;
    int col0 = blockIdx.x * 64;
    int head = col0 >> 6;

    float acc[2][4][4];
#pragma unroll
    for (int mt = 0; mt < 2; mt++)
#pragma unroll
        for (int nt = 0; nt < 4; nt++)
#pragma unroll
            for (int i = 0; i < 4; i++) acc[mt][nt][i] = 0.f;

    int ar = tid >> 1;
    int acq = (tid & 1);
    int gr = row0 + ar;
    int aok = (gr < M) ? 16 : 0;
    int grc = min(gr, M - 1);
    int t2 = tid & 127;
    int kp = t2 >> 4;
    int nq = (t2 & 15) * 4;
    bool isHi = tid < 128;

    uint32_t ah_b = (uint32_t)__cvta_generic_to_shared(&Ah[0][0][0]);
    uint32_t al_b = (uint32_t)__cvta_generic_to_shared(&Al[0][0][0]);
    uint32_t bh_b = (uint32_t)__cvta_generic_to_shared(&Bh[0][0][0]);
    uint32_t a_dst = ar * A_ROWB + acq * 16;
    uint32_t b_dst = bh_b + kp * B_ROWB + nq * 4;

    uint32_t lm_off = (uint32_t)(m_base + (lane & 7) + ((lane >> 3) & 1) * 8) * A_ROWB
                      + (lane >> 4) * 16;

    int jq = lane >> 2;
    int jc = lane & 3;

    {
        const __half* sa = Axh + (size_t)grc * K + acq * 8;
        const __half* sl = Axl + (size_t)grc * K + acq * 8;
        CP16(ah_b + a_dst, sa, aok);
        CP16(al_b + a_dst, sl, aok);
        if (isHi) CP16(b_dst, Wph + (size_t)kp * N + col0 + nq, 16);
        CPCOMMIT();
    }

    const int NS = K / 16;
    for (int s = 0; s < NS; s++) {
        int cur = s & 1;
        CPWAIT0();
        __syncthreads();
        if (s + 1 < NS) {
            int k0 = (s + 1) * 16;
            uint32_t stoff = (cur ^ 1) ? A_STAGEB : 0;
            const __half* sa = Axh + (size_t)grc * K + k0 + acq * 8;
            const __half* sl = Axl + (size_t)grc * K + k0 + acq * 8;
            CP16(ah_b + stoff + a_dst, sa, aok);
            CP16(al_b + stoff + a_dst, sl, aok);
            uint32_t bst = (cur ^ 1) ? B_STAGEB : 0;
            if (isHi) CP16(b_dst + bst, Wph + ((size_t)(k0 >> 1) + kp) * N + col0 + nq, 16);
            CPCOMMIT();
        }

        uint32_t ah[2][4], al_[2][4];
        uint32_t a_st = cur ? A_STAGEB : 0;
#pragma unroll
        for (int mt = 0; mt < 2; mt++) {
            uint32_t off = a_st + lm_off + mt * (16 * A_ROWB);
            LDSM4(ah[mt][0], ah[mt][1], ah[mt][2], ah[mt][3], ah_b + off);
            LDSM4(al_[mt][0], al_[mt][1], al_[mt][2], al_[mt][3], al_b + off);
        }
        uint32_t bh[4][2];
#pragma unroll
        for (int nt = 0; nt < 4; nt++) {
            int n = n_base + nt * 8 + jq;
            bh[nt][0] = *(const uint32_t*)&Bh[cur][jc][n];
            bh[nt][1] = *(const uint32_t*)&Bh[cur][jc + 4][n];
        }
#pragma unroll
        for (int mt = 0; mt < 2; mt++)
#pragma unroll
            for (int nt = 0; nt < 4; nt++) {
                mma16(acc[mt][nt], ah[mt], bh[nt]);
                mma16(acc[mt][nt], al_[mt], bh[nt]);
            }
    }

    // ---- fp16 feature store + fused el/er ------------------------------------
    float elv[4] = {0.f, 0.f, 0.f, 0.f}, erv[4] = {0.f, 0.f, 0.f, 0.f};
#pragma unroll
    for (int mt = 0; mt < 2; mt++)
#pragma unroll
        for (int nt = 0; nt < 4; nt++) {
            int r = row0 + m_base + mt * 16 + jq;
            int cl = n_base + nt * 8 + 2 * jc;
            int c = col0 + cl;
            if (r < M)
                *(__half2*)&Ch[(size_t)r * N + c] =
                    __floats2half2_rn(acc[mt][nt][0], acc[mt][nt][1]);
            if (r + 8 < M)
                *(__half2*)&Ch[(size_t)(r + 8) * N + c] =
                    __floats2half2_rn(acc[mt][nt][2], acc[mt][nt][3]);
            float w0 = pal[c], w1 = pal[c + 1];
            float u0 = pare[c], u1 = pare[c + 1];
            elv[mt * 2]     += acc[mt][nt][0] * w0 + acc[mt][nt][1] * w1;
            elv[mt * 2 + 1] += acc[mt][nt][2] * w0 + acc[mt][nt][3] * w1;
            erv[mt * 2]     += acc[mt][nt][0] * u0 + acc[mt][nt][1] * u1;
            erv[mt * 2 + 1] += acc[mt][nt][2] * u0 + acc[mt][nt][3] * u1;
        }
#pragma unroll
    for (int o = 1; o <= 2; o <<= 1) {
#pragma unroll
        for (int i = 0; i < 4; i++) {
            elv[i] += __shfl_xor_sync(0xffffffffu, elv[i], o);
            erv[i] += __shfl_xor_sync(0xffffffffu, erv[i], o);
        }
    }
    if (jc == 0) {
#pragma unroll
        for (int i = 0; i < 4; i++) {
            int lr = m_base + (i >> 1) * 16 + (i & 1) * 8 + jq;
            s_el[warp_n][lr] = elv[i];
            s_er[warp_n][lr] = erv[i];
        }
    }
    __syncthreads();
    if (tid < 128) {
        int r = row0 + tid;
        if (r < M) {
            g_el[r * 4 + head] = s_el[0][tid] + s_el[1][tid];
            g_er[r * 4 + head] = s_er[0][tid] + s_er[1][tid];
        }
    }
}

// ---------------- fused dual small GEMM + layer2 el/er -----------------------
__global__ void k_gemm16x2(const float* __restrict__ A, const float* __restrict__ B1,
                           const float* __restrict__ B2, float* __restrict__ C1,
                           float* __restrict__ C2, const float* __restrict__ al2,
                           const float* __restrict__ ar2) {
    __shared__ float Bs[256 * 32];
    for (int i = threadIdx.x; i < 256 * 16; i += blockDim.x) {
        Bs[(i >> 4) * 32 + (i & 15)] = B1[i];
        Bs[(i >> 4) * 32 + 16 + (i & 15)] = B2[i];
    }
    __syncthreads();
    int tid = blockIdx.x * blockDim.x + threadIdx.x;
    int f = tid & 31, node = tid >> 5;
    if (node >= NN) return;
    const float* a = A + (size_t)node * 256;
    float acc = 0.f;
#pragma unroll 8
    for (int k = 0; k < 256; k++) acc += a[k] * Bs[k * 32 + f];
    float elv = 0.f, erv = 0.f;
    if (f < 16) {
        C1[node * 16 + f] = acc;
        elv = acc * al2[f];
        erv = acc * ar2[f];
    } else {
        C2[node * 16 + f - 16] = acc;
    }
#pragma unroll
    for (int o = 8; o; o >>= 1) {
        elv += __shfl_xor_sync(0xffffffffu, elv, o, 16);
        erv += __shfl_xor_sync(0xffffffffu, erv, o, 16);
    }
    if (f == 0) { g_el[node] = elv; g_er[node] = erv; }
}

// ---------------- fused softmax-aggregate ------------------------------------
__device__ __forceinline__ float mishf(float x) {
    float sp = fmaxf(x, 0.f) + log1pf(__expf(-fabsf(x)));
    return x * tanhf(sp);
}

__device__ __forceinline__ float lrelu(float e) { return (e > 0.f) ? e : 0.2f * e; }

// lane l owns output columns [8l, 8l+8). One LDG.128 per edge per warp.
// MODE 0: res fp32 -> out split; MODE 1: res split -> out fp32
template <int MODE>
__global__ __launch_bounds__(256) void k_agg4(
    const __half* __restrict__ feath, const float* __restrict__ resf,
    const __half* __restrict__ resh, const __half* __restrict__ resl,
    const float* __restrict__ bias, float* __restrict__ outf,
    __half* __restrict__ outh, __half* __restrict__ outl) {
    __shared__ float4 sw[8][32];   // per-warp per-edge weights (4 heads)
    int node = (blockIdx.x * blockDim.x + threadIdx.x) >> 5;
    int lane = threadIdx.x & 31;
    int warp = (threadIdx.x >> 5);
    if (node >= NN) return;
    int start = g_rowptr[node], end = g_rowptr[node + 1];
    float4 er4 = *(const float4*)&g_er[node * 4];
    int h = lane >> 3;             // my head
    float acc[8] = {0.f, 0.f, 0.f, 0.f, 0.f, 0.f, 0.f, 0.f};
    float ss0 = 0.f, ss1 = 0.f, ss2 = 0.f, ss3 = 0.f;

    for (int base = start; base < end; base += 32) {
        int i = base + lane;
        int s = 0;
        float w0 = 0.f, w1 = 0.f, w2 = 0.f, w3 = 0.f;
        if (i < end) {
            s = g_csr_src[i];
            float4 el4 = *(const float4*)&g_el[s * 4];
            w0 = __expf(lrelu(el4.x + er4.x));
            w1 = __expf(lrelu(el4.y + er4.y));
            w2 = __expf(lrelu(el4.z + er4.z));
            w3 = __expf(lrelu(el4.w + er4.w));
            ss0 += w0; ss1 += w1; ss2 += w2; ss3 += w3;
        }
        __syncwarp();
        sw[warp][lane] = make_float4(w0, w1, w2, w3);
        __syncwarp();
        int cnt = min(32, end - base);
        const float* swp = (const float*)&sw[warp][0];
        int j = 0;
        for (; j + 1 < cnt; j += 2) {
            int sjA = __shfl_sync(0xffffffffu, s, j);
            int sjB = __shfl_sync(0xffffffffu, s, j + 1);
            uint4 vA = *(const uint4*)(feath + (size_t)sjA * 256 + lane * 8);
            uint4 vB = *(const uint4*)(feath + (size_t)sjB * 256 + lane * 8);
            float wA = swp[j * 4 + h];
            float wB = swp[(j + 1) * 4 + h];
            float2 f0 = __half22float2(*(__half2*)&vA.x);
            float2 f1 = __half22float2(*(__half2*)&vA.y);
            float2 f2 = __half22float2(*(__half2*)&vA.z);
            float2 f3 = __half22float2(*(__half2*)&vA.w);
            acc[0] += wA * f0.x; acc[1] += wA * f0.y;
            acc[2] += wA * f1.x; acc[3] += wA * f1.y;
            acc[4] += wA * f2.x; acc[5] += wA * f2.y;
            acc[6] += wA * f3.x; acc[7] += wA * f3.y;
            f0 = __half22float2(*(__half2*)&vB.x);
            f1 = __half22float2(*(__half2*)&vB.y);
            f2 = __half22float2(*(__half2*)&vB.z);
            f3 = __half22float2(*(__half2*)&vB.w);
            acc[0] += wB * f0.x; acc[1] += wB * f0.y;
            acc[2] += wB * f1.x; acc[3] += wB * f1.y;
            acc[4] += wB * f2.x; acc[5] += wB * f2.y;
            acc[6] += wB * f3.x; acc[7] += wB * f3.y;
        }
        if (j < cnt) {
            int sj = __shfl_sync(0xffffffffu, s, j);
            uint4 v = *(const uint4*)(feath + (size_t)sj * 256 + lane * 8);
            float w = swp[j * 4 + h];
            float2 f0 = __half22float2(*(__half2*)&v.x);
            float2 f1 = __half22float2(*(__half2*)&v.y);
            float2 f2 = __half22float2(*(__half2*)&v.z);
            float2 f3 = __half22float2(*(__half2*)&v.w);
            acc[0] += w * f0.x; acc[1] += w * f0.y;
            acc[2] += w * f1.x; acc[3] += w * f1.y;
            acc[4] += w * f2.x; acc[5] += w * f2.y;
            acc[6] += w * f3.x; acc[7] += w * f3.y;
        }
    }
#pragma unroll
    for (int o = 16; o; o >>= 1) {
        ss0 += __shfl_xor_sync(0xffffffffu, ss0, o);
        ss1 += __shfl_xor_sync(0xffffffffu, ss1, o);
        ss2 += __shfl_xor_sync(0xffffffffu, ss2, o);
        ss3 += __shfl_xor_sync(0xffffffffu, ss3, o);
    }
    bool has = (end > start);
    float inv;
    {
        float sssel = (h == 0) ? ss0 : (h == 1) ? ss1 : (h == 2) ? ss2 : ss3;
        inv = has ? 1.f / sssel : 0.f;
    }

    size_t off = (size_t)node * 256 + lane * 8;
    int bc = lane * 8;
    float o[8];
    if (MODE == 0) {
        float4 r0 = *(const float4*)&resf[off];
        float4 r1 = *(const float4*)&resf[off + 4];
        o[0] = mishf(acc[0] * inv + r0.x + bias[bc]);
        o[1] = mishf(acc[1] * inv + r0.y + bias[bc + 1]);
        o[2] = mishf(acc[2] * inv + r0.z + bias[bc + 2]);
        o[3] = mishf(acc[3] * inv + r0.w + bias[bc + 3]);
        o[4] = mishf(acc[4] * inv + r1.x + bias[bc + 4]);
        o[5] = mishf(acc[5] * inv + r1.y + bias[bc + 5]);
        o[6] = mishf(acc[6] * inv + r1.z + bias[bc + 6]);
        o[7] = mishf(acc[7] * inv + r1.w + bias[bc + 7]);
        uint4 vh, vl;
        __half2 hh, ll;
        split2(o[0], o[1], hh, ll); vh.x = *(uint32_t*)&hh; vl.x = *(uint32_t*)&ll;
        split2(o[2], o[3], hh, ll); vh.y = *(uint32_t*)&hh; vl.y = *(uint32_t*)&ll;
        split2(o[4], o[5], hh, ll); vh.z = *(uint32_t*)&hh; vl.z = *(uint32_t*)&ll;
        split2(o[6], o[7], hh, ll); vh.w = *(uint32_t*)&hh; vl.w = *(uint32_t*)&ll;
        *(uint4*)(outh + off) = vh;
        *(uint4*)(outl + off) = vl;
    } else {
        uint4 vh = *(const uint4*)(resh + off);
        uint4 vl = *(const uint4*)(resl + off);
        float2 rh[4], rl[4];
        rh[0] = __half22float2(*(__half2*)&vh.x); rl[0] = __half22float2(*(__half2*)&vl.x);
        rh[1] = __half22float2(*(__half2*)&vh.y); rl[1] = __half22float2(*(__half2*)&vl.y);
        rh[2] = __half22float2(*(__half2*)&vh.z); rl[2] = __half22float2(*(__half2*)&vl.z);
        rh[3] = __half22float2(*(__half2*)&vh.w); rl[3] = __half22float2(*(__half2*)&vl.w);
#pragma unroll
        for (int q = 0; q < 4; q++) {
            o[2 * q]     = mishf(acc[2 * q] * inv + rh[q].x + rl[q].x + bias[bc + 2 * q]);
            o[2 * q + 1] = mishf(acc[2 * q + 1] * inv + rh[q].y + rl[q].y + bias[bc + 2 * q + 1]);
        }
        *(float4*)&outf[off] = make_float4(o[0], o[1], o[2], o[3]);
        *(float4*)&outf[off + 4] = make_float4(o[4], o[5], o[6], o[7]);
    }
}

// ---------------- softmax-aggregate layer2, H=1 D=16 -------------------------
__global__ __launch_bounds__(256) void k_agg2(
    const float* __restrict__ feat, const float* __restrict__ res,
    const float* __restrict__ bias, float* __restrict__ out) {
    int node = (blockIdx.x * blockDim.x + threadIdx.x) >> 5;
    int lane = threadIdx.x & 31;
    if (node >= NN) return;
    int start = g_rowptr[node], end = g_rowptr[node + 1];
    float er_n = g_er[node];

    float acc = 0.f, ss = 0.f;
    for (int base = start; base < end; base += 32) {
        int i = base + lane;
        int s = 0;
        float w = 0.f;
        if (i < end) {
            s = g_csr_src[i];
            w = __expf(lrelu(g_el[s] + er_n));
            ss += w;
        }
        int cnt = min(32, end - base);
        for (int j = 0; j < cnt; j++) {
            int   sj = __shfl_sync(0xffffffffu, s, j);
            float bw = __shfl_sync(0xffffffffu, w, j);
            if (lane < 16) acc += bw * feat[(size_t)sj * 16 + lane];
        }
    }
#pragma unroll
    for (int o = 16; o; o >>= 1) ss += __shfl_xor_sync(0xffffffffu, ss, o);
    float inv = (end > start) ? 1.f / ss : 0.f;
    if (lane < 16)
        out[(size_t)node * 16 + lane] = acc * inv + res[(size_t)node * 16 + lane] + bias[lane];
}

// ---------------- launch -----------------------------------------------------
extern "C" void kernel_launch(void* const* d_in, const int* in_sizes, int n_in,
                              void* d_out, int out_size) {
    const float* x    = (const float*)d_in[0];
    const int*   src  = (const int*)d_in[1];
    const int*   dst  = (const int*)d_in[2];
    const float* W0   = (const float*)d_in[3];
    const float* al0  = (const float*)d_in[4];
    const float* ar0  = (const float*)d_in[5];
    const float* b0   = (const float*)d_in[6];
    const float* W1   = (const float*)d_in[7];
    const float* al1  = (const float*)d_in[8];
    const float* ar1  = (const float*)d_in[9];
    const float* b1   = (const float*)d_in[10];
    const float* W2   = (const float*)d_in[11];
    const float* al2  = (const float*)d_in[12];
    const float* ar2  = (const float*)d_in[13];
    const float* b2   = (const float*)d_in[14];
    const float* rW2  = (const float*)d_in[15];
    float* out = (float*)d_out;

    __half *feath, *xh, *xl, *h1h, *h1l;
    float *h2, *feat2, *res2;
    __half2 *w0h, *w1h;
    void* degp;
    cudaGetSymbolAddress((void**)&feath, g_feat_h);
    cudaGetSymbolAddress((void**)&xh, g_xh);
    cudaGetSymbolAddress((void**)&xl, g_xl);
    cudaGetSymbolAddress((void**)&h1h, g_h1h);
    cudaGetSymbolAddress((void**)&h1l, g_h1l);
    cudaGetSymbolAddress((void**)&h2, g_h2);
    cudaGetSymbolAddress((void**)&feat2, g_feat2);
    cudaGetSymbolAddress((void**)&res2, g_res2);
    cudaGetSymbolAddress((void**)&w0h, g_w0h);
    cudaGetSymbolAddress((void**)&w1h, g_w1h);
    cudaGetSymbolAddress(&degp, g_deg);

    // fork a side stream for the CSR build
    cudaStream_t s2 = 0;
    cudaEvent_t evF = 0, evJ = 0;
    bool forked = (cudaStreamCreateWithFlags(&s2, cudaStreamNonBlocking) == cudaSuccess) &&
                  (cudaEventCreateWithFlags(&evF, cudaEventDisableTiming) == cudaSuccess) &&
                  (cudaEventCreateWithFlags(&evJ, cudaEventDisableTiming) == cudaSuccess);
    cudaStream_t sc = forked ? s2 : 0;

    if (forked) {
        cudaEventRecord(evF, 0);
        cudaStreamWaitEvent(s2, evF, 0);
    }
    cudaMemsetAsync(degp, 0, NN * sizeof(int), sc);
    k_hist<<<(NE + 255) / 256, 256, 0, sc>>>(dst);
    k_scan<<<1, 1024, 0, sc>>>();
    k_scatter<<<(NE + 255) / 256, 256, 0, sc>>>(src, dst);
    if (forked) cudaEventRecord(evJ, s2);

    // main stream: presplit + layer0 GEMM
    k_presplitW<<<(128 * 256 + 255) / 256, 256>>>(W0, w0h);
    k_presplitW<<<(128 * 256 + 255) / 256, 256>>>(W1, w1h);
    k_presplit<<<(NN * 64 + 255) / 256, 256>>>((const float4*)x, (uint2*)xh, (uint2*)xl, NN * 64);

    dim3 gtc(4, (NN + 127) / 128);
    int aggBlocks = (NN * 32 + 255) / 256;

    k_gemm_tc<<<gtc, 256>>>(xh, xl, w0h, feath, al0, ar0, NN);

    if (forked) cudaStreamWaitEvent(0, evJ, 0);

    k_agg4<0><<<aggBlocks, 256>>>(feath, x, nullptr, nullptr, b0, nullptr, h1h, h1l);

    k_gemm_tc<<<gtc, 256>>>(h1h, h1l, w1h, feath, al1, ar1, NN);
    k_agg4<1><<<aggBlocks, 256>>>(feath, nullptr, h1h, h1l, b1, h2, nullptr, nullptr);

    k_gemm16x2<<<(NN * 32 + 255) / 256, 256>>>(h2, W2, rW2, feat2, res2, al2, ar2);
    k_agg2<<<aggBlocks, 256>>>(feat2, res2, b2, out);
}

// round 11
// speedup vs baseline: 3.1694x; 1.2556x over previous
#include <cuda_runtime.h>
#include <cuda_fp16.h>
#include <math.h>
#include <stdint.h>

#define NN 50000
#define NE 800000

// ---------------- scratch ----------------------------------------------------
__device__ __align__(16) __half g_feat_h[NN * 256]; // GEMM output (fp16) for gathers
__device__ __align__(16) __half g_xh[NN * 256];     // presplit x hi; later h2 hi
__device__ __align__(16) __half g_xl[NN * 256];     // presplit x lo; later h2 lo
__device__ __align__(16) __half g_h1h[NN * 256];    // layer0 out hi (= layer1 A hi)
__device__ __align__(16) __half g_h1l[NN * 256];    // layer0 out lo
__device__ __align__(16) float  g_feat2[NN * 16];
__device__ __align__(16) float  g_res2[NN * 16];
__device__ __align__(16) __half2 g_w0h[128 * 256];  // W packed k-pairs (hi only)
__device__ __align__(16) __half2 g_w1h[128 * 256];
__device__ __align__(16) __half2 g_w2h[128 * 32];   // [W2|rW2] packed hi
__device__ __align__(16) __half2 g_w2l[128 * 32];   // [W2|rW2] packed lo
__device__ __align__(16) float g_el[NN * 4];
__device__ __align__(16) float g_er[NN * 4];
__device__ int g_deg[NN];
__device__ int g_rowptr[NN + 1];
__device__ int g_pos[NN];
__device__ int g_csr_src[NE];

// ---------------- CSR build --------------------------------------------------
__global__ void k_hist(const int* __restrict__ dst) {
    int e = blockIdx.x * blockDim.x + threadIdx.x;
    if (e < NE) atomicAdd(&g_deg[dst[e]], 1);
}

__global__ void k_scan() {
    __shared__ int warp_pref[32];
    const int T = 1024;
    int t = threadIdx.x;
    const int per = (NN + T - 1) / T;
    int begin = t * per;
    int end = min(begin + per, NN);
    if (begin > NN) begin = NN;
    if (end < begin) end = begin;

    int sum = 0;
    for (int i = begin; i < end; i++) sum += g_deg[i];

    int lane = t & 31, wid = t >> 5;
    int v = sum;
#pragma unroll
    for (int o = 1; o < 32; o <<= 1) {
        int u = __shfl_up_sync(0xffffffffu, v, o);
        if (lane >= o) v += u;
    }
    if (lane == 31) warp_pref[wid] = v;
    __syncthreads();
    if (wid == 0) {
        int w = warp_pref[lane];
#pragma unroll
        for (int o = 1; o < 32; o <<= 1) {
            int u = __shfl_up_sync(0xffffffffu, w, o);
            if (lane >= o) w += u;
        }
        warp_pref[lane] = w;
    }
    __syncthreads();
    int excl = v - sum + (wid ? warp_pref[wid - 1] : 0);

    int run = excl;
    for (int i = begin; i < end; i++) {
        g_rowptr[i] = run;
        g_pos[i] = run;
        run += g_deg[i];
    }
    if (t == T - 1) g_rowptr[NN] = run;
}

__global__ void k_scatter(const int* __restrict__ src, const int* __restrict__ dst) {
    int e = blockIdx.x * blockDim.x + threadIdx.x;
    if (e < NE) {
        int p = atomicAdd(&g_pos[dst[e]], 1);
        g_csr_src[p] = src[e];
    }
}

// ---------------- presplit helpers -------------------------------------------
__device__ __forceinline__ void split2(float x, float y, __half2& hi, __half2& lo) {
    __half hx = __float2half_rn(x), hy = __float2half_rn(y);
    hi = __halves2half2(hx, hy);
    lo = __floats2half2_rn(x - __half2float(hx), y - __half2float(hy));
}

__global__ void k_presplit(const float4* __restrict__ A, uint2* __restrict__ H,
                           uint2* __restrict__ L, int n4) {
    int i = blockIdx.x * blockDim.x + threadIdx.x;
    if (i >= n4) return;
    float4 v = A[i];
    __half2 h0, l0, h1, l1;
    split2(v.x, v.y, h0, l0);
    split2(v.z, v.w, h1, l1);
    H[i] = make_uint2(*(uint32_t*)&h0, *(uint32_t*)&h1);
    L[i] = make_uint2(*(uint32_t*)&l0, *(uint32_t*)&l1);
}

__global__ void k_presplitW(const float* __restrict__ W, __half2* __restrict__ Ph) {
    int idx = blockIdx.x * blockDim.x + threadIdx.x;
    if (idx >= 128 * 256) return;
    int kp = idx >> 8, n = idx & 255;
    float a = W[(2 * kp) * 256 + n];
    float b = W[(2 * kp + 1) * 256 + n];
    Ph[idx] = __halves2half2(__float2half_rn(a), __float2half_rn(b));
}

// [W2|rW2] (256x16 each) -> packed k-pair [128][32], hi+lo
__global__ void k_presplitW2(const float* __restrict__ W2, const float* __restrict__ rW2,
                             __half2* __restrict__ Ph, __half2* __restrict__ Pl) {
    int idx = blockIdx.x * blockDim.x + threadIdx.x;
    if (idx >= 128 * 32) return;
    int kp = idx >> 5, n = idx & 31;
    float a, b;
    if (n < 16) { a = W2[(2 * kp) * 16 + n];      b = W2[(2 * kp + 1) * 16 + n]; }
    else        { a = rW2[(2 * kp) * 16 + n - 16]; b = rW2[(2 * kp + 1) * 16 + n - 16]; }
    __half2 h, l;
    split2(a, b, h, l);
    Ph[idx] = h;
    Pl[idx] = l;
}

// ---------------- MMA / copy primitives --------------------------------------
__device__ __forceinline__ void mma16(float* d, const uint32_t* a, const uint32_t* b) {
    asm volatile(
        "mma.sync.aligned.m16n8k16.row.col.f32.f16.f16.f32 "
        "{%0,%1,%2,%3}, {%4,%5,%6,%7}, {%8,%9}, {%0,%1,%2,%3};\n"
        : "+f"(d[0]), "+f"(d[1]), "+f"(d[2]), "+f"(d[3])
        : "r"(a[0]), "r"(a[1]), "r"(a[2]), "r"(a[3]), "r"(b[0]), "r"(b[1]));
}

#define LDSM4(r0, r1, r2, r3, addr)                                           \
    asm volatile("ldmatrix.sync.aligned.m8n8.x4.shared.b16 {%0,%1,%2,%3}, [%4];" \
                 : "=r"(r0), "=r"(r1), "=r"(r2), "=r"(r3) : "r"(addr))

#define CP16(dst, src, n)                                                     \
    asm volatile("cp.async.cg.shared.global [%0], [%1], 16, %2;\n"            \
                 :: "r"(dst), "l"(src), "r"(n))
#define CPCOMMIT() asm volatile("cp.async.commit_group;\n" ::: "memory")
#define CPWAIT0()  asm volatile("cp.async.wait_group 0;\n" ::: "memory")

#define A_ROWB 48          // bytes per A smem row (12 half2)
#define A_STAGEB (128 * A_ROWB)
#define B_ROWB 288         // bytes per B smem k-pair row (72 half2)
#define B_STAGEB (8 * B_ROWB)

// ---------------- big GEMM: 2-term (exact-A x fp16-W), fused el/er -----------
__global__ __launch_bounds__(256, 2) void k_gemm_tc(
    const __half* __restrict__ Axh, const __half* __restrict__ Axl,
    const __half2* __restrict__ Wph,
    __half* __restrict__ Ch, const float* __restrict__ pal,
    const float* __restrict__ pare, int M) {
    const int K = 256, N = 256;
    __shared__ __half2 Ah[2][128][12];
    __shared__ __half2 Al[2][128][12];
    __shared__ __half2 Bh[2][8][72];
    __shared__ float s_el[2][128];
    __shared__ float s_er[2][128];

    int tid = threadIdx.x;
    int lane = tid & 31;
    int wid = tid >> 5;
    int warp_n = wid & 1;
    int m_base = (wid >> 1) * 32;
    int n_base = warp_n * 32;
    int row0 = blockIdx.y * 128;
    int col0 = blockIdx.x * 64;
    int head = col0 >> 6;

    float acc[2][4][4];
#pragma unroll
    for (int mt = 0; mt < 2; mt++)
#pragma unroll
        for (int nt = 0; nt < 4; nt++)
#pragma unroll
            for (int i = 0; i < 4; i++) acc[mt][nt][i] = 0.f;

    int ar = tid >> 1;
    int acq = (tid & 1);
    int gr = row0 + ar;
    int aok = (gr < M) ? 16 : 0;
    int grc = min(gr, M - 1);
    int t2 = tid & 127;
    int kp = t2 >> 4;
    int nq = (t2 & 15) * 4;
    bool isHi = tid < 128;

    uint32_t ah_b = (uint32_t)__cvta_generic_to_shared(&Ah[0][0][0]);
    uint32_t al_b = (uint32_t)__cvta_generic_to_shared(&Al[0][0][0]);
    uint32_t bh_b = (uint32_t)__cvta_generic_to_shared(&Bh[0][0][0]);
    uint32_t a_dst = ar * A_ROWB + acq * 16;
    uint32_t b_dst = bh_b + kp * B_ROWB + nq * 4;

    uint32_t lm_off = (uint32_t)(m_base + (lane & 7) + ((lane >> 3) & 1) * 8) * A_ROWB
                      + (lane >> 4) * 16;

    int jq = lane >> 2;
    int jc = lane & 3;

    {
        const __half* sa = Axh + (size_t)grc * K + acq * 8;
        const __half* sl = Axl + (size_t)grc * K + acq * 8;
        CP16(ah_b + a_dst, sa, aok);
        CP16(al_b + a_dst, sl, aok);
        if (isHi) CP16(b_dst, Wph + (size_t)kp * N + col0 + nq, 16);
        CPCOMMIT();
    }

    const int NS = K / 16;
    for (int s = 0; s < NS; s++) {
        int cur = s & 1;
        CPWAIT0();
        __syncthreads();
        if (s + 1 < NS) {
            int k0 = (s + 1) * 16;
            uint32_t stoff = (cur ^ 1) ? A_STAGEB : 0;
            const __half* sa = Axh + (size_t)grc * K + k0 + acq * 8;
            const __half* sl = Axl + (size_t)grc * K + k0 + acq * 8;
            CP16(ah_b + stoff + a_dst, sa, aok);
            CP16(al_b + stoff + a_dst, sl, aok);
            uint32_t bst = (cur ^ 1) ? B_STAGEB : 0;
            if (isHi) CP16(b_dst + bst, Wph + ((size_t)(k0 >> 1) + kp) * N + col0 + nq, 16);
            CPCOMMIT();
        }

        uint32_t ah[2][4], al_[2][4];
        uint32_t a_st = cur ? A_STAGEB : 0;
#pragma unroll
        for (int mt = 0; mt < 2; mt++) {
            uint32_t off = a_st + lm_off + mt * (16 * A_ROWB);
            LDSM4(ah[mt][0], ah[mt][1], ah[mt][2], ah[mt][3], ah_b + off);
            LDSM4(al_[mt][0], al_[mt][1], al_[mt][2], al_[mt][3], al_b + off);
        }
        uint32_t bh[4][2];
#pragma unroll
        for (int nt = 0; nt < 4; nt++) {
            int n = n_base + nt * 8 + jq;
            bh[nt][0] = *(const uint32_t*)&Bh[cur][jc][n];
            bh[nt][1] = *(const uint32_t*)&Bh[cur][jc + 4][n];
        }
#pragma unroll
        for (int mt = 0; mt < 2; mt++)
#pragma unroll
            for (int nt = 0; nt < 4; nt++) {
                mma16(acc[mt][nt], ah[mt], bh[nt]);
                mma16(acc[mt][nt], al_[mt], bh[nt]);
            }
    }

    // ---- fp16 feature store + fused el/er ------------------------------------
    float elv[4] = {0.f, 0.f, 0.f, 0.f}, erv[4] = {0.f, 0.f, 0.f, 0.f};
#pragma unroll
    for (int mt = 0; mt < 2; mt++)
#pragma unroll
        for (int nt = 0; nt < 4; nt++) {
            int r = row0 + m_base + mt * 16 + jq;
            int cl = n_base + nt * 8 + 2 * jc;
            int c = col0 + cl;
            if (r < M)
                *(__half2*)&Ch[(size_t)r * N + c] =
                    __floats2half2_rn(acc[mt][nt][0], acc[mt][nt][1]);
            if (r + 8 < M)
                *(__half2*)&Ch[(size_t)(r + 8) * N + c] =
                    __floats2half2_rn(acc[mt][nt][2], acc[mt][nt][3]);
            float w0 = pal[c], w1 = pal[c + 1];
            float u0 = pare[c], u1 = pare[c + 1];
            elv[mt * 2]     += acc[mt][nt][0] * w0 + acc[mt][nt][1] * w1;
            elv[mt * 2 + 1] += acc[mt][nt][2] * w0 + acc[mt][nt][3] * w1;
            erv[mt * 2]     += acc[mt][nt][0] * u0 + acc[mt][nt][1] * u1;
            erv[mt * 2 + 1] += acc[mt][nt][2] * u0 + acc[mt][nt][3] * u1;
        }
#pragma unroll
    for (int o = 1; o <= 2; o <<= 1) {
#pragma unroll
        for (int i = 0; i < 4; i++) {
            elv[i] += __shfl_xor_sync(0xffffffffu, elv[i], o);
            erv[i] += __shfl_xor_sync(0xffffffffu, erv[i], o);
        }
    }
    if (jc == 0) {
#pragma unroll
        for (int i = 0; i < 4; i++) {
            int lr = m_base + (i >> 1) * 16 + (i & 1) * 8 + jq;
            s_el[warp_n][lr] = elv[i];
            s_er[warp_n][lr] = erv[i];
        }
    }
    __syncthreads();
    if (tid < 128) {
        int r = row0 + tid;
        if (r < M) {
            g_el[r * 4 + head] = s_el[0][tid] + s_el[1][tid];
            g_er[r * 4 + head] = s_er[0][tid] + s_er[1][tid];
        }
    }
}

// ---------------- layer-2 GEMM: [feat2|res2] = h2 @ [W2|rW2], 3-term exact ---
#define B2_ROWB 160      // bytes per B smem k-pair row (40 half2; 32 used)
#define B2_STAGEB (8 * B2_ROWB)

__global__ __launch_bounds__(256, 2) void k_gemm16_tc(
    const __half* __restrict__ Axh, const __half* __restrict__ Axl,
    const __half2* __restrict__ Wph, const __half2* __restrict__ Wpl,
    float* __restrict__ feat2, float* __restrict__ res2,
    const float* __restrict__ al2, const float* __restrict__ ar2, int M) {
    const int K = 256;
    __shared__ __half2 Ah[2][128][12];
    __shared__ __half2 Al[2][128][12];
    __shared__ __half2 Bh[2][8][40];
    __shared__ __half2 Bl[2][8][40];

    int tid = threadIdx.x;
    int lane = tid & 31;
    int wid = tid >> 5;
    int m_base = wid * 16;
    int row0 = blockIdx.x * 128;

    float acc[4][4];
#pragma unroll
    for (int nt = 0; nt < 4; nt++)
#pragma unroll
        for (int i = 0; i < 4; i++) acc[nt][i] = 0.f;

    int ar = tid >> 1;
    int acq = (tid & 1);
    int gr = row0 + ar;
    int aok = (gr < M) ? 16 : 0;
    int grc = min(gr, M - 1);
    // B staging: threads 0..63 hi, 64..127 lo; kp 0..7, chunk 0..7 (16B each)
    int t2 = tid & 63;
    int kp = t2 >> 3;
    int chk = t2 & 7;
    bool isB = tid < 128;
    bool isHi = tid < 64;

    uint32_t ah_b = (uint32_t)__cvta_generic_to_shared(&Ah[0][0][0]);
    uint32_t al_b = (uint32_t)__cvta_generic_to_shared(&Al[0][0][0]);
    uint32_t bh_b = (uint32_t)__cvta_generic_to_shared(&Bh[0][0][0]);
    uint32_t bl_b = (uint32_t)__cvta_generic_to_shared(&Bl[0][0][0]);
    uint32_t a_dst = ar * A_ROWB + acq * 16;
    uint32_t b_dst = (isHi ? bh_b : bl_b) + kp * B2_ROWB + chk * 16;
    const __half2* Wsrc = isHi ? Wph : Wpl;

    uint32_t lm_off = (uint32_t)(m_base + (lane & 7) + ((lane >> 3) & 1) * 8) * A_ROWB
                      + (lane >> 4) * 16;

    int jq = lane >> 2;
    int jc = lane & 3;

    {
        const __half* sa = Axh + (size_t)grc * K + acq * 8;
        const __half* sl = Axl + (size_t)grc * K + acq * 8;
        CP16(ah_b + a_dst, sa, aok);
        CP16(al_b + a_dst, sl, aok);
        if (isB) CP16(b_dst, Wsrc + (size_t)kp * 32 + chk * 4, 16);
        CPCOMMIT();
    }

    const int NS = K / 16;
    for (int s = 0; s < NS; s++) {
        int cur = s & 1;
        CPWAIT0();
        __syncthreads();
        if (s + 1 < NS) {
            int k0 = (s + 1) * 16;
            uint32_t stoff = (cur ^ 1) ? A_STAGEB : 0;
            const __half* sa = Axh + (size_t)grc * K + k0 + acq * 8;
            const __half* sl = Axl + (size_t)grc * K + k0 + acq * 8;
            CP16(ah_b + stoff + a_dst, sa, aok);
            CP16(al_b + stoff + a_dst, sl, aok);
            uint32_t bst = (cur ^ 1) ? B2_STAGEB : 0;
            if (isB) CP16(b_dst + bst, Wsrc + ((size_t)(k0 >> 1) + kp) * 32 + chk * 4, 16);
            CPCOMMIT();
        }

        uint32_t ah[4], al_[4];
        uint32_t a_st = cur ? A_STAGEB : 0;
        LDSM4(ah[0], ah[1], ah[2], ah[3], ah_b + a_st + lm_off);
        LDSM4(al_[0], al_[1], al_[2], al_[3], al_b + a_st + lm_off);
        uint32_t bh[4][2], bl[4][2];
#pragma unroll
        for (int nt = 0; nt < 4; nt++) {
            int n = nt * 8 + jq;
            bh[nt][0] = *(const uint32_t*)&Bh[cur][jc][n];
            bh[nt][1] = *(const uint32_t*)&Bh[cur][jc + 4][n];
            bl[nt][0] = *(const uint32_t*)&Bl[cur][jc][n];
            bl[nt][1] = *(const uint32_t*)&Bl[cur][jc + 4][n];
        }
#pragma unroll
        for (int nt = 0; nt < 4; nt++) {
            mma16(acc[nt], ah, bh[nt]);
            mma16(acc[nt], al_, bh[nt]);
            mma16(acc[nt], ah, bl[nt]);
        }
    }

    // ---- epilogue: feat2 (cols 0-15), res2 (cols 16-31), el/er ---------------
    int r0 = row0 + m_base + jq;
    int r1 = r0 + 8;
    float elv0 = 0.f, elv1 = 0.f, erv0 = 0.f, erv1 = 0.f;
#pragma unroll
    for (int nt = 0; nt < 4; nt++) {
        int c = nt * 8 + 2 * jc;
        if (nt < 2) {
            if (r0 < M) *(float2*)&feat2[(size_t)r0 * 16 + c] = make_float2(acc[nt][0], acc[nt][1]);
            if (r1 < M) *(float2*)&feat2[(size_t)r1 * 16 + c] = make_float2(acc[nt][2], acc[nt][3]);
            float w0 = al2[c], w1 = al2[c + 1];
            float u0 = ar2[c], u1 = ar2[c + 1];
            elv0 += acc[nt][0] * w0 + acc[nt][1] * w1;
            elv1 += acc[nt][2] * w0 + acc[nt][3] * w1;
            erv0 += acc[nt][0] * u0 + acc[nt][1] * u1;
            erv1 += acc[nt][2] * u0 + acc[nt][3] * u1;
        } else {
            int cc = c - 16;
            if (r0 < M) *(float2*)&res2[(size_t)r0 * 16 + cc] = make_float2(acc[nt][0], acc[nt][1]);
            if (r1 < M) *(float2*)&res2[(size_t)r1 * 16 + cc] = make_float2(acc[nt][2], acc[nt][3]);
        }
    }
#pragma unroll
    for (int o = 1; o <= 2; o <<= 1) {
        elv0 += __shfl_xor_sync(0xffffffffu, elv0, o);
        elv1 += __shfl_xor_sync(0xffffffffu, elv1, o);
        erv0 += __shfl_xor_sync(0xffffffffu, erv0, o);
        erv1 += __shfl_xor_sync(0xffffffffu, erv1, o);
    }
    if (jc == 0) {
        if (r0 < M) { g_el[r0] = elv0; g_er[r0] = erv0; }
        if (r1 < M) { g_el[r1] = elv1; g_er[r1] = erv1; }
    }
}

// ---------------- fused softmax-aggregate ------------------------------------
__device__ __forceinline__ float mishf(float x) {
    float sp = fmaxf(x, 0.f) + log1pf(__expf(-fabsf(x)));
    return x * tanhf(sp);
}

__device__ __forceinline__ float lrelu(float e) { return (e > 0.f) ? e : 0.2f * e; }

// lane l owns output columns [8l, 8l+8). One LDG.128 per edge per warp.
// MODE 0: res fp32; MODE 1: res split. Both output split (outh, outl).
template <int MODE>
__global__ __launch_bounds__(256) void k_agg4(
    const __half* __restrict__ feath, const float* __restrict__ resf,
    const __half* __restrict__ resh, const __half* __restrict__ resl,
    const float* __restrict__ bias,
    __half* __restrict__ outh, __half* __restrict__ outl) {
    __shared__ float4 sw[8][32];
    int node = (blockIdx.x * blockDim.x + threadIdx.x) >> 5;
    int lane = threadIdx.x & 31;
    int warp = (threadIdx.x >> 5);
    if (node >= NN) return;
    int start = g_rowptr[node], end = g_rowptr[node + 1];
    float4 er4 = *(const float4*)&g_er[node * 4];
    int h = lane >> 3;
    float acc[8] = {0.f, 0.f, 0.f, 0.f, 0.f, 0.f, 0.f, 0.f};
    float ss0 = 0.f, ss1 = 0.f, ss2 = 0.f, ss3 = 0.f;

    for (int base = start; base < end; base += 32) {
        int i = base + lane;
        int s = 0;
        float w0 = 0.f, w1 = 0.f, w2 = 0.f, w3 = 0.f;
        if (i < end) {
            s = g_csr_src[i];
            float4 el4 = *(const float4*)&g_el[s * 4];
            w0 = __expf(lrelu(el4.x + er4.x));
            w1 = __expf(lrelu(el4.y + er4.y));
            w2 = __expf(lrelu(el4.z + er4.z));
            w3 = __expf(lrelu(el4.w + er4.w));
            ss0 += w0; ss1 += w1; ss2 += w2; ss3 += w3;
        }
        __syncwarp();
        sw[warp][lane] = make_float4(w0, w1, w2, w3);
        __syncwarp();
        int cnt = min(32, end - base);
        const float* swp = (const float*)&sw[warp][0];
        int j = 0;
        for (; j + 1 < cnt; j += 2) {
            int sjA = __shfl_sync(0xffffffffu, s, j);
            int sjB = __shfl_sync(0xffffffffu, s, j + 1);
            uint4 vA = *(const uint4*)(feath + (size_t)sjA * 256 + lane * 8);
            uint4 vB = *(const uint4*)(feath + (size_t)sjB * 256 + lane * 8);
            float wA = swp[j * 4 + h];
            float wB = swp[(j + 1) * 4 + h];
            float2 f0 = __half22float2(*(__half2*)&vA.x);
            float2 f1 = __half22float2(*(__half2*)&vA.y);
            float2 f2 = __half22float2(*(__half2*)&vA.z);
            float2 f3 = __half22float2(*(__half2*)&vA.w);
            acc[0] += wA * f0.x; acc[1] += wA * f0.y;
            acc[2] += wA * f1.x; acc[3] += wA * f1.y;
            acc[4] += wA * f2.x; acc[5] += wA * f2.y;
            acc[6] += wA * f3.x; acc[7] += wA * f3.y;
            f0 = __half22float2(*(__half2*)&vB.x);
            f1 = __half22float2(*(__half2*)&vB.y);
            f2 = __half22float2(*(__half2*)&vB.z);
            f3 = __half22float2(*(__half2*)&vB.w);
            acc[0] += wB * f0.x; acc[1] += wB * f0.y;
            acc[2] += wB * f1.x; acc[3] += wB * f1.y;
            acc[4] += wB * f2.x; acc[5] += wB * f2.y;
            acc[6] += wB * f3.x; acc[7] += wB * f3.y;
        }
        if (j < cnt) {
            int sj = __shfl_sync(0xffffffffu, s, j);
            uint4 v = *(const uint4*)(feath + (size_t)sj * 256 + lane * 8);
            float w = swp[j * 4 + h];
            float2 f0 = __half22float2(*(__half2*)&v.x);
            float2 f1 = __half22float2(*(__half2*)&v.y);
            float2 f2 = __half22float2(*(__half2*)&v.z);
            float2 f3 = __half22float2(*(__half2*)&v.w);
            acc[0] += w * f0.x; acc[1] += w * f0.y;
            acc[2] += w * f1.x; acc[3] += w * f1.y;
            acc[4] += w * f2.x; acc[5] += w * f2.y;
            acc[6] += w * f3.x; acc[7] += w * f3.y;
        }
    }
#pragma unroll
    for (int o = 16; o; o >>= 1) {
        ss0 += __shfl_xor_sync(0xffffffffu, ss0, o);
        ss1 += __shfl_xor_sync(0xffffffffu, ss1, o);
        ss2 += __shfl_xor_sync(0xffffffffu, ss2, o);
        ss3 += __shfl_xor_sync(0xffffffffu, ss3, o);
    }
    bool has = (end > start);
    float inv;
    {
        float sssel = (h == 0) ? ss0 : (h == 1) ? ss1 : (h == 2) ? ss2 : ss3;
        inv = has ? 1.f / sssel : 0.f;
    }

    size_t off = (size_t)node * 256 + lane * 8;
    int bc = lane * 8;
    float o[8];
    if (MODE == 0) {
        float4 r0 = *(const float4*)&resf[off];
        float4 r1 = *(const float4*)&resf[off + 4];
        o[0] = acc[0] * inv + r0.x + bias[bc];
        o[1] = acc[1] * inv + r0.y + bias[bc + 1];
        o[2] = acc[2] * inv + r0.z + bias[bc + 2];
        o[3] = acc[3] * inv + r0.w + bias[bc + 3];
        o[4] = acc[4] * inv + r1.x + bias[bc + 4];
        o[5] = acc[5] * inv + r1.y + bias[bc + 5];
        o[6] = acc[6] * inv + r1.z + bias[bc + 6];
        o[7] = acc[7] * inv + r1.w + bias[bc + 7];
    } else {
        uint4 vh = *(const uint4*)(resh + off);
        uint4 vl = *(const uint4*)(resl + off);
        float2 rh[4], rl[4];
        rh[0] = __half22float2(*(__half2*)&vh.x); rl[0] = __half22float2(*(__half2*)&vl.x);
        rh[1] = __half22float2(*(__half2*)&vh.y); rl[1] = __half22float2(*(__half2*)&vl.y);
        rh[2] = __half22float2(*(__half2*)&vh.z); rl[2] = __half22float2(*(__half2*)&vl.z);
        rh[3] = __half22float2(*(__half2*)&vh.w); rl[3] = __half22float2(*(__half2*)&vl.w);
#pragma unroll
        for (int q = 0; q < 4; q++) {
            o[2 * q]     = acc[2 * q] * inv + rh[q].x + rl[q].x + bias[bc + 2 * q];
            o[2 * q + 1] = acc[2 * q + 1] * inv + rh[q].y + rl[q].y + bias[bc + 2 * q + 1];
        }
    }
#pragma unroll
    for (int q = 0; q < 8; q++) o[q] = mishf(o[q]);
    uint4 vh, vl;
    __half2 hh, ll;
    split2(o[0], o[1], hh, ll); vh.x = *(uint32_t*)&hh; vl.x = *(uint32_t*)&ll;
    split2(o[2], o[3], hh, ll); vh.y = *(uint32_t*)&hh; vl.y = *(uint32_t*)&ll;
    split2(o[4], o[5], hh, ll); vh.z = *(uint32_t*)&hh; vl.z = *(uint32_t*)&ll;
    split2(o[6], o[7], hh, ll); vh.w = *(uint32_t*)&hh; vl.w = *(uint32_t*)&ll;
    *(uint4*)(outh + off) = vh;
    *(uint4*)(outl + off) = vl;
}

// ---------------- softmax-aggregate layer2, H=1 D=16 -------------------------
__global__ __launch_bounds__(256) void k_agg2(
    const float* __restrict__ feat, const float* __restrict__ res,
    const float* __restrict__ bias, float* __restrict__ out) {
    int node = (blockIdx.x * blockDim.x + threadIdx.x) >> 5;
    int lane = threadIdx.x & 31;
    if (node >= NN) return;
    int start = g_rowptr[node], end = g_rowptr[node + 1];
    float er_n = g_er[node];

    float acc = 0.f, ss = 0.f;
    for (int base = start; base < end; base += 32) {
        int i = base + lane;
        int s = 0;
        float w = 0.f;
        if (i < end) {
            s = g_csr_src[i];
            w = __expf(lrelu(g_el[s] + er_n));
            ss += w;
        }
        int cnt = min(32, end - base);
        for (int j = 0; j < cnt; j++) {
            int   sj = __shfl_sync(0xffffffffu, s, j);
            float bw = __shfl_sync(0xffffffffu, w, j);
            if (lane < 16) acc += bw * feat[(size_t)sj * 16 + lane];
        }
    }
#pragma unroll
    for (int o = 16; o; o >>= 1) ss += __shfl_xor_sync(0xffffffffu, ss, o);
    float inv = (end > start) ? 1.f / ss : 0.f;
    if (lane < 16)
        out[(size_t)node * 16 + lane] = acc * inv + res[(size_t)node * 16 + lane] + bias[lane];
}

// ---------------- launch -----------------------------------------------------
extern "C" void kernel_launch(void* const* d_in, const int* in_sizes, int n_in,
                              void* d_out, int out_size) {
    const float* x    = (const float*)d_in[0];
    const int*   src  = (const int*)d_in[1];
    const int*   dst  = (const int*)d_in[2];
    const float* W0   = (const float*)d_in[3];
    const float* al0  = (const float*)d_in[4];
    const float* ar0  = (const float*)d_in[5];
    const float* b0   = (const float*)d_in[6];
    const float* W1   = (const float*)d_in[7];
    const float* al1  = (const float*)d_in[8];
    const float* ar1  = (const float*)d_in[9];
    const float* b1   = (const float*)d_in[10];
    const float* W2   = (const float*)d_in[11];
    const float* al2  = (const float*)d_in[12];
    const float* ar2  = (const float*)d_in[13];
    const float* b2   = (const float*)d_in[14];
    const float* rW2  = (const float*)d_in[15];
    float* out = (float*)d_out;

    __half *feath, *xh, *xl, *h1h, *h1l;
    float *feat2, *res2;
    __half2 *w0h, *w1h, *w2h, *w2l;
    void* degp;
    cudaGetSymbolAddress((void**)&feath, g_feat_h);
    cudaGetSymbolAddress((void**)&xh, g_xh);
    cudaGetSymbolAddress((void**)&xl, g_xl);
    cudaGetSymbolAddress((void**)&h1h, g_h1h);
    cudaGetSymbolAddress((void**)&h1l, g_h1l);
    cudaGetSymbolAddress((void**)&feat2, g_feat2);
    cudaGetSymbolAddress((void**)&res2, g_res2);
    cudaGetSymbolAddress((void**)&w0h, g_w0h);
    cudaGetSymbolAddress((void**)&w1h, g_w1h);
    cudaGetSymbolAddress((void**)&w2h, g_w2h);
    cudaGetSymbolAddress((void**)&w2l, g_w2l);
    cudaGetSymbolAddress(&degp, g_deg);

    // fork a side stream for the CSR build
    cudaStream_t s2 = 0;
    cudaEvent_t evF = 0, evJ = 0;
    bool forked = (cudaStreamCreateWithFlags(&s2, cudaStreamNonBlocking) == cudaSuccess) &&
                  (cudaEventCreateWithFlags(&evF, cudaEventDisableTiming) == cudaSuccess) &&
                  (cudaEventCreateWithFlags(&evJ, cudaEventDisableTiming) == cudaSuccess);
    cudaStream_t sc = forked ? s2 : 0;

    if (forked) {
        cudaEventRecord(evF, 0);
        cudaStreamWaitEvent(s2, evF, 0);
    }
    cudaMemsetAsync(degp, 0, NN * sizeof(int), sc);
    k_hist<<<(NE + 255) / 256, 256, 0, sc>>>(dst);
    k_scan<<<1, 1024, 0, sc>>>();
    k_scatter<<<(NE + 255) / 256, 256, 0, sc>>>(src, dst);
    if (forked) cudaEventRecord(evJ, s2);

    // main stream: presplit + layer0 GEMM
    k_presplitW<<<(128 * 256 + 255) / 256, 256>>>(W0, w0h);
    k_presplitW<<<(128 * 256 + 255) / 256, 256>>>(W1, w1h);
    k_presplitW2<<<(128 * 32 + 255) / 256, 256>>>(W2, rW2, w2h, w2l);
    k_presplit<<<(NN * 64 + 255) / 256, 256>>>((const float4*)x, (uint2*)xh, (uint2*)xl, NN * 64);

    dim3 gtc(4, (NN + 127) / 128);
    int aggBlocks = (NN * 32 + 255) / 256;

    k_gemm_tc<<<gtc, 256>>>(xh, xl, w0h, feath, al0, ar0, NN);

    if (forked) cudaStreamWaitEvent(0, evJ, 0);

    // layer 0 aggregate: res = x fp32, out -> split h1
    k_agg4<0><<<aggBlocks, 256>>>(feath, x, nullptr, nullptr, b0, h1h, h1l);

    // layer 1: GEMM + aggregate -> split h2 (reuses xh/xl)
    k_gemm_tc<<<gtc, 256>>>(h1h, h1l, w1h, feath, al1, ar1, NN);
    k_agg4<1><<<aggBlocks, 256>>>(feath, nullptr, h1h, h1l, b1, xh, xl);

    // layer 2: tensor-core dual GEMM (+el/er) + aggregate
    k_gemm16_tc<<<(NN + 127) / 128, 256>>>(xh, xl, w2h, w2l, feat2, res2, al2, ar2, NN);
    k_agg2<<<aggBlocks, 256>>>(feat2, res2, b2, out);
}

// round 12
// speedup vs baseline: 3.5494x; 1.1199x over previous
#include <cuda_runtime.h>
#include <cuda_fp16.h>
#include <math.h>
#include <stdint.h>

#define NN 50000
#define NE 800000

// ---------------- scratch ----------------------------------------------------
__device__ __align__(16) __half g_feat_h[NN * 256]; // GEMM output (fp16) for gathers
__device__ __align__(16) __half g_xh[NN * 256];     // presplit x hi; later h2 hi
__device__ __align__(16) __half g_xl[NN * 256];     // presplit x lo; later h2 lo
__device__ __align__(16) __half g_h1h[NN * 256];    // layer0 out hi
__device__ __align__(16) __half g_h1l[NN * 256];    // layer0 out lo
__device__ __align__(16) float  g_feat2[NN * 16];
__device__ __align__(16) float  g_res2[NN * 16];
__device__ __align__(16) __half2 g_w0h[128 * 256];  // W packed k-pairs (hi only)
__device__ __align__(16) __half2 g_w1h[128 * 256];
__device__ __align__(16) __half2 g_w2h[128 * 32];   // [W2|rW2] packed hi
__device__ __align__(16) __half2 g_w2l[128 * 32];   // [W2|rW2] packed lo
__device__ __align__(16) float g_el[NN * 4];
__device__ __align__(16) float g_er[NN * 4];
__device__ int g_deg[NN];
__device__ int g_rowptr[NN + 1];
__device__ int g_pos[NN];
__device__ int g_csr_src[NE];

// ---------------- CSR build --------------------------------------------------
__global__ void k_hist(const int* __restrict__ dst) {
    int e = blockIdx.x * blockDim.x + threadIdx.x;
    if (e < NE) atomicAdd(&g_deg[dst[e]], 1);
}

__global__ void k_scan() {
    __shared__ int warp_pref[32];
    const int T = 1024;
    int t = threadIdx.x;
    const int per = (NN + T - 1) / T;
    int begin = t * per;
    int end = min(begin + per, NN);
    if (begin > NN) begin = NN;
    if (end < begin) end = begin;

    int sum = 0;
    for (int i = begin; i < end; i++) sum += g_deg[i];

    int lane = t & 31, wid = t >> 5;
    int v = sum;
#pragma unroll
    for (int o = 1; o < 32; o <<= 1) {
        int u = __shfl_up_sync(0xffffffffu, v, o);
        if (lane >= o) v += u;
    }
    if (lane == 31) warp_pref[wid] = v;
    __syncthreads();
    if (wid == 0) {
        int w = warp_pref[lane];
#pragma unroll
        for (int o = 1; o < 32; o <<= 1) {
            int u = __shfl_up_sync(0xffffffffu, w, o);
            if (lane >= o) w += u;
        }
        warp_pref[lane] = w;
    }
    __syncthreads();
    int excl = v - sum + (wid ? warp_pref[wid - 1] : 0);

    int run = excl;
    for (int i = begin; i < end; i++) {
        g_rowptr[i] = run;
        g_pos[i] = run;
        run += g_deg[i];
    }
    if (t == T - 1) g_rowptr[NN] = run;
}

__global__ void k_scatter(const int* __restrict__ src, const int* __restrict__ dst) {
    int e = blockIdx.x * blockDim.x + threadIdx.x;
    if (e < NE) {
        int p = atomicAdd(&g_pos[dst[e]], 1);
        g_csr_src[p] = src[e];
    }
}

// ---------------- presplit helpers -------------------------------------------
__device__ __forceinline__ void split2(float x, float y, __half2& hi, __half2& lo) {
    __half hx = __float2half_rn(x), hy = __float2half_rn(y);
    hi = __halves2half2(hx, hy);
    lo = __floats2half2_rn(x - __half2float(hx), y - __half2float(hy));
}

__global__ void k_presplit(const float4* __restrict__ A, uint2* __restrict__ H,
                           uint2* __restrict__ L, int n4) {
    int i = blockIdx.x * blockDim.x + threadIdx.x;
    if (i >= n4) return;
    float4 v = A[i];
    __half2 h0, l0, h1, l1;
    split2(v.x, v.y, h0, l0);
    split2(v.z, v.w, h1, l1);
    H[i] = make_uint2(*(uint32_t*)&h0, *(uint32_t*)&h1);
    L[i] = make_uint2(*(uint32_t*)&l0, *(uint32_t*)&l1);
}

// both W0 and W1 in one launch
__global__ void k_presplitW(const float* __restrict__ W0, const float* __restrict__ W1,
                            __half2* __restrict__ P0, __half2* __restrict__ P1) {
    int idx = blockIdx.x * blockDim.x + threadIdx.x;
    if (idx >= 2 * 128 * 256) return;
    const float* W = (idx < 128 * 256) ? W0 : W1;
    __half2* P = (idx < 128 * 256) ? P0 : P1;
    int li = idx & (128 * 256 - 1);
    int kp = li >> 8, n = li & 255;
    float a = W[(2 * kp) * 256 + n];
    float b = W[(2 * kp + 1) * 256 + n];
    P[li] = __halves2half2(__float2half_rn(a), __float2half_rn(b));
}

// [W2|rW2] (256x16 each) -> packed k-pair [128][32], hi+lo
__global__ void k_presplitW2(const float* __restrict__ W2, const float* __restrict__ rW2,
                             __half2* __restrict__ Ph, __half2* __restrict__ Pl) {
    int idx = blockIdx.x * blockDim.x + threadIdx.x;
    if (idx >= 128 * 32) return;
    int kp = idx >> 5, n = idx & 31;
    float a, b;
    if (n < 16) { a = W2[(2 * kp) * 16 + n];      b = W2[(2 * kp + 1) * 16 + n]; }
    else        { a = rW2[(2 * kp) * 16 + n - 16]; b = rW2[(2 * kp + 1) * 16 + n - 16]; }
    __half2 h, l;
    split2(a, b, h, l);
    Ph[idx] = h;
    Pl[idx] = l;
}

// ---------------- MMA / copy primitives --------------------------------------
__device__ __forceinline__ void mma16(float* d, const uint32_t* a, const uint32_t* b) {
    asm volatile(
        "mma.sync.aligned.m16n8k16.row.col.f32.f16.f16.f32 "
        "{%0,%1,%2,%3}, {%4,%5,%6,%7}, {%8,%9}, {%0,%1,%2,%3};\n"
        : "+f"(d[0]), "+f"(d[1]), "+f"(d[2]), "+f"(d[3])
        : "r"(a[0]), "r"(a[1]), "r"(a[2]), "r"(a[3]), "r"(b[0]), "r"(b[1]));
}

#define LDSM4(r0, r1, r2, r3, addr)                                           \
    asm volatile("ldmatrix.sync.aligned.m8n8.x4.shared.b16 {%0,%1,%2,%3}, [%4];" \
                 : "=r"(r0), "=r"(r1), "=r"(r2), "=r"(r3) : "r"(addr))

#define CP16(dst, src, n)                                                     \
    asm volatile("cp.async.cg.shared.global [%0], [%1], 16, %2;\n"            \
                 :: "r"(dst), "l"(src), "r"(n))
#define CPCOMMIT() asm volatile("cp.async.commit_group;\n" ::: "memory")
#define CPWAIT0()  asm volatile("cp.async.wait_group 0;\n" ::: "memory")

// ---------------- big GEMM: BK=32, XOR-swizzled A rows, 2-term ---------------
// A smem row: 64B = 32 halves (one 32-k chunk), 16B chunks XOR-swizzled:
//   unit(row, c) = c ^ ((row>>1)&3)  -> conflict-free ldmatrix & full chunk perm
#define AG_ROWB 64
#define AG_STAGEB (128 * AG_ROWB)
#define BG_ROWB 288        // 64 half2 data + 8 pad
#define BG_STAGEB (16 * BG_ROWB)

__global__ __launch_bounds__(256, 2) void k_gemm_tc(
    const __half* __restrict__ Axh, const __half* __restrict__ Axl,
    const __half2* __restrict__ Wph,
    __half* __restrict__ Ch, const float* __restrict__ pal,
    const float* __restrict__ pare, int M) {
    const int K = 256, N = 256;
    __shared__ __half2 Ah[2][128][16];   // 64B rows
    __shared__ __half2 Al[2][128][16];
    __shared__ __half2 Bh[2][16][72];
    __shared__ float s_el[2][128];
    __shared__ float s_er[2][128];

    int tid = threadIdx.x;
    int lane = tid & 31;
    int wid = tid >> 5;
    int warp_n = wid & 1;
    int m_base = (wid >> 1) * 32;
    int n_base = warp_n * 32;
    int row0 = blockIdx.y * 128;
    int col0 = blockIdx.x * 64;
    int head = col0 >> 6;

    float acc[2][4][4];
#pragma unroll
    for (int mt = 0; mt < 2; mt++)
#pragma unroll
        for (int nt = 0; nt < 4; nt++)
#pragma unroll
            for (int i = 0; i < 4; i++) acc[mt][nt][i] = 0.f;

    // A staging: 512 chunks of 16B per buffer; thread t takes chunks t, t+256
    int arow0 = tid >> 2, ac0 = tid & 3;          // chunk t
    int arow1 = (tid + 256) >> 2, ac1 = tid & 3;  // chunk t+256 (same c bits)
    int gr0 = row0 + arow0, gr1 = row0 + arow1;
    int aok0 = (gr0 < M) ? 16 : 0, aok1 = (gr1 < M) ? 16 : 0;
    int grc0 = min(gr0, M - 1), grc1 = min(gr1, M - 1);
    uint32_t adst0 = arow0 * AG_ROWB + (ac0 ^ ((arow0 >> 1) & 3)) * 16;
    uint32_t adst1 = arow1 * AG_ROWB + (ac1 ^ ((arow1 >> 1) & 3)) * 16;
    // B staging: 256 chunks; thread t: row t>>4 (0..15), chunk t&15
    int brow = tid >> 4, bchk = tid & 15;

    uint32_t ah_b = (uint32_t)__cvta_generic_to_shared(&Ah[0][0][0]);
    uint32_t al_b = (uint32_t)__cvta_generic_to_shared(&Al[0][0][0]);
    uint32_t bh_b = (uint32_t)__cvta_generic_to_shared(&Bh[0][0][0]);
    uint32_t b_dst = bh_b + brow * BG_ROWB + bchk * 16;

    int jq = lane >> 2;
    int jc = lane & 3;
    // ldmatrix lane row (within 16-row matrix group) and 16B-unit base
    int lrow = (lane & 7) + ((lane >> 3) & 1) * 8;  // 0..15
    int lu = lane >> 4;                              // 0..1

    auto stageA = [&](int st, int k0) {
        const __half* s0h = Axh + (size_t)grc0 * K + k0 + ac0 * 8;
        const __half* s0l = Axl + (size_t)grc0 * K + k0 + ac0 * 8;
        const __half* s1h = Axh + (size_t)grc1 * K + k0 + ac1 * 8;
        const __half* s1l = Axl + (size_t)grc1 * K + k0 + ac1 * 8;
        uint32_t so = st ? AG_STAGEB : 0;
        CP16(ah_b + so + adst0, s0h, aok0);
        CP16(al_b + so + adst0, s0l, aok0);
        CP16(ah_b + so + adst1, s1h, aok1);
        CP16(al_b + so + adst1, s1l, aok1);
    };
    auto stageB = [&](int st, int k0) {
        uint32_t so = st ? BG_STAGEB : 0;
        CP16(b_dst + so, Wph + ((size_t)(k0 >> 1) + brow) * N + col0 + bchk * 4, 16);
    };

    stageA(0, 0);
    stageB(0, 0);
    CPCOMMIT();

    const int NS = K / 32;   // 8
    for (int s = 0; s < NS; s++) {
        int cur = s & 1;
        CPWAIT0();
        __syncthreads();
        if (s + 1 < NS) {
            int k0 = (s + 1) * 32;
            stageA(cur ^ 1, k0);
            stageB(cur ^ 1, k0);
            CPCOMMIT();
        }

        uint32_t a_st = cur ? AG_STAGEB : 0;
#pragma unroll
        for (int sub = 0; sub < 2; sub++) {
            uint32_t ah[2][4], al_[2][4];
#pragma unroll
            for (int mt = 0; mt < 2; mt++) {
                int r = m_base + mt * 16 + lrow;
                uint32_t unit = (uint32_t)((lu + sub * 2) ^ ((r >> 1) & 3));
                uint32_t off = a_st + (uint32_t)r * AG_ROWB + unit * 16;
                LDSM4(ah[mt][0], ah[mt][1], ah[mt][2], ah[mt][3], ah_b + off);
                LDSM4(al_[mt][0], al_[mt][1], al_[mt][2], al_[mt][3], al_b + off);
            }
            uint32_t bh[4][2];
#pragma unroll
            for (int nt = 0; nt < 4; nt++) {
                int n = n_base + nt * 8 + jq;
                bh[nt][0] = *(const uint32_t*)&Bh[cur][sub * 8 + jc][n];
                bh[nt][1] = *(const uint32_t*)&Bh[cur][sub * 8 + jc + 4][n];
            }
#pragma unroll
            for (int mt = 0; mt < 2; mt++)
#pragma unroll
                for (int nt = 0; nt < 4; nt++) {
                    mma16(acc[mt][nt], ah[mt], bh[nt]);
                    mma16(acc[mt][nt], al_[mt], bh[nt]);
                }
        }
    }

    // ---- fp16 feature store + fused el/er ------------------------------------
    float elv[4] = {0.f, 0.f, 0.f, 0.f}, erv[4] = {0.f, 0.f, 0.f, 0.f};
#pragma unroll
    for (int mt = 0; mt < 2; mt++)
#pragma unroll
        for (int nt = 0; nt < 4; nt++) {
            int r = row0 + m_base + mt * 16 + jq;
            int cl = n_base + nt * 8 + 2 * jc;
            int c = col0 + cl;
            if (r < M)
                *(__half2*)&Ch[(size_t)r * N + c] =
                    __floats2half2_rn(acc[mt][nt][0], acc[mt][nt][1]);
            if (r + 8 < M)
                *(__half2*)&Ch[(size_t)(r + 8) * N + c] =
                    __floats2half2_rn(acc[mt][nt][2], acc[mt][nt][3]);
            float w0 = pal[c], w1 = pal[c + 1];
            float u0 = pare[c], u1 = pare[c + 1];
            elv[mt * 2]     += acc[mt][nt][0] * w0 + acc[mt][nt][1] * w1;
            elv[mt * 2 + 1] += acc[mt][nt][2] * w0 + acc[mt][nt][3] * w1;
            erv[mt * 2]     += acc[mt][nt][0] * u0 + acc[mt][nt][1] * u1;
            erv[mt * 2 + 1] += acc[mt][nt][2] * u0 + acc[mt][nt][3] * u1;
        }
#pragma unroll
    for (int o = 1; o <= 2; o <<= 1) {
#pragma unroll
        for (int i = 0; i < 4; i++) {
            elv[i] += __shfl_xor_sync(0xffffffffu, elv[i], o);
            erv[i] += __shfl_xor_sync(0xffffffffu, erv[i], o);
        }
    }
    if (jc == 0) {
#pragma unroll
        for (int i = 0; i < 4; i++) {
            int lr = m_base + (i >> 1) * 16 + (i & 1) * 8 + jq;
            s_el[warp_n][lr] = elv[i];
            s_er[warp_n][lr] = erv[i];
        }
    }
    __syncthreads();
    if (tid < 128) {
        int r = row0 + tid;
        if (r < M) {
            g_el[r * 4 + head] = s_el[0][tid] + s_el[1][tid];
            g_er[r * 4 + head] = s_er[0][tid] + s_er[1][tid];
        }
    }
}

// ---------------- layer-2 GEMM (BK=16 path, verified in R11) -----------------
#define A_ROWB 48
#define A_STAGEB (128 * A_ROWB)
#define B2_ROWB 160
#define B2_STAGEB (8 * B2_ROWB)

__global__ __launch_bounds__(256, 2) void k_gemm16_tc(
    const __half* __restrict__ Axh, const __half* __restrict__ Axl,
    const __half2* __restrict__ Wph, const __half2* __restrict__ Wpl,
    float* __restrict__ feat2, float* __restrict__ res2,
    const float* __restrict__ al2, const float* __restrict__ ar2, int M) {
    const int K = 256;
    __shared__ __half2 Ah[2][128][12];
    __shared__ __half2 Al[2][128][12];
    __shared__ __half2 Bh[2][8][40];
    __shared__ __half2 Bl[2][8][40];

    int tid = threadIdx.x;
    int lane = tid & 31;
    int wid = tid >> 5;
    int m_base = wid * 16;
    int row0 = blockIdx.x * 128;

    float acc[4][4];
#pragma unroll
    for (int nt = 0; nt < 4; nt++)
#pragma unroll
        for (int i = 0; i < 4; i++) acc[nt][i] = 0.f;

    int ar = tid >> 1;
    int acq = (tid & 1);
    int gr = row0 + ar;
    int aok = (gr < M) ? 16 : 0;
    int grc = min(gr, M - 1);
    int t2 = tid & 63;
    int kp = t2 >> 3;
    int chk = t2 & 7;
    bool isB = tid < 128;
    bool isHi = tid < 64;

    uint32_t ah_b = (uint32_t)__cvta_generic_to_shared(&Ah[0][0][0]);
    uint32_t al_b = (uint32_t)__cvta_generic_to_shared(&Al[0][0][0]);
    uint32_t bh_b = (uint32_t)__cvta_generic_to_shared(&Bh[0][0][0]);
    uint32_t bl_b = (uint32_t)__cvta_generic_to_shared(&Bl[0][0][0]);
    uint32_t a_dst = ar * A_ROWB + acq * 16;
    uint32_t b_dst = (isHi ? bh_b : bl_b) + kp * B2_ROWB + chk * 16;
    const __half2* Wsrc = isHi ? Wph : Wpl;

    uint32_t lm_off = (uint32_t)(m_base + (lane & 7) + ((lane >> 3) & 1) * 8) * A_ROWB
                      + (lane >> 4) * 16;

    int jq = lane >> 2;
    int jc = lane & 3;

    {
        const __half* sa = Axh + (size_t)grc * K + acq * 8;
        const __half* sl = Axl + (size_t)grc * K + acq * 8;
        CP16(ah_b + a_dst, sa, aok);
        CP16(al_b + a_dst, sl, aok);
        if (isB) CP16(b_dst, Wsrc + (size_t)kp * 32 + chk * 4, 16);
        CPCOMMIT();
    }

    const int NS = K / 16;
    for (int s = 0; s < NS; s++) {
        int cur = s & 1;
        CPWAIT0();
        __syncthreads();
        if (s + 1 < NS) {
            int k0 = (s + 1) * 16;
            uint32_t stoff = (cur ^ 1) ? A_STAGEB : 0;
            const __half* sa = Axh + (size_t)grc * K + k0 + acq * 8;
            const __half* sl = Axl + (size_t)grc * K + k0 + acq * 8;
            CP16(ah_b + stoff + a_dst, sa, aok);
            CP16(al_b + stoff + a_dst, sl, aok);
            uint32_t bst = (cur ^ 1) ? B2_STAGEB : 0;
            if (isB) CP16(b_dst + bst, Wsrc + ((size_t)(k0 >> 1) + kp) * 32 + chk * 4, 16);
            CPCOMMIT();
        }

        uint32_t ah[4], al_[4];
        uint32_t a_st = cur ? A_STAGEB : 0;
        LDSM4(ah[0], ah[1], ah[2], ah[3], ah_b + a_st + lm_off);
        LDSM4(al_[0], al_[1], al_[2], al_[3], al_b + a_st + lm_off);
        uint32_t bh[4][2], bl[4][2];
#pragma unroll
        for (int nt = 0; nt < 4; nt++) {
            int n = nt * 8 + jq;
            bh[nt][0] = *(const uint32_t*)&Bh[cur][jc][n];
            bh[nt][1] = *(const uint32_t*)&Bh[cur][jc + 4][n];
            bl[nt][0] = *(const uint32_t*)&Bl[cur][jc][n];
            bl[nt][1] = *(const uint32_t*)&Bl[cur][jc + 4][n];
        }
#pragma unroll
        for (int nt = 0; nt < 4; nt++) {
            mma16(acc[nt], ah, bh[nt]);
            mma16(acc[nt], al_, bh[nt]);
            mma16(acc[nt], ah, bl[nt]);
        }
    }

    int r0 = row0 + m_base + jq;
    int r1 = r0 + 8;
    float elv0 = 0.f, elv1 = 0.f, erv0 = 0.f, erv1 = 0.f;
#pragma unroll
    for (int nt = 0; nt < 4; nt++) {
        int c = nt * 8 + 2 * jc;
        if (nt < 2) {
            if (r0 < M) *(float2*)&feat2[(size_t)r0 * 16 + c] = make_float2(acc[nt][0], acc[nt][1]);
            if (r1 < M) *(float2*)&feat2[(size_t)r1 * 16 + c] = make_float2(acc[nt][2], acc[nt][3]);
            float w0 = al2[c], w1 = al2[c + 1];
            float u0 = ar2[c], u1 = ar2[c + 1];
            elv0 += acc[nt][0] * w0 + acc[nt][1] * w1;
            elv1 += acc[nt][2] * w0 + acc[nt][3] * w1;
            erv0 += acc[nt][0] * u0 + acc[nt][1] * u1;
            erv1 += acc[nt][2] * u0 + acc[nt][3] * u1;
        } else {
            int cc = c - 16;
            if (r0 < M) *(float2*)&res2[(size_t)r0 * 16 + cc] = make_float2(acc[nt][0], acc[nt][1]);
            if (r1 < M) *(float2*)&res2[(size_t)r1 * 16 + cc] = make_float2(acc[nt][2], acc[nt][3]);
        }
    }
#pragma unroll
    for (int o = 1; o <= 2; o <<= 1) {
        elv0 += __shfl_xor_sync(0xffffffffu, elv0, o);
        elv1 += __shfl_xor_sync(0xffffffffu, elv1, o);
        erv0 += __shfl_xor_sync(0xffffffffu, erv0, o);
        erv1 += __shfl_xor_sync(0xffffffffu, erv1, o);
    }
    if (jc == 0) {
        if (r0 < M) { g_el[r0] = elv0; g_er[r0] = erv0; }
        if (r1 < M) { g_el[r1] = elv1; g_er[r1] = erv1; }
    }
}

// ---------------- fused softmax-aggregate ------------------------------------
__device__ __forceinline__ float mishf(float x) {
    float sp = fmaxf(x, 0.f) + log1pf(__expf(-fabsf(x)));
    return x * tanhf(sp);
}

__device__ __forceinline__ float lrelu(float e) { return (e > 0.f) ? e : 0.2f * e; }

// lane l owns output columns [8l, 8l+8). One LDG.128 per edge per warp.
template <int MODE>
__global__ __launch_bounds__(256) void k_agg4(
    const __half* __restrict__ feath, const float* __restrict__ resf,
    const __half* __restrict__ resh, const __half* __restrict__ resl,
    const float* __restrict__ bias,
    __half* __restrict__ outh, __half* __restrict__ outl) {
    __shared__ float4 sw[8][32];
    int node = (blockIdx.x * blockDim.x + threadIdx.x) >> 5;
    int lane = threadIdx.x & 31;
    int warp = (threadIdx.x >> 5);
    if (node >= NN) return;
    int start = g_rowptr[node], end = g_rowptr[node + 1];
    float4 er4 = *(const float4*)&g_er[node * 4];
    int h = lane >> 3;
    float acc[8] = {0.f, 0.f, 0.f, 0.f, 0.f, 0.f, 0.f, 0.f};
    float ss0 = 0.f, ss1 = 0.f, ss2 = 0.f, ss3 = 0.f;

    for (int base = start; base < end; base += 32) {
        int i = base + lane;
        int s = 0;
        float w0 = 0.f, w1 = 0.f, w2 = 0.f, w3 = 0.f;
        if (i < end) {
            s = g_csr_src[i];
            float4 el4 = *(const float4*)&g_el[s * 4];
            w0 = __expf(lrelu(el4.x + er4.x));
            w1 = __expf(lrelu(el4.y + er4.y));
            w2 = __expf(lrelu(el4.z + er4.z));
            w3 = __expf(lrelu(el4.w + er4.w));
            ss0 += w0; ss1 += w1; ss2 += w2; ss3 += w3;
        }
        __syncwarp();
        sw[warp][lane] = make_float4(w0, w1, w2, w3);
        __syncwarp();
        int cnt = min(32, end - base);
        const float* swp = (const float*)&sw[warp][0];
        int j = 0;
        for (; j + 1 < cnt; j += 2) {
            int sjA = __shfl_sync(0xffffffffu, s, j);
            int sjB = __shfl_sync(0xffffffffu, s, j + 1);
            uint4 vA = *(const uint4*)(feath + (size_t)sjA * 256 + lane * 8);
            uint4 vB = *(const uint4*)(feath + (size_t)sjB * 256 + lane * 8);
            float wA = swp[j * 4 + h];
            float wB = swp[(j + 1) * 4 + h];
            float2 f0 = __half22float2(*(__half2*)&vA.x);
            float2 f1 = __half22float2(*(__half2*)&vA.y);
            float2 f2 = __half22float2(*(__half2*)&vA.z);
            float2 f3 = __half22float2(*(__half2*)&vA.w);
            acc[0] += wA * f0.x; acc[1] += wA * f0.y;
            acc[2] += wA * f1.x; acc[3] += wA * f1.y;
            acc[4] += wA * f2.x; acc[5] += wA * f2.y;
            acc[6] += wA * f3.x; acc[7] += wA * f3.y;
            f0 = __half22float2(*(__half2*)&vB.x);
            f1 = __half22float2(*(__half2*)&vB.y);
            f2 = __half22float2(*(__half2*)&vB.z);
            f3 = __half22float2(*(__half2*)&vB.w);
            acc[0] += wB * f0.x; acc[1] += wB * f0.y;
            acc[2] += wB * f1.x; acc[3] += wB * f1.y;
            acc[4] += wB * f2.x; acc[5] += wB * f2.y;
            acc[6] += wB * f3.x; acc[7] += wB * f3.y;
        }
        if (j < cnt) {
            int sj = __shfl_sync(0xffffffffu, s, j);
            uint4 v = *(const uint4*)(feath + (size_t)sj * 256 + lane * 8);
            float w = swp[j * 4 + h];
            float2 f0 = __half22float2(*(__half2*)&v.x);
            float2 f1 = __half22float2(*(__half2*)&v.y);
            float2 f2 = __half22float2(*(__half2*)&v.z);
            float2 f3 = __half22float2(*(__half2*)&v.w);
            acc[0] += w * f0.x; acc[1] += w * f0.y;
            acc[2] += w * f1.x; acc[3] += w * f1.y;
            acc[4] += w * f2.x; acc[5] += w * f2.y;
            acc[6] += w * f3.x; acc[7] += w * f3.y;
        }
    }
#pragma unroll
    for (int o = 16; o; o >>= 1) {
        ss0 += __shfl_xor_sync(0xffffffffu, ss0, o);
        ss1 += __shfl_xor_sync(0xffffffffu, ss1, o);
        ss2 += __shfl_xor_sync(0xffffffffu, ss2, o);
        ss3 += __shfl_xor_sync(0xffffffffu, ss3, o);
    }
    bool has = (end > start);
    float inv;
    {
        float sssel = (h == 0) ? ss0 : (h == 1) ? ss1 : (h == 2) ? ss2 : ss3;
        inv = has ? 1.f / sssel : 0.f;
    }

    size_t off = (size_t)node * 256 + lane * 8;
    int bc = lane * 8;
    float o[8];
    if (MODE == 0) {
        float4 r0 = *(const float4*)&resf[off];
        float4 r1 = *(const float4*)&resf[off + 4];
        o[0] = acc[0] * inv + r0.x + bias[bc];
        o[1] = acc[1] * inv + r0.y + bias[bc + 1];
        o[2] = acc[2] * inv + r0.z + bias[bc + 2];
        o[3] = acc[3] * inv + r0.w + bias[bc + 3];
        o[4] = acc[4] * inv + r1.x + bias[bc + 4];
        o[5] = acc[5] * inv + r1.y + bias[bc + 5];
        o[6] = acc[6] * inv + r1.z + bias[bc + 6];
        o[7] = acc[7] * inv + r1.w + bias[bc + 7];
    } else {
        uint4 vh = *(const uint4*)(resh + off);
        uint4 vl = *(const uint4*)(resl + off);
        float2 rh[4], rl[4];
        rh[0] = __half22float2(*(__half2*)&vh.x); rl[0] = __half22float2(*(__half2*)&vl.x);
        rh[1] = __half22float2(*(__half2*)&vh.y); rl[1] = __half22float2(*(__half2*)&vl.y);
        rh[2] = __half22float2(*(__half2*)&vh.z); rl[2] = __half22float2(*(__half2*)&vl.z);
        rh[3] = __half22float2(*(__half2*)&vh.w); rl[3] = __half22float2(*(__half2*)&vl.w);
#pragma unroll
        for (int q = 0; q < 4; q++) {
            o[2 * q]     = acc[2 * q] * inv + rh[q].x + rl[q].x + bias[bc + 2 * q];
            o[2 * q + 1] = acc[2 * q + 1] * inv + rh[q].y + rl[q].y + bias[bc + 2 * q + 1];
        }
    }
#pragma unroll
    for (int q = 0; q < 8; q++) o[q] = mishf(o[q]);
    uint4 vh, vl;
    __half2 hh, ll;
    split2(o[0], o[1], hh, ll); vh.x = *(uint32_t*)&hh; vl.x = *(uint32_t*)&ll;
    split2(o[2], o[3], hh, ll); vh.y = *(uint32_t*)&hh; vl.y = *(uint32_t*)&ll;
    split2(o[4], o[5], hh, ll); vh.z = *(uint32_t*)&hh; vl.z = *(uint32_t*)&ll;
    split2(o[6], o[7], hh, ll); vh.w = *(uint32_t*)&hh; vl.w = *(uint32_t*)&ll;
    *(uint4*)(outh + off) = vh;
    *(uint4*)(outl + off) = vl;
}

// ---------------- softmax-aggregate layer2: 2 edges/iter (half-warp split) ---
__global__ __launch_bounds__(256) void k_agg2(
    const float* __restrict__ feat, const float* __restrict__ res,
    const float* __restrict__ bias, float* __restrict__ out) {
    int node = (blockIdx.x * blockDim.x + threadIdx.x) >> 5;
    int lane = threadIdx.x & 31;
    if (node >= NN) return;
    int start = g_rowptr[node], end = g_rowptr[node + 1];
    float er_n = g_er[node];
    int half = lane >> 4;
    int sub = lane & 15;

    float acc = 0.f, ss = 0.f;
    for (int base = start; base < end; base += 32) {
        int i = base + lane;
        int s = 0;
        float w = 0.f;
        if (i < end) {
            s = g_csr_src[i];
            w = __expf(lrelu(g_el[s] + er_n));
            ss += w;
        }
        int cnt = min(32, end - base);
        int j = 0;
        for (; j + 1 < cnt; j += 2) {
            int   sj = __shfl_sync(0xffffffffu, s, j + half);
            float bw = __shfl_sync(0xffffffffu, w, j + half);
            acc += bw * feat[(size_t)sj * 16 + sub];
        }
        if (j < cnt) {
            int   sj = __shfl_sync(0xffffffffu, s, j);
            float bw = __shfl_sync(0xffffffffu, w, j);
            if (half == 0) acc += bw * feat[(size_t)sj * 16 + sub];
        }
    }
#pragma unroll
    for (int o = 16; o; o >>= 1) ss += __shfl_xor_sync(0xffffffffu, ss, o);
    acc += __shfl_xor_sync(0xffffffffu, acc, 16);
    float inv = (end > start) ? 1.f / ss : 0.f;
    if (lane < 16)
        out[(size_t)node * 16 + lane] = acc * inv + res[(size_t)node * 16 + lane] + bias[lane];
}

// ---------------- launch -----------------------------------------------------
extern "C" void kernel_launch(void* const* d_in, const int* in_sizes, int n_in,
                              void* d_out, int out_size) {
    const float* x    = (const float*)d_in[0];
    const int*   src  = (const int*)d_in[1];
    const int*   dst  = (const int*)d_in[2];
    const float* W0   = (const float*)d_in[3];
    const float* al0  = (const float*)d_in[4];
    const float* ar0  = (const float*)d_in[5];
    const float* b0   = (const float*)d_in[6];
    const float* W1   = (const float*)d_in[7];
    const float* al1  = (const float*)d_in[8];
    const float* ar1  = (const float*)d_in[9];
    const float* b1   = (const float*)d_in[10];
    const float* W2   = (const float*)d_in[11];
    const float* al2  = (const float*)d_in[12];
    const float* ar2  = (const float*)d_in[13];
    const float* b2   = (const float*)d_in[14];
    const float* rW2  = (const float*)d_in[15];
    float* out = (float*)d_out;

    __half *feath, *xh, *xl, *h1h, *h1l;
    float *feat2, *res2;
    __half2 *w0h, *w1h, *w2h, *w2l;
    void* degp;
    cudaGetSymbolAddress((void**)&feath, g_feat_h);
    cudaGetSymbolAddress((void**)&xh, g_xh);
    cudaGetSymbolAddress((void**)&xl, g_xl);
    cudaGetSymbolAddress((void**)&h1h, g_h1h);
    cudaGetSymbolAddress((void**)&h1l, g_h1l);
    cudaGetSymbolAddress((void**)&feat2, g_feat2);
    cudaGetSymbolAddress((void**)&res2, g_res2);
    cudaGetSymbolAddress((void**)&w0h, g_w0h);
    cudaGetSymbolAddress((void**)&w1h, g_w1h);
    cudaGetSymbolAddress((void**)&w2h, g_w2h);
    cudaGetSymbolAddress((void**)&w2l, g_w2l);
    cudaGetSymbolAddress(&degp, g_deg);

    // fork a side stream for the CSR build
    cudaStream_t s2 = 0;
    cudaEvent_t evF = 0, evJ = 0;
    bool forked = (cudaStreamCreateWithFlags(&s2, cudaStreamNonBlocking) == cudaSuccess) &&
                  (cudaEventCreateWithFlags(&evF, cudaEventDisableTiming) == cudaSuccess) &&
                  (cudaEventCreateWithFlags(&evJ, cudaEventDisableTiming) == cudaSuccess);
    cudaStream_t sc = forked ? s2 : 0;

    if (forked) {
        cudaEventRecord(evF, 0);
        cudaStreamWaitEvent(s2, evF, 0);
    }
    cudaMemsetAsync(degp, 0, NN * sizeof(int), sc);
    k_hist<<<(NE + 255) / 256, 256, 0, sc>>>(dst);
    k_scan<<<1, 1024, 0, sc>>>();
    k_scatter<<<(NE + 255) / 256, 256, 0, sc>>>(src, dst);
    if (forked) cudaEventRecord(evJ, s2);

    // main stream: presplit + layer0 GEMM
    k_presplitW<<<(2 * 128 * 256 + 255) / 256, 256>>>(W0, W1, w0h, w1h);
    k_presplitW2<<<(128 * 32 + 255) / 256, 256>>>(W2, rW2, w2h, w2l);
    k_presplit<<<(NN * 64 + 255) / 256, 256>>>((const float4*)x, (uint2*)xh, (uint2*)xl, NN * 64);

    dim3 gtc(4, (NN + 127) / 128);
    int aggBlocks = (NN * 32 + 255) / 256;

    k_gemm_tc<<<gtc, 256>>>(xh, xl, w0h, feath, al0, ar0, NN);

    if (forked) cudaStreamWaitEvent(0, evJ, 0);

    // layer 0 aggregate: res = x fp32, out -> split h1
    k_agg4<0><<<aggBlocks, 256>>>(feath, x, nullptr, nullptr, b0, h1h, h1l);

    // layer 1: GEMM + aggregate -> split h2 (reuses xh/xl)
    k_gemm_tc<<<gtc, 256>>>(h1h, h1l, w1h, feath, al1, ar1, NN);
    k_agg4<1><<<aggBlocks, 256>>>(feath, nullptr, h1h, h1l, b1, xh, xl);

    // layer 2: tensor-core dual GEMM (+el/er) + aggregate
    k_gemm16_tc<<<(NN + 127) / 128, 256>>>(xh, xl, w2h, w2l, feat2, res2, al2, ar2, NN);
    k_agg2<<<aggBlocks, 256>>>(feat2, res2, b2, out);
}